// round 2
// baseline (speedup 1.0000x reference)
#include <cuda_runtime.h>
#include <cstdint>

#define BN 16384
#define SEQ 32
#define RNN 64
#define NG 256            // 4*RNN gates
#define TB 32             // samples per LSTM block
#define LSTM_THREADS 256
#define HT 128            // heads threads per block

// JAX PRNG path: 1 = threefry_partitionable (default in modern JAX), 0 = original
#define THREEFRY_PARTITIONABLE 1

// scratch: h outputs for dialog 0 and 1
__device__ float g_h[2 * BN * RNN];

// ---------------- threefry2x32 (host+device, exact JAX algorithm) ----------------
__host__ __device__ __forceinline__ uint32_t rotl32(uint32_t x, int d) {
    return (x << d) | (x >> (32 - d));
}

__host__ __device__ __forceinline__ void threefry2x32(uint32_t k0, uint32_t k1,
                                                      uint32_t c0, uint32_t c1,
                                                      uint32_t& o0, uint32_t& o1) {
    uint32_t ks2 = k0 ^ k1 ^ 0x1BD11BDAu;
    uint32_t x0 = c0 + k0, x1 = c1 + k1;
#define TF_R4(a,b,c,d) \
    x0 += x1; x1 = rotl32(x1,a); x1 ^= x0; \
    x0 += x1; x1 = rotl32(x1,b); x1 ^= x0; \
    x0 += x1; x1 = rotl32(x1,c); x1 ^= x0; \
    x0 += x1; x1 = rotl32(x1,d); x1 ^= x0;
    TF_R4(13,15,26,6);  x0 += k1;  x1 += ks2 + 1u;
    TF_R4(17,29,16,24); x0 += ks2; x1 += k0  + 2u;
    TF_R4(13,15,26,6);  x0 += k0;  x1 += k1  + 3u;
    TF_R4(17,29,16,24); x0 += k1;  x1 += ks2 + 4u;
    TF_R4(13,15,26,6);  x0 += ks2; x1 += k0  + 5u;
#undef TF_R4
    o0 = x0; o1 = x1;
}

struct Keys { uint32_t a[7]; uint32_t b[7]; };

// 32-bit random bits for flat element idx of an array of n elements (n even)
__device__ __forceinline__ uint32_t jax_bits32(uint32_t k0, uint32_t k1,
                                               uint32_t idx, uint32_t half) {
#if THREEFRY_PARTITIONABLE
    uint32_t y0, y1;
    threefry2x32(k0, k1, 0u, idx, y0, y1);
    return y0 ^ y1;
#else
    uint32_t p = (idx < half) ? idx : idx - half;
    uint32_t y0, y1;
    threefry2x32(k0, k1, p, p + half, y0, y1);
    return (idx < half) ? y0 : y1;
#endif
}

__device__ __forceinline__ float jax_gumbel(uint32_t k0, uint32_t k1,
                                            uint32_t idx, uint32_t half) {
    uint32_t bits = jax_bits32(k0, k1, idx, half);
    float f = __uint_as_float((bits >> 9) | 0x3f800000u) - 1.0f; // [0,1)
    f = fmaxf(f, 1.17549435e-38f);                                // minval=tiny
    return -logf(-logf(f));
}

__device__ __forceinline__ float sigf(float x) {
    // XLA logistic lowering: 0.5 + 0.5*tanh(0.5 x)
    return fmaf(0.5f, tanhf(0.5f * x), 0.5f);
}

// ---------------- LSTM kernel ----------------
// smem layout (floats): Wsm[128*256] | bsm[256] | actT[128*36] | gsm[32*264] | tok[32*32](int)
#define SM_W    0
#define SM_B    (128*256)
#define SM_ACT  (SM_B + 256)
#define SM_G    (SM_ACT + 128*36)
#define SM_TOK  (SM_G + 32*264)
#define LSTM_SMEM_BYTES ((SM_TOK + 32*32) * 4)

__global__ void __launch_bounds__(LSTM_THREADS, 1)
lstm_kernel(const int* __restrict__ inst0, const int* __restrict__ inst1,
            const float* __restrict__ embed,
            const float* __restrict__ W_ih, const float* __restrict__ W_hh,
            const float* __restrict__ b_ih, const float* __restrict__ b_hh) {
    extern __shared__ float sm[];
    float* Wsm  = sm + SM_W;
    float* bsm  = sm + SM_B;
    float* actT = sm + SM_ACT;   // [k][s] padded stride 36
    float* gsm  = sm + SM_G;     // [s][j] padded stride 264
    int*   tok  = (int*)(sm + SM_TOK);

    const int tid  = threadIdx.x;
    const int base = blockIdx.x * TB;
    const int* inst = (blockIdx.y == 0) ? inst0 : inst1;
    float* hout = g_h + blockIdx.y * (BN * RNN);

    // load weights transposed: Wsm[k*256+j] = W[j][k] (k<64 -> W_ih, else W_hh)
    for (int idx = tid; idx < NG * RNN; idx += LSTM_THREADS) {
        int j = idx >> 6, k = idx & 63;
        Wsm[k * 256 + j]        = W_ih[idx];
        Wsm[(64 + k) * 256 + j] = W_hh[idx];
    }
    if (tid < NG) bsm[tid] = b_ih[tid] + b_hh[tid];
    for (int idx = tid; idx < TB * SEQ; idx += LSTM_THREADS) {
        int s = idx >> 5, t = idx & 31;
        tok[s * SEQ + t] = inst[(base + s) * SEQ + t];
    }
    // zero h rows of actT
    for (int idx = tid; idx < TB * RNN; idx += LSTM_THREADS) {
        int s = idx & 31, u = idx >> 5;
        actT[(64 + u) * 36 + s] = 0.f;
    }
    float c_reg[8];
#pragma unroll
    for (int i = 0; i < 8; i++) c_reg[i] = 0.f;
    __syncthreads();

    const int gj  = tid & 31;         // gate group: gates gj*8 .. gj*8+7
    const int si4 = (tid >> 5) * 4;   // sample base: samples si4 .. si4+3

    for (int t = 0; t < SEQ; t++) {
        // ---- phase A: gather x_t into actT rows 0..63 ----
#pragma unroll
        for (int i = 0; i < 8; i++) {
            int idx = tid + LSTM_THREADS * i;   // 0..2047
            int s = idx >> 6, k = idx & 63;
            actT[k * 36 + s] = embed[tok[s * SEQ + t] * RNN + k];
        }
        __syncthreads();

        // ---- phase B: gates = [x;h] @ [Wih;Whh] + b ----
        float acc[4][8];
#pragma unroll
        for (int r = 0; r < 4; r++)
#pragma unroll
            for (int j = 0; j < 8; j++) acc[r][j] = bsm[gj * 8 + j];

#pragma unroll 2
        for (int k = 0; k < 128; k++) {
            float4 a  = *(const float4*)(actT + k * 36 + si4);
            float4 w0 = *(const float4*)(Wsm + k * 256 + gj * 8);
            float4 w1 = *(const float4*)(Wsm + k * 256 + gj * 8 + 4);
            float av[4] = {a.x, a.y, a.z, a.w};
            float wv[8] = {w0.x, w0.y, w0.z, w0.w, w1.x, w1.y, w1.z, w1.w};
#pragma unroll
            for (int r = 0; r < 4; r++)
#pragma unroll
                for (int j = 0; j < 8; j++)
                    acc[r][j] = fmaf(av[r], wv[j], acc[r][j]);
        }

        // ---- phase C: stage gates ----
#pragma unroll
        for (int r = 0; r < 4; r++) {
            *(float4*)(gsm + (si4 + r) * 264 + gj * 8) =
                make_float4(acc[r][0], acc[r][1], acc[r][2], acc[r][3]);
            *(float4*)(gsm + (si4 + r) * 264 + gj * 8 + 4) =
                make_float4(acc[r][4], acc[r][5], acc[r][6], acc[r][7]);
        }
        __syncthreads();

        // ---- phase D: elementwise state update ----
#pragma unroll
        for (int i = 0; i < 8; i++) {
            int idx = tid + LSTM_THREADS * i;
            int s = idx >> 6, u = idx & 63;
            const float* gr = gsm + s * 264;
            float ig = gr[u], fg = gr[64 + u], gg = gr[128 + u], og = gr[192 + u];
            float c = sigf(fg) * c_reg[i] + sigf(ig) * tanhf(gg);
            float h = sigf(og) * tanhf(c);
            c_reg[i] = c;
            actT[(64 + u) * 36 + s] = h;
            if (t == SEQ - 1) hout[(base + s) * RNN + u] = h;
        }
        __syncthreads();
    }
}

// ---------------- heads kernel ----------------
// smem: weights block then h tile [128][65]
#define HW_WC   0
#define HW_BC   (HW_WC + 192)
#define HW_WS   (HW_BC + 4)
#define HW_BS   (HW_WS + 192)
#define HW_WL   (HW_BS + 4)
#define HW_BL   (HW_WL + 1600)
#define HW_WP   (HW_BL + 28)
#define HW_BP   (HW_WP + 512)
#define HW_WR1  (HW_BP + 8)
#define HW_BR1  (HW_WR1 + 2176)
#define HW_WR2  (HW_BR1 + 32)
#define HW_BR2  (HW_WR2 + 32)
#define HW_HB   (HW_BR2 + 4)      // 16B-aligned: (2548)*4 = 10192? ensure below
#define HEADS_SMEM_FLOATS (HW_HB + HT * 65)
#define HEADS_SMEM_BYTES  (HEADS_SMEM_FLOATS * 4)

__device__ const int c_offx[8] = {-1, 1, 0, 0, -1, -1, 1, 1};
__device__ const int c_offy[8] = {0, 0, 1, -1, -1, 1, -1, 1};

template <int V>
__device__ __forceinline__ int sample_lp(const float* lg, uint32_t k0, uint32_t k1,
                                         int b, float& lp) {
    const uint32_t half = (uint32_t)(BN * V / 2);
    int best = 0;
    float bestz = -1e30f, bestl = lg[0], m = -1e30f;
#pragma unroll
    for (int v = 0; v < V; v++) {
        float z = lg[v] + jax_gumbel(k0, k1, (uint32_t)(b * V + v), half);
        if (z > bestz) { bestz = z; best = v; bestl = lg[v]; }
        m = fmaxf(m, lg[v]);
    }
    float ssum = 0.f;
#pragma unroll
    for (int v = 0; v < V; v++) ssum += expf(lg[v] - m);
    lp = (bestl - m) - logf(ssum);
    return best;
}

__global__ void __launch_bounds__(HT)
heads_kernel(const int* __restrict__ canvas0, const int* __restrict__ canvas1,
             const int* __restrict__ refp,
             const float* __restrict__ Wc, const float* __restrict__ bc,
             const float* __restrict__ Ws, const float* __restrict__ bs,
             const float* __restrict__ Wl, const float* __restrict__ bl,
             const float* __restrict__ Wr1, const float* __restrict__ br1,
             const float* __restrict__ Wr2, const float* __restrict__ br2,
             const float* __restrict__ Wp, const float* __restrict__ bp,
             float* __restrict__ out, Keys keys) {
    extern __shared__ float sm[];
    const int tid = threadIdx.x;
    const int b = blockIdx.x * HT + tid;
    const int tile = blockIdx.x * HT;

    for (int i = tid; i < 192;  i += HT) sm[HW_WC + i] = Wc[i];
    for (int i = tid; i < 192;  i += HT) sm[HW_WS + i] = Ws[i];
    for (int i = tid; i < 1600; i += HT) sm[HW_WL + i] = Wl[i];
    for (int i = tid; i < 512;  i += HT) sm[HW_WP + i] = Wp[i];
    for (int i = tid; i < 2176; i += HT) sm[HW_WR1 + i] = Wr1[i];
    if (tid < 3)  sm[HW_BC + tid]  = bc[tid];
    if (tid < 3)  sm[HW_BS + tid]  = bs[tid];
    if (tid < 25) sm[HW_BL + tid]  = bl[tid];
    if (tid < 8)  sm[HW_BP + tid]  = bp[tid];
    if (tid < 32) sm[HW_BR1 + tid] = br1[tid];
    if (tid < 32) sm[HW_WR2 + tid] = Wr2[tid];
    if (tid == 0) sm[HW_BR2] = br2[0];

    float* hb = sm + HW_HB;
    // load h0 tile (dialog 0)
    for (int i = tid; i < HT * RNN; i += HT) {
        int s = i >> 6, k = i & 63;
        hb[s * 65 + k] = g_h[(tile + s) * RNN + k];
    }
    __syncthreads();

    // ======== dialog step 0 ========
    const float* h = hb + tid * 65;
    float lc[3], lsh[3], ll[25];
#pragma unroll
    for (int r = 0; r < 3; r++) {
        float d = 0.f, e = 0.f;
        for (int k = 0; k < 64; k++) {
            d = fmaf(h[k], sm[HW_WC + r * 64 + k], d);
            e = fmaf(h[k], sm[HW_WS + r * 64 + k], e);
        }
        lc[r] = d + sm[HW_BC + r];
        lsh[r] = e + sm[HW_BS + r];
    }
#pragma unroll 5
    for (int r = 0; r < 25; r++) {
        float d = 0.f;
        for (int k = 0; k < 64; k++) d = fmaf(h[k], sm[HW_WL + r * 64 + k], d);
        ll[r] = d + sm[HW_BL + r];
    }
    float clp0, slp0, llp0;
    int cs0  = sample_lp<3>(lc,  keys.a[0], keys.b[0], b, clp0);
    sample_lp<3>(lsh, keys.a[1], keys.b[1], b, slp0);
    int loc0 = sample_lp<25>(ll, keys.a[2], keys.b[2], b, llp0);

    int lclip = min(max(loc0, 0), 24);
    int4 pt = *(const int4*)(canvas1 + (b * 25 + lclip) * 4);
    bool ok0 = (loc0 >= 0) && (loc0 < 25) && ((pt.x + pt.y + pt.z + pt.w) >= 0);
    float loc_r0 = ok0 ? 1.f : -1.f;
    float col_r0 = ok0 ? ((cs0 == pt.x) ? 1.f : -1.f) : 0.f;

    __syncthreads();
    // load h1 tile (dialog 1)
    for (int i = tid; i < HT * RNN; i += HT) {
        int s = i >> 6, k = i & 63;
        hb[s * 65 + k] = g_h[BN * RNN + (tile + s) * RNN + k];
    }
    __syncthreads();

    // ======== dialog step 1 ========
    float lp8[8];
#pragma unroll
    for (int r = 0; r < 3; r++) {
        float d = 0.f, e = 0.f;
        for (int k = 0; k < 64; k++) {
            d = fmaf(h[k], sm[HW_WC + r * 64 + k], d);
            e = fmaf(h[k], sm[HW_WS + r * 64 + k], e);
        }
        lc[r] = d + sm[HW_BC + r];
        lsh[r] = e + sm[HW_BS + r];
    }
#pragma unroll 4
    for (int r = 0; r < 8; r++) {
        float d = 0.f;
        for (int k = 0; k < 64; k++) d = fmaf(h[k], sm[HW_WP + r * 64 + k], d);
        lp8[r] = d + sm[HW_BP + r];
    }
    float clp1, slp1, llp1, alp1;
    int cs1 = sample_lp<3>(lc,  keys.a[3], keys.b[3], b, clp1);
    sample_lp<3>(lsh, keys.a[4], keys.b[4], b, slp1);
    int ls1 = sample_lp<8>(lp8, keys.a[5], keys.b[5], b, llp1);

    // attention MLP over 25 locations
    float pre[32];
#pragma unroll 8
    for (int j = 0; j < 32; j++) {
        float d = 0.f;
        for (int k = 0; k < 64; k++) d = fmaf(h[k], sm[HW_WR1 + j * 68 + k], d);
        pre[j] = d + sm[HW_BR1 + j];
    }
    float al[25];
#pragma unroll
    for (int loc = 0; loc < 25; loc++) {
        int4 cv = *(const int4*)(canvas0 + (b * 25 + loc) * 4);
        float cx = (float)cv.x, cy = (float)cv.y, cz = (float)cv.z, cw = (float)cv.w;
        float a = sm[HW_BR2];
#pragma unroll
        for (int j = 0; j < 32; j++) {
            float v = pre[j];
            v = fmaf(cx, sm[HW_WR1 + j * 68 + 64], v);
            v = fmaf(cy, sm[HW_WR1 + j * 68 + 65], v);
            v = fmaf(cz, sm[HW_WR1 + j * 68 + 66], v);
            v = fmaf(cw, sm[HW_WR1 + j * 68 + 67], v);
            v = fmaxf(v, 0.f);
            a = fmaf(v, sm[HW_WR2 + j], a);
        }
        al[loc] = a;
    }
    int att = sample_lp<25>(al, keys.a[6], keys.b[6], b, alp1);

    int4 ro = *(const int4*)(canvas0 + (b * 25 + att) * 4);
    int4 rf = *(const int4*)(refp + b * 4);
    float att_rew = (ro.x == rf.x && ro.y == rf.y && ro.z == rf.z && ro.w == rf.w)
                        ? 1.f : -1.f;
    int loc1 = (ro.z + c_offx[ls1]) * 5 + (ro.w + c_offy[ls1]);
    int l1c = min(max(loc1, 0), 24);
    int4 pt1 = *(const int4*)(canvas1 + (b * 25 + l1c) * 4);
    bool ok1 = (loc1 >= 0) && (loc1 < 25) && ((pt1.x + pt1.y + pt1.z + pt1.w) >= 0);
    float loc_r1 = ok1 ? 1.f : -1.f;
    float col_r1 = ok1 ? ((cs1 == pt1.x) ? 1.f : -1.f) : 0.f;

    // ---- outputs: logp [7,B] then rew [7,B] ----
    out[0 * BN + b] = clp0;
    out[1 * BN + b] = slp0;
    out[2 * BN + b] = llp0;
    out[3 * BN + b] = clp1;
    out[4 * BN + b] = slp1;
    out[5 * BN + b] = llp1;
    out[6 * BN + b] = alp1;
    out[(7 + 0) * BN + b] = loc_r0;
    out[(7 + 1) * BN + b] = col_r0;
    out[(7 + 2) * BN + b] = loc_r0;
    out[(7 + 3) * BN + b] = loc_r1;
    out[(7 + 4) * BN + b] = col_r1;
    out[(7 + 5) * BN + b] = loc_r1;
    out[(7 + 6) * BN + b] = att_rew;
}

// ---------------- launch ----------------
extern "C" void kernel_launch(void* const* d_in, const int* in_sizes, int n_in,
                              void* d_out, int out_size) {
    const int*   inst0   = (const int*)d_in[0];
    const int*   inst1   = (const int*)d_in[1];
    const int*   canvas0 = (const int*)d_in[2];
    const int*   canvas1 = (const int*)d_in[3];
    const int*   refp    = (const int*)d_in[4];
    const float* embed   = (const float*)d_in[5];
    const float* W_ih    = (const float*)d_in[6];
    const float* W_hh    = (const float*)d_in[7];
    const float* b_ih    = (const float*)d_in[8];
    const float* b_hh    = (const float*)d_in[9];
    const float* Wc      = (const float*)d_in[10];
    const float* bc      = (const float*)d_in[11];
    const float* Ws      = (const float*)d_in[12];
    const float* bs      = (const float*)d_in[13];
    const float* Wl      = (const float*)d_in[14];
    const float* bl      = (const float*)d_in[15];
    const float* Wr1     = (const float*)d_in[16];
    const float* br1     = (const float*)d_in[17];
    const float* Wr2     = (const float*)d_in[18];
    const float* br2     = (const float*)d_in[19];
    const float* Wp      = (const float*)d_in[20];
    const float* bp      = (const float*)d_in[21];

    // keys = jax.random.split(jax.random.key(42), 7)
    Keys keys;
#if THREEFRY_PARTITIONABLE
    for (int i = 0; i < 7; i++)
        threefry2x32(0u, 42u, 0u, (uint32_t)i, keys.a[i], keys.b[i]);
#else
    uint32_t o[14];
    for (int i = 0; i < 7; i++)
        threefry2x32(0u, 42u, (uint32_t)i, (uint32_t)(i + 7), o[i], o[7 + i]);
    for (int i = 0; i < 7; i++) { keys.a[i] = o[2 * i]; keys.b[i] = o[2 * i + 1]; }
#endif

    cudaFuncSetAttribute(lstm_kernel, cudaFuncAttributeMaxDynamicSharedMemorySize,
                         LSTM_SMEM_BYTES);
    cudaFuncSetAttribute(heads_kernel, cudaFuncAttributeMaxDynamicSharedMemorySize,
                         HEADS_SMEM_BYTES);

    lstm_kernel<<<dim3(BN / TB, 2), LSTM_THREADS, LSTM_SMEM_BYTES>>>(
        inst0, inst1, embed, W_ih, W_hh, b_ih, b_hh);
    heads_kernel<<<BN / HT, HT, HEADS_SMEM_BYTES>>>(
        canvas0, canvas1, refp, Wc, bc, Ws, bs, Wl, bl, Wr1, br1, Wr2, br2,
        Wp, bp, (float*)d_out, keys);
}

// round 3
// speedup vs baseline: 2.5879x; 2.5879x over previous
#include <cuda_runtime.h>
#include <cstdint>

#define BN 16384
#define SEQ 32
#define RNN 64
#define NG 256            // 4*RNN gates
#define VOCAB 1001

// LSTM tiling
#define TB 64             // samples per LSTM block
#define LSTM_THREADS 256
#define WS_STRIDE 260     // Wsm row stride (floats)
#define HT_STRIDE 68      // hT row stride (floats)

// heads
#define HT 64             // heads threads per block

#define THREEFRY_PARTITIONABLE 1

typedef unsigned long long u64;

// scratch: h outputs for dialog 0 and 1, token-gate table
__device__ float g_h[2 * BN * RNN];
__device__ float g_tokgate[VOCAB * NG];

// ---------------- f32x2 packed helpers (sm_103a) ----------------
__device__ __forceinline__ void fma2(u64& d, u64 a, u64 b) {
    asm("fma.rn.f32x2 %0, %1, %2, %0;" : "+l"(d) : "l"(a), "l"(b));
}
__device__ __forceinline__ u64 splat2(float x) {
    u64 r; asm("mov.b64 %0, {%1, %1};" : "=l"(r) : "f"(x)); return r;
}
__device__ __forceinline__ u64 pack2(float x, float y) {
    u64 r; asm("mov.b64 %0, {%1, %2};" : "=l"(r) : "f"(x), "f"(y)); return r;
}
__device__ __forceinline__ void unpack2(u64 v, float& x, float& y) {
    asm("mov.b64 {%0, %1}, %2;" : "=f"(x), "=f"(y) : "l"(v));
}

// ---------------- threefry2x32 (host+device, exact JAX algorithm) ----------------
__host__ __device__ __forceinline__ uint32_t rotl32(uint32_t x, int d) {
    return (x << d) | (x >> (32 - d));
}

__host__ __device__ __forceinline__ void threefry2x32(uint32_t k0, uint32_t k1,
                                                      uint32_t c0, uint32_t c1,
                                                      uint32_t& o0, uint32_t& o1) {
    uint32_t ks2 = k0 ^ k1 ^ 0x1BD11BDAu;
    uint32_t x0 = c0 + k0, x1 = c1 + k1;
#define TF_R4(a,b,c,d) \
    x0 += x1; x1 = rotl32(x1,a); x1 ^= x0; \
    x0 += x1; x1 = rotl32(x1,b); x1 ^= x0; \
    x0 += x1; x1 = rotl32(x1,c); x1 ^= x0; \
    x0 += x1; x1 = rotl32(x1,d); x1 ^= x0;
    TF_R4(13,15,26,6);  x0 += k1;  x1 += ks2 + 1u;
    TF_R4(17,29,16,24); x0 += ks2; x1 += k0  + 2u;
    TF_R4(13,15,26,6);  x0 += k0;  x1 += k1  + 3u;
    TF_R4(17,29,16,24); x0 += k1;  x1 += ks2 + 4u;
    TF_R4(13,15,26,6);  x0 += ks2; x1 += k0  + 5u;
#undef TF_R4
    o0 = x0; o1 = x1;
}

struct Keys { uint32_t a[7]; uint32_t b[7]; };

__device__ __forceinline__ uint32_t jax_bits32(uint32_t k0, uint32_t k1,
                                               uint32_t idx, uint32_t half) {
#if THREEFRY_PARTITIONABLE
    uint32_t y0, y1;
    threefry2x32(k0, k1, 0u, idx, y0, y1);
    return y0 ^ y1;
#else
    uint32_t p = (idx < half) ? idx : idx - half;
    uint32_t y0, y1;
    threefry2x32(k0, k1, p, p + half, y0, y1);
    return (idx < half) ? y0 : y1;
#endif
}

__device__ __forceinline__ float jax_gumbel(uint32_t k0, uint32_t k1,
                                            uint32_t idx, uint32_t half) {
    uint32_t bits = jax_bits32(k0, k1, idx, half);
    float f = __uint_as_float((bits >> 9) | 0x3f800000u) - 1.0f; // [0,1)
    f = fmaxf(f, 1.17549435e-38f);                                // minval=tiny
    return -logf(-logf(f));
}

__device__ __forceinline__ float sigf(float x) {
    // XLA logistic lowering: 0.5 + 0.5*tanh(0.5 x)
    return fmaf(0.5f, tanhf(0.5f * x), 0.5f);
}

// ---------------- tokgate precompute ----------------
// g_tokgate[v][c], c = 4*u + g  (gate-interleaved), value = embed[v] . W_ih[g*64+u] + b_ih + b_hh
__global__ void __launch_bounds__(256)
tokgate_kernel(const float* __restrict__ embed,
               const float* __restrict__ W_ih,
               const float* __restrict__ b_ih, const float* __restrict__ b_hh) {
    __shared__ float e[RNN];
    int v = blockIdx.x;
    int c = threadIdx.x;
    if (c < RNN) e[c] = embed[v * RNN + c];
    __syncthreads();
    int g = c & 3, u = c >> 2;
    int row = g * 64 + u;
    float d = b_ih[row] + b_hh[row];
    const float* w = W_ih + row * RNN;
#pragma unroll
    for (int k = 0; k < RNN; k++) d = fmaf(e[k], w[k], d);
    g_tokgate[v * NG + c] = d;
}

// ---------------- LSTM kernel ----------------
// smem: Wsm[64][WS_STRIDE] | hT[64][HT_STRIDE] | tok[64][32]
#define SM_W    0
#define SM_H    (64 * WS_STRIDE)
#define SM_TOK  (SM_H + 64 * HT_STRIDE)
#define LSTM_SMEM_BYTES ((SM_TOK + TB * SEQ) * 4)

__global__ void __launch_bounds__(LSTM_THREADS, 2)
lstm_kernel(const int* __restrict__ inst0, const int* __restrict__ inst1,
            const float* __restrict__ W_hh) {
    extern __shared__ float sm[];
    float* Wsm = sm + SM_W;
    float* hT  = sm + SM_H;     // [u][s]
    int*   tok = (int*)(sm + SM_TOK);

    const int tid  = threadIdx.x;
    const int base = blockIdx.x * TB;
    const int* inst = (blockIdx.y == 0) ? inst0 : inst1;
    float* hout = g_h + blockIdx.y * (BN * RNN);

    // W_hh permuted: Wsm[k][c], c = 4u+g <- W_hh[(g*64+u)][k]
    for (int idx = tid; idx < RNN * NG; idx += LSTM_THREADS) {
        int c = idx >> 6, k = idx & 63;
        int g = c & 3, u = c >> 2;
        Wsm[k * WS_STRIDE + c] = W_hh[(g * 64 + u) * RNN + k];
    }
    for (int idx = tid; idx < 64 * HT_STRIDE; idx += LSTM_THREADS) hT[idx] = 0.f;
    for (int idx = tid; idx < TB * SEQ; idx += LSTM_THREADS)
        tok[idx] = inst[base * SEQ + idx];

    float c_reg[16];
#pragma unroll
    for (int i = 0; i < 16; i++) c_reg[i] = 0.f;
    __syncthreads();

    const int gj    = tid & 31;        // column group: c = gj*8 .. gj*8+7  (units 2gj, 2gj+1)
    const int si8   = (tid >> 5) * 8;  // samples si8 .. si8+7 (warp-uniform)
    const int cbase = gj * 8;

    for (int t = 0; t < SEQ; t++) {
        // ---- acc init = tokgate gather (x-side GEMM precomputed) ----
        u64 acc[8][4];
#pragma unroll
        for (int r = 0; r < 8; r++) {
            int tk = tok[(si8 + r) * SEQ + t];
            const float4* tg = (const float4*)(g_tokgate + tk * NG + cbase);
            float4 g0 = tg[0], g1 = tg[1];
            acc[r][0] = pack2(g0.x, g0.y);
            acc[r][1] = pack2(g0.z, g0.w);
            acc[r][2] = pack2(g1.x, g1.y);
            acc[r][3] = pack2(g1.z, g1.w);
        }

        // ---- recurrent GEMM: gates += h_prev @ W_hh (packed f32x2) ----
#pragma unroll 2
        for (int k = 0; k < 64; k++) {
            const float* wr = Wsm + k * WS_STRIDE + cbase;
            ulonglong2 wA = *(const ulonglong2*)wr;        // cols (c,c+1),(c+2,c+3)
            ulonglong2 wB = *(const ulonglong2*)(wr + 4);  // cols (c+4,c+5),(c+6,c+7)
            const float* ar = hT + k * HT_STRIDE + si8;
            float4 a0 = *(const float4*)ar;
            float4 a1 = *(const float4*)(ar + 4);
            u64 s0 = splat2(a0.x), s1 = splat2(a0.y), s2 = splat2(a0.z), s3 = splat2(a0.w);
            u64 s4 = splat2(a1.x), s5 = splat2(a1.y), s6 = splat2(a1.z), s7 = splat2(a1.w);
#define ROW(r, sv) \
            fma2(acc[r][0], wA.x, sv); fma2(acc[r][1], wA.y, sv); \
            fma2(acc[r][2], wB.x, sv); fma2(acc[r][3], wB.y, sv);
            ROW(0, s0) ROW(1, s1) ROW(2, s2) ROW(3, s3)
            ROW(4, s4) ROW(5, s5) ROW(6, s6) ROW(7, s7)
#undef ROW
        }
        __syncthreads();   // all reads of hT done before rewrite

        // ---- cell update: fully thread-local (gate-interleaved layout) ----
#pragma unroll
        for (int ul = 0; ul < 2; ul++) {
            float hv[8];
#pragma unroll
            for (int r = 0; r < 8; r++) {
                float ig, fg, gg, og;
                unpack2(acc[r][2 * ul],     ig, fg);
                unpack2(acc[r][2 * ul + 1], gg, og);
                float c = sigf(fg) * c_reg[ul * 8 + r] + sigf(ig) * tanhf(gg);
                float h = sigf(og) * tanhf(c);
                c_reg[ul * 8 + r] = c;
                hv[r] = h;
            }
            float* dst = hT + (2 * gj + ul) * HT_STRIDE + si8;
            *(float4*)dst       = make_float4(hv[0], hv[1], hv[2], hv[3]);
            *(float4*)(dst + 4) = make_float4(hv[4], hv[5], hv[6], hv[7]);
            if (t == SEQ - 1) {
#pragma unroll
                for (int r = 0; r < 8; r++)
                    hout[(base + si8 + r) * RNN + 2 * gj + ul] = hv[r];
            }
        }
        __syncthreads();   // h写 complete before next step's reads
    }
}

// ---------------- heads kernel ----------------
#define HW_WC   0
#define HW_BC   (HW_WC + 192)
#define HW_WS   (HW_BC + 4)
#define HW_BS   (HW_WS + 192)
#define HW_WL   (HW_BS + 4)
#define HW_BL   (HW_WL + 1600)
#define HW_WP   (HW_BL + 28)
#define HW_BP   (HW_WP + 512)
#define HW_WR1  (HW_BP + 8)
#define HW_BR1  (HW_WR1 + 2176)
#define HW_WR2  (HW_BR1 + 32)
#define HW_BR2  (HW_WR2 + 32)
#define HW_HB   (HW_BR2 + 4)
#define HEADS_SMEM_FLOATS (HW_HB + HT * 65)
#define HEADS_SMEM_BYTES  (HEADS_SMEM_FLOATS * 4)

__device__ const int c_offx[8] = {-1, 1, 0, 0, -1, -1, 1, 1};
__device__ const int c_offy[8] = {0, 0, 1, -1, -1, 1, -1, 1};

template <int V>
__device__ __forceinline__ int sample_lp(const float* lg, uint32_t k0, uint32_t k1,
                                         int b, float& lp) {
    const uint32_t half = (uint32_t)(BN * V / 2);
    int best = 0;
    float bestz = -1e30f, bestl = lg[0], m = -1e30f;
#pragma unroll
    for (int v = 0; v < V; v++) {
        float z = lg[v] + jax_gumbel(k0, k1, (uint32_t)(b * V + v), half);
        if (z > bestz) { bestz = z; best = v; bestl = lg[v]; }
        m = fmaxf(m, lg[v]);
    }
    float ssum = 0.f;
#pragma unroll
    for (int v = 0; v < V; v++) ssum += expf(lg[v] - m);
    lp = (bestl - m) - logf(ssum);
    return best;
}

__global__ void __launch_bounds__(HT)
heads_kernel(const int* __restrict__ canvas0, const int* __restrict__ canvas1,
             const int* __restrict__ refp,
             const float* __restrict__ Wc, const float* __restrict__ bc,
             const float* __restrict__ Ws, const float* __restrict__ bs,
             const float* __restrict__ Wl, const float* __restrict__ bl,
             const float* __restrict__ Wr1, const float* __restrict__ br1,
             const float* __restrict__ Wr2, const float* __restrict__ br2,
             const float* __restrict__ Wp, const float* __restrict__ bp,
             float* __restrict__ out, Keys keys) {
    extern __shared__ float sm[];
    const int tid = threadIdx.x;
    const int b = blockIdx.x * HT + tid;
    const int tile = blockIdx.x * HT;

    for (int i = tid; i < 192;  i += HT) sm[HW_WC + i] = Wc[i];
    for (int i = tid; i < 192;  i += HT) sm[HW_WS + i] = Ws[i];
    for (int i = tid; i < 1600; i += HT) sm[HW_WL + i] = Wl[i];
    for (int i = tid; i < 512;  i += HT) sm[HW_WP + i] = Wp[i];
    for (int i = tid; i < 2176; i += HT) sm[HW_WR1 + i] = Wr1[i];
    if (tid < 3)  sm[HW_BC + tid]  = bc[tid];
    if (tid < 3)  sm[HW_BS + tid]  = bs[tid];
    if (tid < 25) sm[HW_BL + tid]  = bl[tid];
    if (tid < 8)  sm[HW_BP + tid]  = bp[tid];
    if (tid < 32) sm[HW_BR1 + tid] = br1[tid];
    if (tid < 32) sm[HW_WR2 + tid] = Wr2[tid];
    if (tid == 0) sm[HW_BR2] = br2[0];

    float* hb = sm + HW_HB;
    for (int i = tid; i < HT * RNN; i += HT) {
        int s = i >> 6, k = i & 63;
        hb[s * 65 + k] = g_h[(tile + s) * RNN + k];
    }
    __syncthreads();

    // ======== dialog step 0 ========
    const float* h = hb + tid * 65;
    float lc[3], lsh[3], ll[25];
#pragma unroll
    for (int r = 0; r < 3; r++) {
        float d = 0.f, e = 0.f;
        for (int k = 0; k < 64; k++) {
            d = fmaf(h[k], sm[HW_WC + r * 64 + k], d);
            e = fmaf(h[k], sm[HW_WS + r * 64 + k], e);
        }
        lc[r] = d + sm[HW_BC + r];
        lsh[r] = e + sm[HW_BS + r];
    }
#pragma unroll 5
    for (int r = 0; r < 25; r++) {
        float d = 0.f;
        for (int k = 0; k < 64; k++) d = fmaf(h[k], sm[HW_WL + r * 64 + k], d);
        ll[r] = d + sm[HW_BL + r];
    }
    float clp0, slp0, llp0;
    int cs0  = sample_lp<3>(lc,  keys.a[0], keys.b[0], b, clp0);
    sample_lp<3>(lsh, keys.a[1], keys.b[1], b, slp0);
    int loc0 = sample_lp<25>(ll, keys.a[2], keys.b[2], b, llp0);

    int lclip = min(max(loc0, 0), 24);
    int4 pt = *(const int4*)(canvas1 + (b * 25 + lclip) * 4);
    bool ok0 = (loc0 >= 0) && (loc0 < 25) && ((pt.x + pt.y + pt.z + pt.w) >= 0);
    float loc_r0 = ok0 ? 1.f : -1.f;
    float col_r0 = ok0 ? ((cs0 == pt.x) ? 1.f : -1.f) : 0.f;

    __syncthreads();
    for (int i = tid; i < HT * RNN; i += HT) {
        int s = i >> 6, k = i & 63;
        hb[s * 65 + k] = g_h[BN * RNN + (tile + s) * RNN + k];
    }
    __syncthreads();

    // ======== dialog step 1 ========
    float lp8[8];
#pragma unroll
    for (int r = 0; r < 3; r++) {
        float d = 0.f, e = 0.f;
        for (int k = 0; k < 64; k++) {
            d = fmaf(h[k], sm[HW_WC + r * 64 + k], d);
            e = fmaf(h[k], sm[HW_WS + r * 64 + k], e);
        }
        lc[r] = d + sm[HW_BC + r];
        lsh[r] = e + sm[HW_BS + r];
    }
#pragma unroll 4
    for (int r = 0; r < 8; r++) {
        float d = 0.f;
        for (int k = 0; k < 64; k++) d = fmaf(h[k], sm[HW_WP + r * 64 + k], d);
        lp8[r] = d + sm[HW_BP + r];
    }
    float clp1, slp1, llp1, alp1;
    int cs1 = sample_lp<3>(lc,  keys.a[3], keys.b[3], b, clp1);
    sample_lp<3>(lsh, keys.a[4], keys.b[4], b, slp1);
    int ls1 = sample_lp<8>(lp8, keys.a[5], keys.b[5], b, llp1);

    float pre[32];
#pragma unroll 8
    for (int j = 0; j < 32; j++) {
        float d = 0.f;
        for (int k = 0; k < 64; k++) d = fmaf(h[k], sm[HW_WR1 + j * 68 + k], d);
        pre[j] = d + sm[HW_BR1 + j];
    }
    float al[25];
#pragma unroll
    for (int loc = 0; loc < 25; loc++) {
        int4 cv = *(const int4*)(canvas0 + (b * 25 + loc) * 4);
        float cx = (float)cv.x, cy = (float)cv.y, cz = (float)cv.z, cw = (float)cv.w;
        float a = sm[HW_BR2];
#pragma unroll
        for (int j = 0; j < 32; j++) {
            float v = pre[j];
            v = fmaf(cx, sm[HW_WR1 + j * 68 + 64], v);
            v = fmaf(cy, sm[HW_WR1 + j * 68 + 65], v);
            v = fmaf(cz, sm[HW_WR1 + j * 68 + 66], v);
            v = fmaf(cw, sm[HW_WR1 + j * 68 + 67], v);
            v = fmaxf(v, 0.f);
            a = fmaf(v, sm[HW_WR2 + j], a);
        }
        al[loc] = a;
    }
    int att = sample_lp<25>(al, keys.a[6], keys.b[6], b, alp1);

    int4 ro = *(const int4*)(canvas0 + (b * 25 + att) * 4);
    int4 rf = *(const int4*)(refp + b * 4);
    float att_rew = (ro.x == rf.x && ro.y == rf.y && ro.z == rf.z && ro.w == rf.w)
                        ? 1.f : -1.f;
    int loc1 = (ro.z + c_offx[ls1]) * 5 + (ro.w + c_offy[ls1]);
    int l1c = min(max(loc1, 0), 24);
    int4 pt1 = *(const int4*)(canvas1 + (b * 25 + l1c) * 4);
    bool ok1 = (loc1 >= 0) && (loc1 < 25) && ((pt1.x + pt1.y + pt1.z + pt1.w) >= 0);
    float loc_r1 = ok1 ? 1.f : -1.f;
    float col_r1 = ok1 ? ((cs1 == pt1.x) ? 1.f : -1.f) : 0.f;

    out[0 * BN + b] = clp0;
    out[1 * BN + b] = slp0;
    out[2 * BN + b] = llp0;
    out[3 * BN + b] = clp1;
    out[4 * BN + b] = slp1;
    out[5 * BN + b] = llp1;
    out[6 * BN + b] = alp1;
    out[(7 + 0) * BN + b] = loc_r0;
    out[(7 + 1) * BN + b] = col_r0;
    out[(7 + 2) * BN + b] = loc_r0;
    out[(7 + 3) * BN + b] = loc_r1;
    out[(7 + 4) * BN + b] = col_r1;
    out[(7 + 5) * BN + b] = loc_r1;
    out[(7 + 6) * BN + b] = att_rew;
}

// ---------------- launch ----------------
extern "C" void kernel_launch(void* const* d_in, const int* in_sizes, int n_in,
                              void* d_out, int out_size) {
    const int*   inst0   = (const int*)d_in[0];
    const int*   inst1   = (const int*)d_in[1];
    const int*   canvas0 = (const int*)d_in[2];
    const int*   canvas1 = (const int*)d_in[3];
    const int*   refp    = (const int*)d_in[4];
    const float* embed   = (const float*)d_in[5];
    const float* W_ih    = (const float*)d_in[6];
    const float* W_hh    = (const float*)d_in[7];
    const float* b_ih    = (const float*)d_in[8];
    const float* b_hh    = (const float*)d_in[9];
    const float* Wc      = (const float*)d_in[10];
    const float* bc      = (const float*)d_in[11];
    const float* Ws      = (const float*)d_in[12];
    const float* bs      = (const float*)d_in[13];
    const float* Wl      = (const float*)d_in[14];
    const float* bl      = (const float*)d_in[15];
    const float* Wr1     = (const float*)d_in[16];
    const float* br1     = (const float*)d_in[17];
    const float* Wr2     = (const float*)d_in[18];
    const float* br2     = (const float*)d_in[19];
    const float* Wp      = (const float*)d_in[20];
    const float* bp      = (const float*)d_in[21];

    Keys keys;
#if THREEFRY_PARTITIONABLE
    for (int i = 0; i < 7; i++)
        threefry2x32(0u, 42u, 0u, (uint32_t)i, keys.a[i], keys.b[i]);
#else
    uint32_t o[14];
    for (int i = 0; i < 7; i++)
        threefry2x32(0u, 42u, (uint32_t)i, (uint32_t)(i + 7), o[i], o[7 + i]);
    for (int i = 0; i < 7; i++) { keys.a[i] = o[2 * i]; keys.b[i] = o[2 * i + 1]; }
#endif

    cudaFuncSetAttribute(lstm_kernel, cudaFuncAttributeMaxDynamicSharedMemorySize,
                         LSTM_SMEM_BYTES);
    cudaFuncSetAttribute(heads_kernel, cudaFuncAttributeMaxDynamicSharedMemorySize,
                         HEADS_SMEM_BYTES);

    tokgate_kernel<<<VOCAB, 256>>>(embed, W_ih, b_ih, b_hh);
    lstm_kernel<<<dim3(BN / TB, 2), LSTM_THREADS, LSTM_SMEM_BYTES>>>(
        inst0, inst1, W_hh);
    heads_kernel<<<BN / HT, HT, HEADS_SMEM_BYTES>>>(
        canvas0, canvas1, refp, Wc, bc, Ws, bs, Wl, bl, Wr1, br1, Wr2, br2,
        Wp, bp, (float*)d_out, keys);
}

// round 4
// speedup vs baseline: 2.5897x; 1.0007x over previous
#include <cuda_runtime.h>
#include <cstdint>

#define BN 16384
#define SEQ 32
#define RNN 64
#define NG 256            // 4*RNN gates
#define VOCAB 1001

// LSTM tiling
#define TB 64             // samples per LSTM block
#define LSTM_THREADS 256
#define WS_STRIDE 260     // Wsm row stride (floats)
#define HT_STRIDE 68      // hT row stride (floats)

// heads
#define HT 64             // heads threads per block

#define THREEFRY_PARTITIONABLE 1

typedef unsigned long long u64;

// scratch: h outputs for dialog 0 and 1, token-gate table
__device__ float g_h[2 * BN * RNN];
__device__ float g_tokgate[VOCAB * NG];

// ---------------- f32x2 packed helpers (sm_103a) ----------------
__device__ __forceinline__ void fma2(u64& d, u64 a, u64 b) {
    asm("fma.rn.f32x2 %0, %1, %2, %0;" : "+l"(d) : "l"(a), "l"(b));
}
__device__ __forceinline__ u64 splat2(float x) {
    u64 r; asm("mov.b64 %0, {%1, %1};" : "=l"(r) : "f"(x)); return r;
}
__device__ __forceinline__ u64 pack2(float x, float y) {
    u64 r; asm("mov.b64 %0, {%1, %2};" : "=l"(r) : "f"(x), "f"(y)); return r;
}
__device__ __forceinline__ void unpack2(u64 v, float& x, float& y) {
    asm("mov.b64 {%0, %1}, %2;" : "=f"(x), "=f"(y) : "l"(v));
}

// ---------------- threefry2x32 (host+device, exact JAX algorithm) ----------------
__host__ __device__ __forceinline__ uint32_t rotl32(uint32_t x, int d) {
    return (x << d) | (x >> (32 - d));
}

__host__ __device__ __forceinline__ void threefry2x32(uint32_t k0, uint32_t k1,
                                                      uint32_t c0, uint32_t c1,
                                                      uint32_t& o0, uint32_t& o1) {
    uint32_t ks2 = k0 ^ k1 ^ 0x1BD11BDAu;
    uint32_t x0 = c0 + k0, x1 = c1 + k1;
#define TF_R4(a,b,c,d) \
    x0 += x1; x1 = rotl32(x1,a); x1 ^= x0; \
    x0 += x1; x1 = rotl32(x1,b); x1 ^= x0; \
    x0 += x1; x1 = rotl32(x1,c); x1 ^= x0; \
    x0 += x1; x1 = rotl32(x1,d); x1 ^= x0;
    TF_R4(13,15,26,6);  x0 += k1;  x1 += ks2 + 1u;
    TF_R4(17,29,16,24); x0 += ks2; x1 += k0  + 2u;
    TF_R4(13,15,26,6);  x0 += k0;  x1 += k1  + 3u;
    TF_R4(17,29,16,24); x0 += k1;  x1 += ks2 + 4u;
    TF_R4(13,15,26,6);  x0 += ks2; x1 += k0  + 5u;
#undef TF_R4
    o0 = x0; o1 = x1;
}

struct Keys { uint32_t a[7]; uint32_t b[7]; };

__device__ __forceinline__ uint32_t jax_bits32(uint32_t k0, uint32_t k1,
                                               uint32_t idx, uint32_t half) {
#if THREEFRY_PARTITIONABLE
    uint32_t y0, y1;
    threefry2x32(k0, k1, 0u, idx, y0, y1);
    return y0 ^ y1;
#else
    uint32_t p = (idx < half) ? idx : idx - half;
    uint32_t y0, y1;
    threefry2x32(k0, k1, p, p + half, y0, y1);
    return (idx < half) ? y0 : y1;
#endif
}

__device__ __forceinline__ float jax_gumbel(uint32_t k0, uint32_t k1,
                                            uint32_t idx, uint32_t half) {
    uint32_t bits = jax_bits32(k0, k1, idx, half);
    float f = __uint_as_float((bits >> 9) | 0x3f800000u) - 1.0f; // [0,1)
    f = fmaxf(f, 1.17549435e-38f);                                // minval=tiny
    return -logf(-logf(f));
}

__device__ __forceinline__ float sigf(float x) {
    // XLA logistic lowering: 0.5 + 0.5*tanh(0.5 x)
    return fmaf(0.5f, tanhf(0.5f * x), 0.5f);
}

// ---------------- tokgate precompute ----------------
// g_tokgate[v][c], c = 4*u + g  (gate-interleaved), value = embed[v] . W_ih[g*64+u] + b_ih + b_hh
__global__ void __launch_bounds__(256)
tokgate_kernel(const float* __restrict__ embed,
               const float* __restrict__ W_ih,
               const float* __restrict__ b_ih, const float* __restrict__ b_hh) {
    __shared__ float e[RNN];
    int v = blockIdx.x;
    int c = threadIdx.x;
    if (c < RNN) e[c] = embed[v * RNN + c];
    __syncthreads();
    int g = c & 3, u = c >> 2;
    int row = g * 64 + u;
    float d = b_ih[row] + b_hh[row];
    const float* w = W_ih + row * RNN;
#pragma unroll
    for (int k = 0; k < RNN; k++) d = fmaf(e[k], w[k], d);
    g_tokgate[v * NG + c] = d;
}

// ---------------- LSTM kernel ----------------
// smem: Wsm[64][WS_STRIDE] | hT[64][HT_STRIDE] | tok[64][32]
#define SM_W    0
#define SM_H    (64 * WS_STRIDE)
#define SM_TOK  (SM_H + 64 * HT_STRIDE)
#define LSTM_SMEM_BYTES ((SM_TOK + TB * SEQ) * 4)

__global__ void __launch_bounds__(LSTM_THREADS, 2)
lstm_kernel(const int* __restrict__ inst0, const int* __restrict__ inst1,
            const float* __restrict__ W_hh) {
    extern __shared__ float sm[];
    float* Wsm = sm + SM_W;
    float* hT  = sm + SM_H;     // [u][s]
    int*   tok = (int*)(sm + SM_TOK);

    const int tid  = threadIdx.x;
    const int base = blockIdx.x * TB;
    const int* inst = (blockIdx.y == 0) ? inst0 : inst1;
    float* hout = g_h + blockIdx.y * (BN * RNN);

    // W_hh permuted: Wsm[k][c], c = 4u+g <- W_hh[(g*64+u)][k]
    for (int idx = tid; idx < RNN * NG; idx += LSTM_THREADS) {
        int c = idx >> 6, k = idx & 63;
        int g = c & 3, u = c >> 2;
        Wsm[k * WS_STRIDE + c] = W_hh[(g * 64 + u) * RNN + k];
    }
    for (int idx = tid; idx < 64 * HT_STRIDE; idx += LSTM_THREADS) hT[idx] = 0.f;
    for (int idx = tid; idx < TB * SEQ; idx += LSTM_THREADS)
        tok[idx] = inst[base * SEQ + idx];

    float c_reg[16];
#pragma unroll
    for (int i = 0; i < 16; i++) c_reg[i] = 0.f;
    __syncthreads();

    const int gj    = tid & 31;        // column group: c = gj*8 .. gj*8+7  (units 2gj, 2gj+1)
    const int si8   = (tid >> 5) * 8;  // samples si8 .. si8+7 (warp-uniform)
    const int cbase = gj * 8;

    for (int t = 0; t < SEQ; t++) {
        // ---- acc init = tokgate gather (x-side GEMM precomputed) ----
        u64 acc[8][4];
#pragma unroll
        for (int r = 0; r < 8; r++) {
            int tk = tok[(si8 + r) * SEQ + t];
            const float4* tg = (const float4*)(g_tokgate + tk * NG + cbase);
            float4 g0 = tg[0], g1 = tg[1];
            acc[r][0] = pack2(g0.x, g0.y);
            acc[r][1] = pack2(g0.z, g0.w);
            acc[r][2] = pack2(g1.x, g1.y);
            acc[r][3] = pack2(g1.z, g1.w);
        }

        // ---- recurrent GEMM: gates += h_prev @ W_hh (packed f32x2) ----
#pragma unroll 2
        for (int k = 0; k < 64; k++) {
            const float* wr = Wsm + k * WS_STRIDE + cbase;
            ulonglong2 wA = *(const ulonglong2*)wr;        // cols (c,c+1),(c+2,c+3)
            ulonglong2 wB = *(const ulonglong2*)(wr + 4);  // cols (c+4,c+5),(c+6,c+7)
            const float* ar = hT + k * HT_STRIDE + si8;
            float4 a0 = *(const float4*)ar;
            float4 a1 = *(const float4*)(ar + 4);
            u64 s0 = splat2(a0.x), s1 = splat2(a0.y), s2 = splat2(a0.z), s3 = splat2(a0.w);
            u64 s4 = splat2(a1.x), s5 = splat2(a1.y), s6 = splat2(a1.z), s7 = splat2(a1.w);
#define ROW(r, sv) \
            fma2(acc[r][0], wA.x, sv); fma2(acc[r][1], wA.y, sv); \
            fma2(acc[r][2], wB.x, sv); fma2(acc[r][3], wB.y, sv);
            ROW(0, s0) ROW(1, s1) ROW(2, s2) ROW(3, s3)
            ROW(4, s4) ROW(5, s5) ROW(6, s6) ROW(7, s7)
#undef ROW
        }
        __syncthreads();   // all reads of hT done before rewrite

        // ---- cell update: fully thread-local (gate-interleaved layout) ----
#pragma unroll
        for (int ul = 0; ul < 2; ul++) {
            float hv[8];
#pragma unroll
            for (int r = 0; r < 8; r++) {
                float ig, fg, gg, og;
                unpack2(acc[r][2 * ul],     ig, fg);
                unpack2(acc[r][2 * ul + 1], gg, og);
                float c = sigf(fg) * c_reg[ul * 8 + r] + sigf(ig) * tanhf(gg);
                float h = sigf(og) * tanhf(c);
                c_reg[ul * 8 + r] = c;
                hv[r] = h;
            }
            float* dst = hT + (2 * gj + ul) * HT_STRIDE + si8;
            *(float4*)dst       = make_float4(hv[0], hv[1], hv[2], hv[3]);
            *(float4*)(dst + 4) = make_float4(hv[4], hv[5], hv[6], hv[7]);
            if (t == SEQ - 1) {
#pragma unroll
                for (int r = 0; r < 8; r++)
                    hout[(base + si8 + r) * RNN + 2 * gj + ul] = hv[r];
            }
        }
        __syncthreads();   // h写 complete before next step's reads
    }
}

// ---------------- heads kernel ----------------
#define HW_WC   0
#define HW_BC   (HW_WC + 192)
#define HW_WS   (HW_BC + 4)
#define HW_BS   (HW_WS + 192)
#define HW_WL   (HW_BS + 4)
#define HW_BL   (HW_WL + 1600)
#define HW_WP   (HW_BL + 28)
#define HW_BP   (HW_WP + 512)
#define HW_WR1  (HW_BP + 8)
#define HW_BR1  (HW_WR1 + 2176)
#define HW_WR2  (HW_BR1 + 32)
#define HW_BR2  (HW_WR2 + 32)
#define HW_HB   (HW_BR2 + 4)
#define HEADS_SMEM_FLOATS (HW_HB + HT * 65)
#define HEADS_SMEM_BYTES  (HEADS_SMEM_FLOATS * 4)

__device__ const int c_offx[8] = {-1, 1, 0, 0, -1, -1, 1, 1};
__device__ const int c_offy[8] = {0, 0, 1, -1, -1, 1, -1, 1};

template <int V>
__device__ __forceinline__ int sample_lp(const float* lg, uint32_t k0, uint32_t k1,
                                         int b, float& lp) {
    const uint32_t half = (uint32_t)(BN * V / 2);
    int best = 0;
    float bestz = -1e30f, bestl = lg[0], m = -1e30f;
#pragma unroll
    for (int v = 0; v < V; v++) {
        float z = lg[v] + jax_gumbel(k0, k1, (uint32_t)(b * V + v), half);
        if (z > bestz) { bestz = z; best = v; bestl = lg[v]; }
        m = fmaxf(m, lg[v]);
    }
    float ssum = 0.f;
#pragma unroll
    for (int v = 0; v < V; v++) ssum += expf(lg[v] - m);
    lp = (bestl - m) - logf(ssum);
    return best;
}

__global__ void __launch_bounds__(HT)
heads_kernel(const int* __restrict__ canvas0, const int* __restrict__ canvas1,
             const int* __restrict__ refp,
             const float* __restrict__ Wc, const float* __restrict__ bc,
             const float* __restrict__ Ws, const float* __restrict__ bs,
             const float* __restrict__ Wl, const float* __restrict__ bl,
             const float* __restrict__ Wr1, const float* __restrict__ br1,
             const float* __restrict__ Wr2, const float* __restrict__ br2,
             const float* __restrict__ Wp, const float* __restrict__ bp,
             float* __restrict__ out, Keys keys) {
    extern __shared__ float sm[];
    const int tid = threadIdx.x;
    const int b = blockIdx.x * HT + tid;
    const int tile = blockIdx.x * HT;

    for (int i = tid; i < 192;  i += HT) sm[HW_WC + i] = Wc[i];
    for (int i = tid; i < 192;  i += HT) sm[HW_WS + i] = Ws[i];
    for (int i = tid; i < 1600; i += HT) sm[HW_WL + i] = Wl[i];
    for (int i = tid; i < 512;  i += HT) sm[HW_WP + i] = Wp[i];
    for (int i = tid; i < 2176; i += HT) sm[HW_WR1 + i] = Wr1[i];
    if (tid < 3)  sm[HW_BC + tid]  = bc[tid];
    if (tid < 3)  sm[HW_BS + tid]  = bs[tid];
    if (tid < 25) sm[HW_BL + tid]  = bl[tid];
    if (tid < 8)  sm[HW_BP + tid]  = bp[tid];
    if (tid < 32) sm[HW_BR1 + tid] = br1[tid];
    if (tid < 32) sm[HW_WR2 + tid] = Wr2[tid];
    if (tid == 0) sm[HW_BR2] = br2[0];

    float* hb = sm + HW_HB;
    for (int i = tid; i < HT * RNN; i += HT) {
        int s = i >> 6, k = i & 63;
        hb[s * 65 + k] = g_h[(tile + s) * RNN + k];
    }
    __syncthreads();

    // ======== dialog step 0 ========
    const float* h = hb + tid * 65;
    float lc[3], lsh[3], ll[25];
#pragma unroll
    for (int r = 0; r < 3; r++) {
        float d = 0.f, e = 0.f;
        for (int k = 0; k < 64; k++) {
            d = fmaf(h[k], sm[HW_WC + r * 64 + k], d);
            e = fmaf(h[k], sm[HW_WS + r * 64 + k], e);
        }
        lc[r] = d + sm[HW_BC + r];
        lsh[r] = e + sm[HW_BS + r];
    }
#pragma unroll 5
    for (int r = 0; r < 25; r++) {
        float d = 0.f;
        for (int k = 0; k < 64; k++) d = fmaf(h[k], sm[HW_WL + r * 64 + k], d);
        ll[r] = d + sm[HW_BL + r];
    }
    float clp0, slp0, llp0;
    int cs0  = sample_lp<3>(lc,  keys.a[0], keys.b[0], b, clp0);
    sample_lp<3>(lsh, keys.a[1], keys.b[1], b, slp0);
    int loc0 = sample_lp<25>(ll, keys.a[2], keys.b[2], b, llp0);

    int lclip = min(max(loc0, 0), 24);
    int4 pt = *(const int4*)(canvas1 + (b * 25 + lclip) * 4);
    bool ok0 = (loc0 >= 0) && (loc0 < 25) && ((pt.x + pt.y + pt.z + pt.w) >= 0);
    float loc_r0 = ok0 ? 1.f : -1.f;
    float col_r0 = ok0 ? ((cs0 == pt.x) ? 1.f : -1.f) : 0.f;

    __syncthreads();
    for (int i = tid; i < HT * RNN; i += HT) {
        int s = i >> 6, k = i & 63;
        hb[s * 65 + k] = g_h[BN * RNN + (tile + s) * RNN + k];
    }
    __syncthreads();

    // ======== dialog step 1 ========
    float lp8[8];
#pragma unroll
    for (int r = 0; r < 3; r++) {
        float d = 0.f, e = 0.f;
        for (int k = 0; k < 64; k++) {
            d = fmaf(h[k], sm[HW_WC + r * 64 + k], d);
            e = fmaf(h[k], sm[HW_WS + r * 64 + k], e);
        }
        lc[r] = d + sm[HW_BC + r];
        lsh[r] = e + sm[HW_BS + r];
    }
#pragma unroll 4
    for (int r = 0; r < 8; r++) {
        float d = 0.f;
        for (int k = 0; k < 64; k++) d = fmaf(h[k], sm[HW_WP + r * 64 + k], d);
        lp8[r] = d + sm[HW_BP + r];
    }
    float clp1, slp1, llp1, alp1;
    int cs1 = sample_lp<3>(lc,  keys.a[3], keys.b[3], b, clp1);
    sample_lp<3>(lsh, keys.a[4], keys.b[4], b, slp1);
    int ls1 = sample_lp<8>(lp8, keys.a[5], keys.b[5], b, llp1);

    float pre[32];
#pragma unroll 8
    for (int j = 0; j < 32; j++) {
        float d = 0.f;
        for (int k = 0; k < 64; k++) d = fmaf(h[k], sm[HW_WR1 + j * 68 + k], d);
        pre[j] = d + sm[HW_BR1 + j];
    }
    float al[25];
#pragma unroll
    for (int loc = 0; loc < 25; loc++) {
        int4 cv = *(const int4*)(canvas0 + (b * 25 + loc) * 4);
        float cx = (float)cv.x, cy = (float)cv.y, cz = (float)cv.z, cw = (float)cv.w;
        float a = sm[HW_BR2];
#pragma unroll
        for (int j = 0; j < 32; j++) {
            float v = pre[j];
            v = fmaf(cx, sm[HW_WR1 + j * 68 + 64], v);
            v = fmaf(cy, sm[HW_WR1 + j * 68 + 65], v);
            v = fmaf(cz, sm[HW_WR1 + j * 68 + 66], v);
            v = fmaf(cw, sm[HW_WR1 + j * 68 + 67], v);
            v = fmaxf(v, 0.f);
            a = fmaf(v, sm[HW_WR2 + j], a);
        }
        al[loc] = a;
    }
    int att = sample_lp<25>(al, keys.a[6], keys.b[6], b, alp1);

    int4 ro = *(const int4*)(canvas0 + (b * 25 + att) * 4);
    int4 rf = *(const int4*)(refp + b * 4);
    float att_rew = (ro.x == rf.x && ro.y == rf.y && ro.z == rf.z && ro.w == rf.w)
                        ? 1.f : -1.f;
    int loc1 = (ro.z + c_offx[ls1]) * 5 + (ro.w + c_offy[ls1]);
    int l1c = min(max(loc1, 0), 24);
    int4 pt1 = *(const int4*)(canvas1 + (b * 25 + l1c) * 4);
    bool ok1 = (loc1 >= 0) && (loc1 < 25) && ((pt1.x + pt1.y + pt1.z + pt1.w) >= 0);
    float loc_r1 = ok1 ? 1.f : -1.f;
    float col_r1 = ok1 ? ((cs1 == pt1.x) ? 1.f : -1.f) : 0.f;

    out[0 * BN + b] = clp0;
    out[1 * BN + b] = slp0;
    out[2 * BN + b] = llp0;
    out[3 * BN + b] = clp1;
    out[4 * BN + b] = slp1;
    out[5 * BN + b] = llp1;
    out[6 * BN + b] = alp1;
    out[(7 + 0) * BN + b] = loc_r0;
    out[(7 + 1) * BN + b] = col_r0;
    out[(7 + 2) * BN + b] = loc_r0;
    out[(7 + 3) * BN + b] = loc_r1;
    out[(7 + 4) * BN + b] = col_r1;
    out[(7 + 5) * BN + b] = loc_r1;
    out[(7 + 6) * BN + b] = att_rew;
}

// ---------------- launch ----------------
extern "C" void kernel_launch(void* const* d_in, const int* in_sizes, int n_in,
                              void* d_out, int out_size) {
    const int*   inst0   = (const int*)d_in[0];
    const int*   inst1   = (const int*)d_in[1];
    const int*   canvas0 = (const int*)d_in[2];
    const int*   canvas1 = (const int*)d_in[3];
    const int*   refp    = (const int*)d_in[4];
    const float* embed   = (const float*)d_in[5];
    const float* W_ih    = (const float*)d_in[6];
    const float* W_hh    = (const float*)d_in[7];
    const float* b_ih    = (const float*)d_in[8];
    const float* b_hh    = (const float*)d_in[9];
    const float* Wc      = (const float*)d_in[10];
    const float* bc      = (const float*)d_in[11];
    const float* Ws      = (const float*)d_in[12];
    const float* bs      = (const float*)d_in[13];
    const float* Wl      = (const float*)d_in[14];
    const float* bl      = (const float*)d_in[15];
    const float* Wr1     = (const float*)d_in[16];
    const float* br1     = (const float*)d_in[17];
    const float* Wr2     = (const float*)d_in[18];
    const float* br2     = (const float*)d_in[19];
    const float* Wp      = (const float*)d_in[20];
    const float* bp      = (const float*)d_in[21];

    Keys keys;
#if THREEFRY_PARTITIONABLE
    for (int i = 0; i < 7; i++)
        threefry2x32(0u, 42u, 0u, (uint32_t)i, keys.a[i], keys.b[i]);
#else
    uint32_t o[14];
    for (int i = 0; i < 7; i++)
        threefry2x32(0u, 42u, (uint32_t)i, (uint32_t)(i + 7), o[i], o[7 + i]);
    for (int i = 0; i < 7; i++) { keys.a[i] = o[2 * i]; keys.b[i] = o[2 * i + 1]; }
#endif

    cudaFuncSetAttribute(lstm_kernel, cudaFuncAttributeMaxDynamicSharedMemorySize,
                         LSTM_SMEM_BYTES);
    cudaFuncSetAttribute(heads_kernel, cudaFuncAttributeMaxDynamicSharedMemorySize,
                         HEADS_SMEM_BYTES);

    tokgate_kernel<<<VOCAB, 256>>>(embed, W_ih, b_ih, b_hh);
    lstm_kernel<<<dim3(BN / TB, 2), LSTM_THREADS, LSTM_SMEM_BYTES>>>(
        inst0, inst1, W_hh);
    heads_kernel<<<BN / HT, HT, HEADS_SMEM_BYTES>>>(
        canvas0, canvas1, refp, Wc, bc, Ws, bs, Wl, bl, Wr1, br1, Wr2, br2,
        Wp, bp, (float*)d_out, keys);
}

// round 5
// speedup vs baseline: 2.5898x; 1.0000x over previous
#include <cuda_runtime.h>
#include <cstdint>

#define BN 16384
#define SEQ 32
#define RNN 64
#define NG 256            // 4*RNN gates
#define VOCAB 1001

// LSTM tiling
#define TB 64             // samples per LSTM block
#define LSTM_THREADS 256
#define WS_STRIDE 260     // Wsm row stride (floats)
#define HT_STRIDE 68      // hT row stride (floats)

// heads
#define HT 64             // heads threads per block

#define THREEFRY_PARTITIONABLE 1

typedef unsigned long long u64;

// scratch: h outputs for dialog 0 and 1, token-gate table
__device__ float g_h[2 * BN * RNN];
__device__ float g_tokgate[VOCAB * NG];

// ---------------- f32x2 packed helpers (sm_103a) ----------------
__device__ __forceinline__ void fma2(u64& d, u64 a, u64 b) {
    asm("fma.rn.f32x2 %0, %1, %2, %0;" : "+l"(d) : "l"(a), "l"(b));
}
__device__ __forceinline__ u64 splat2(float x) {
    u64 r; asm("mov.b64 %0, {%1, %1};" : "=l"(r) : "f"(x)); return r;
}
__device__ __forceinline__ u64 pack2(float x, float y) {
    u64 r; asm("mov.b64 %0, {%1, %2};" : "=l"(r) : "f"(x), "f"(y)); return r;
}
__device__ __forceinline__ void unpack2(u64 v, float& x, float& y) {
    asm("mov.b64 {%0, %1}, %2;" : "=f"(x), "=f"(y) : "l"(v));
}

// ---------------- threefry2x32 (host+device, exact JAX algorithm) ----------------
__host__ __device__ __forceinline__ uint32_t rotl32(uint32_t x, int d) {
    return (x << d) | (x >> (32 - d));
}

__host__ __device__ __forceinline__ void threefry2x32(uint32_t k0, uint32_t k1,
                                                      uint32_t c0, uint32_t c1,
                                                      uint32_t& o0, uint32_t& o1) {
    uint32_t ks2 = k0 ^ k1 ^ 0x1BD11BDAu;
    uint32_t x0 = c0 + k0, x1 = c1 + k1;
#define TF_R4(a,b,c,d) \
    x0 += x1; x1 = rotl32(x1,a); x1 ^= x0; \
    x0 += x1; x1 = rotl32(x1,b); x1 ^= x0; \
    x0 += x1; x1 = rotl32(x1,c); x1 ^= x0; \
    x0 += x1; x1 = rotl32(x1,d); x1 ^= x0;
    TF_R4(13,15,26,6);  x0 += k1;  x1 += ks2 + 1u;
    TF_R4(17,29,16,24); x0 += ks2; x1 += k0  + 2u;
    TF_R4(13,15,26,6);  x0 += k0;  x1 += k1  + 3u;
    TF_R4(17,29,16,24); x0 += k1;  x1 += ks2 + 4u;
    TF_R4(13,15,26,6);  x0 += ks2; x1 += k0  + 5u;
#undef TF_R4
    o0 = x0; o1 = x1;
}

struct Keys { uint32_t a[7]; uint32_t b[7]; };

__device__ __forceinline__ uint32_t jax_bits32(uint32_t k0, uint32_t k1,
                                               uint32_t idx, uint32_t half) {
#if THREEFRY_PARTITIONABLE
    uint32_t y0, y1;
    threefry2x32(k0, k1, 0u, idx, y0, y1);
    return y0 ^ y1;
#else
    uint32_t p = (idx < half) ? idx : idx - half;
    uint32_t y0, y1;
    threefry2x32(k0, k1, p, p + half, y0, y1);
    return (idx < half) ? y0 : y1;
#endif
}

__device__ __forceinline__ float jax_gumbel(uint32_t k0, uint32_t k1,
                                            uint32_t idx, uint32_t half) {
    uint32_t bits = jax_bits32(k0, k1, idx, half);
    float f = __uint_as_float((bits >> 9) | 0x3f800000u) - 1.0f; // [0,1)
    f = fmaxf(f, 1.17549435e-38f);                                // minval=tiny
    return -logf(-logf(f));
}

__device__ __forceinline__ float sigf(float x) {
    // XLA logistic lowering: 0.5 + 0.5*tanh(0.5 x)
    return fmaf(0.5f, tanhf(0.5f * x), 0.5f);
}

// ---------------- tokgate precompute ----------------
// g_tokgate[v][c], c = 4*u + g  (gate-interleaved), value = embed[v] . W_ih[g*64+u] + b_ih + b_hh
__global__ void __launch_bounds__(256)
tokgate_kernel(const float* __restrict__ embed,
               const float* __restrict__ W_ih,
               const float* __restrict__ b_ih, const float* __restrict__ b_hh) {
    __shared__ float e[RNN];
    int v = blockIdx.x;
    int c = threadIdx.x;
    if (c < RNN) e[c] = embed[v * RNN + c];
    __syncthreads();
    int g = c & 3, u = c >> 2;
    int row = g * 64 + u;
    float d = b_ih[row] + b_hh[row];
    const float* w = W_ih + row * RNN;
#pragma unroll
    for (int k = 0; k < RNN; k++) d = fmaf(e[k], w[k], d);
    g_tokgate[v * NG + c] = d;
}

// ---------------- LSTM kernel ----------------
// smem: Wsm[64][WS_STRIDE] | hT[64][HT_STRIDE] | tok[64][32]
#define SM_W    0
#define SM_H    (64 * WS_STRIDE)
#define SM_TOK  (SM_H + 64 * HT_STRIDE)
#define LSTM_SMEM_BYTES ((SM_TOK + TB * SEQ) * 4)

__global__ void __launch_bounds__(LSTM_THREADS, 2)
lstm_kernel(const int* __restrict__ inst0, const int* __restrict__ inst1,
            const float* __restrict__ W_hh) {
    extern __shared__ float sm[];
    float* Wsm = sm + SM_W;
    float* hT  = sm + SM_H;     // [u][s]
    int*   tok = (int*)(sm + SM_TOK);

    const int tid  = threadIdx.x;
    const int base = blockIdx.x * TB;
    const int* inst = (blockIdx.y == 0) ? inst0 : inst1;
    float* hout = g_h + blockIdx.y * (BN * RNN);

    // W_hh permuted: Wsm[k][c], c = 4u+g <- W_hh[(g*64+u)][k]
    for (int idx = tid; idx < RNN * NG; idx += LSTM_THREADS) {
        int c = idx >> 6, k = idx & 63;
        int g = c & 3, u = c >> 2;
        Wsm[k * WS_STRIDE + c] = W_hh[(g * 64 + u) * RNN + k];
    }
    for (int idx = tid; idx < 64 * HT_STRIDE; idx += LSTM_THREADS) hT[idx] = 0.f;
    for (int idx = tid; idx < TB * SEQ; idx += LSTM_THREADS)
        tok[idx] = inst[base * SEQ + idx];

    float c_reg[16];
#pragma unroll
    for (int i = 0; i < 16; i++) c_reg[i] = 0.f;
    __syncthreads();

    const int gj    = tid & 31;        // column group: c = gj*8 .. gj*8+7  (units 2gj, 2gj+1)
    const int si8   = (tid >> 5) * 8;  // samples si8 .. si8+7 (warp-uniform)
    const int cbase = gj * 8;

    for (int t = 0; t < SEQ; t++) {
        // ---- acc init = tokgate gather (x-side GEMM precomputed) ----
        u64 acc[8][4];
#pragma unroll
        for (int r = 0; r < 8; r++) {
            int tk = tok[(si8 + r) * SEQ + t];
            const float4* tg = (const float4*)(g_tokgate + tk * NG + cbase);
            float4 g0 = tg[0], g1 = tg[1];
            acc[r][0] = pack2(g0.x, g0.y);
            acc[r][1] = pack2(g0.z, g0.w);
            acc[r][2] = pack2(g1.x, g1.y);
            acc[r][3] = pack2(g1.z, g1.w);
        }

        // ---- recurrent GEMM: gates += h_prev @ W_hh (packed f32x2) ----
#pragma unroll 2
        for (int k = 0; k < 64; k++) {
            const float* wr = Wsm + k * WS_STRIDE + cbase;
            ulonglong2 wA = *(const ulonglong2*)wr;        // cols (c,c+1),(c+2,c+3)
            ulonglong2 wB = *(const ulonglong2*)(wr + 4);  // cols (c+4,c+5),(c+6,c+7)
            const float* ar = hT + k * HT_STRIDE + si8;
            float4 a0 = *(const float4*)ar;
            float4 a1 = *(const float4*)(ar + 4);
            u64 s0 = splat2(a0.x), s1 = splat2(a0.y), s2 = splat2(a0.z), s3 = splat2(a0.w);
            u64 s4 = splat2(a1.x), s5 = splat2(a1.y), s6 = splat2(a1.z), s7 = splat2(a1.w);
#define ROW(r, sv) \
            fma2(acc[r][0], wA.x, sv); fma2(acc[r][1], wA.y, sv); \
            fma2(acc[r][2], wB.x, sv); fma2(acc[r][3], wB.y, sv);
            ROW(0, s0) ROW(1, s1) ROW(2, s2) ROW(3, s3)
            ROW(4, s4) ROW(5, s5) ROW(6, s6) ROW(7, s7)
#undef ROW
        }
        __syncthreads();   // all reads of hT done before rewrite

        // ---- cell update: fully thread-local (gate-interleaved layout) ----
#pragma unroll
        for (int ul = 0; ul < 2; ul++) {
            float hv[8];
#pragma unroll
            for (int r = 0; r < 8; r++) {
                float ig, fg, gg, og;
                unpack2(acc[r][2 * ul],     ig, fg);
                unpack2(acc[r][2 * ul + 1], gg, og);
                float c = sigf(fg) * c_reg[ul * 8 + r] + sigf(ig) * tanhf(gg);
                float h = sigf(og) * tanhf(c);
                c_reg[ul * 8 + r] = c;
                hv[r] = h;
            }
            float* dst = hT + (2 * gj + ul) * HT_STRIDE + si8;
            *(float4*)dst       = make_float4(hv[0], hv[1], hv[2], hv[3]);
            *(float4*)(dst + 4) = make_float4(hv[4], hv[5], hv[6], hv[7]);
            if (t == SEQ - 1) {
#pragma unroll
                for (int r = 0; r < 8; r++)
                    hout[(base + si8 + r) * RNN + 2 * gj + ul] = hv[r];
            }
        }
        __syncthreads();   // h写 complete before next step's reads
    }
}

// ---------------- heads kernel ----------------
#define HW_WC   0
#define HW_BC   (HW_WC + 192)
#define HW_WS   (HW_BC + 4)
#define HW_BS   (HW_WS + 192)
#define HW_WL   (HW_BS + 4)
#define HW_BL   (HW_WL + 1600)
#define HW_WP   (HW_BL + 28)
#define HW_BP   (HW_WP + 512)
#define HW_WR1  (HW_BP + 8)
#define HW_BR1  (HW_WR1 + 2176)
#define HW_WR2  (HW_BR1 + 32)
#define HW_BR2  (HW_WR2 + 32)
#define HW_HB   (HW_BR2 + 4)
#define HEADS_SMEM_FLOATS (HW_HB + HT * 65)
#define HEADS_SMEM_BYTES  (HEADS_SMEM_FLOATS * 4)

__device__ const int c_offx[8] = {-1, 1, 0, 0, -1, -1, 1, 1};
__device__ const int c_offy[8] = {0, 0, 1, -1, -1, 1, -1, 1};

template <int V>
__device__ __forceinline__ int sample_lp(const float* lg, uint32_t k0, uint32_t k1,
                                         int b, float& lp) {
    const uint32_t half = (uint32_t)(BN * V / 2);
    int best = 0;
    float bestz = -1e30f, bestl = lg[0], m = -1e30f;
#pragma unroll
    for (int v = 0; v < V; v++) {
        float z = lg[v] + jax_gumbel(k0, k1, (uint32_t)(b * V + v), half);
        if (z > bestz) { bestz = z; best = v; bestl = lg[v]; }
        m = fmaxf(m, lg[v]);
    }
    float ssum = 0.f;
#pragma unroll
    for (int v = 0; v < V; v++) ssum += expf(lg[v] - m);
    lp = (bestl - m) - logf(ssum);
    return best;
}

__global__ void __launch_bounds__(HT)
heads_kernel(const int* __restrict__ canvas0, const int* __restrict__ canvas1,
             const int* __restrict__ refp,
             const float* __restrict__ Wc, const float* __restrict__ bc,
             const float* __restrict__ Ws, const float* __restrict__ bs,
             const float* __restrict__ Wl, const float* __restrict__ bl,
             const float* __restrict__ Wr1, const float* __restrict__ br1,
             const float* __restrict__ Wr2, const float* __restrict__ br2,
             const float* __restrict__ Wp, const float* __restrict__ bp,
             float* __restrict__ out, Keys keys) {
    extern __shared__ float sm[];
    const int tid = threadIdx.x;
    const int b = blockIdx.x * HT + tid;
    const int tile = blockIdx.x * HT;

    for (int i = tid; i < 192;  i += HT) sm[HW_WC + i] = Wc[i];
    for (int i = tid; i < 192;  i += HT) sm[HW_WS + i] = Ws[i];
    for (int i = tid; i < 1600; i += HT) sm[HW_WL + i] = Wl[i];
    for (int i = tid; i < 512;  i += HT) sm[HW_WP + i] = Wp[i];
    for (int i = tid; i < 2176; i += HT) sm[HW_WR1 + i] = Wr1[i];
    if (tid < 3)  sm[HW_BC + tid]  = bc[tid];
    if (tid < 3)  sm[HW_BS + tid]  = bs[tid];
    if (tid < 25) sm[HW_BL + tid]  = bl[tid];
    if (tid < 8)  sm[HW_BP + tid]  = bp[tid];
    if (tid < 32) sm[HW_BR1 + tid] = br1[tid];
    if (tid < 32) sm[HW_WR2 + tid] = Wr2[tid];
    if (tid == 0) sm[HW_BR2] = br2[0];

    float* hb = sm + HW_HB;
    for (int i = tid; i < HT * RNN; i += HT) {
        int s = i >> 6, k = i & 63;
        hb[s * 65 + k] = g_h[(tile + s) * RNN + k];
    }
    __syncthreads();

    // ======== dialog step 0 ========
    const float* h = hb + tid * 65;
    float lc[3], lsh[3], ll[25];
#pragma unroll
    for (int r = 0; r < 3; r++) {
        float d = 0.f, e = 0.f;
        for (int k = 0; k < 64; k++) {
            d = fmaf(h[k], sm[HW_WC + r * 64 + k], d);
            e = fmaf(h[k], sm[HW_WS + r * 64 + k], e);
        }
        lc[r] = d + sm[HW_BC + r];
        lsh[r] = e + sm[HW_BS + r];
    }
#pragma unroll 5
    for (int r = 0; r < 25; r++) {
        float d = 0.f;
        for (int k = 0; k < 64; k++) d = fmaf(h[k], sm[HW_WL + r * 64 + k], d);
        ll[r] = d + sm[HW_BL + r];
    }
    float clp0, slp0, llp0;
    int cs0  = sample_lp<3>(lc,  keys.a[0], keys.b[0], b, clp0);
    sample_lp<3>(lsh, keys.a[1], keys.b[1], b, slp0);
    int loc0 = sample_lp<25>(ll, keys.a[2], keys.b[2], b, llp0);

    int lclip = min(max(loc0, 0), 24);
    int4 pt = *(const int4*)(canvas1 + (b * 25 + lclip) * 4);
    bool ok0 = (loc0 >= 0) && (loc0 < 25) && ((pt.x + pt.y + pt.z + pt.w) >= 0);
    float loc_r0 = ok0 ? 1.f : -1.f;
    float col_r0 = ok0 ? ((cs0 == pt.x) ? 1.f : -1.f) : 0.f;

    __syncthreads();
    for (int i = tid; i < HT * RNN; i += HT) {
        int s = i >> 6, k = i & 63;
        hb[s * 65 + k] = g_h[BN * RNN + (tile + s) * RNN + k];
    }
    __syncthreads();

    // ======== dialog step 1 ========
    float lp8[8];
#pragma unroll
    for (int r = 0; r < 3; r++) {
        float d = 0.f, e = 0.f;
        for (int k = 0; k < 64; k++) {
            d = fmaf(h[k], sm[HW_WC + r * 64 + k], d);
            e = fmaf(h[k], sm[HW_WS + r * 64 + k], e);
        }
        lc[r] = d + sm[HW_BC + r];
        lsh[r] = e + sm[HW_BS + r];
    }
#pragma unroll 4
    for (int r = 0; r < 8; r++) {
        float d = 0.f;
        for (int k = 0; k < 64; k++) d = fmaf(h[k], sm[HW_WP + r * 64 + k], d);
        lp8[r] = d + sm[HW_BP + r];
    }
    float clp1, slp1, llp1, alp1;
    int cs1 = sample_lp<3>(lc,  keys.a[3], keys.b[3], b, clp1);
    sample_lp<3>(lsh, keys.a[4], keys.b[4], b, slp1);
    int ls1 = sample_lp<8>(lp8, keys.a[5], keys.b[5], b, llp1);

    float pre[32];
#pragma unroll 8
    for (int j = 0; j < 32; j++) {
        float d = 0.f;
        for (int k = 0; k < 64; k++) d = fmaf(h[k], sm[HW_WR1 + j * 68 + k], d);
        pre[j] = d + sm[HW_BR1 + j];
    }
    float al[25];
#pragma unroll
    for (int loc = 0; loc < 25; loc++) {
        int4 cv = *(const int4*)(canvas0 + (b * 25 + loc) * 4);
        float cx = (float)cv.x, cy = (float)cv.y, cz = (float)cv.z, cw = (float)cv.w;
        float a = sm[HW_BR2];
#pragma unroll
        for (int j = 0; j < 32; j++) {
            float v = pre[j];
            v = fmaf(cx, sm[HW_WR1 + j * 68 + 64], v);
            v = fmaf(cy, sm[HW_WR1 + j * 68 + 65], v);
            v = fmaf(cz, sm[HW_WR1 + j * 68 + 66], v);
            v = fmaf(cw, sm[HW_WR1 + j * 68 + 67], v);
            v = fmaxf(v, 0.f);
            a = fmaf(v, sm[HW_WR2 + j], a);
        }
        al[loc] = a;
    }
    int att = sample_lp<25>(al, keys.a[6], keys.b[6], b, alp1);

    int4 ro = *(const int4*)(canvas0 + (b * 25 + att) * 4);
    int4 rf = *(const int4*)(refp + b * 4);
    float att_rew = (ro.x == rf.x && ro.y == rf.y && ro.z == rf.z && ro.w == rf.w)
                        ? 1.f : -1.f;
    int loc1 = (ro.z + c_offx[ls1]) * 5 + (ro.w + c_offy[ls1]);
    int l1c = min(max(loc1, 0), 24);
    int4 pt1 = *(const int4*)(canvas1 + (b * 25 + l1c) * 4);
    bool ok1 = (loc1 >= 0) && (loc1 < 25) && ((pt1.x + pt1.y + pt1.z + pt1.w) >= 0);
    float loc_r1 = ok1 ? 1.f : -1.f;
    float col_r1 = ok1 ? ((cs1 == pt1.x) ? 1.f : -1.f) : 0.f;

    out[0 * BN + b] = clp0;
    out[1 * BN + b] = slp0;
    out[2 * BN + b] = llp0;
    out[3 * BN + b] = clp1;
    out[4 * BN + b] = slp1;
    out[5 * BN + b] = llp1;
    out[6 * BN + b] = alp1;
    out[(7 + 0) * BN + b] = loc_r0;
    out[(7 + 1) * BN + b] = col_r0;
    out[(7 + 2) * BN + b] = loc_r0;
    out[(7 + 3) * BN + b] = loc_r1;
    out[(7 + 4) * BN + b] = col_r1;
    out[(7 + 5) * BN + b] = loc_r1;
    out[(7 + 6) * BN + b] = att_rew;
}

// ---------------- launch ----------------
extern "C" void kernel_launch(void* const* d_in, const int* in_sizes, int n_in,
                              void* d_out, int out_size) {
    const int*   inst0   = (const int*)d_in[0];
    const int*   inst1   = (const int*)d_in[1];
    const int*   canvas0 = (const int*)d_in[2];
    const int*   canvas1 = (const int*)d_in[3];
    const int*   refp    = (const int*)d_in[4];
    const float* embed   = (const float*)d_in[5];
    const float* W_ih    = (const float*)d_in[6];
    const float* W_hh    = (const float*)d_in[7];
    const float* b_ih    = (const float*)d_in[8];
    const float* b_hh    = (const float*)d_in[9];
    const float* Wc      = (const float*)d_in[10];
    const float* bc      = (const float*)d_in[11];
    const float* Ws      = (const float*)d_in[12];
    const float* bs      = (const float*)d_in[13];
    const float* Wl      = (const float*)d_in[14];
    const float* bl      = (const float*)d_in[15];
    const float* Wr1     = (const float*)d_in[16];
    const float* br1     = (const float*)d_in[17];
    const float* Wr2     = (const float*)d_in[18];
    const float* br2     = (const float*)d_in[19];
    const float* Wp      = (const float*)d_in[20];
    const float* bp      = (const float*)d_in[21];

    Keys keys;
#if THREEFRY_PARTITIONABLE
    for (int i = 0; i < 7; i++)
        threefry2x32(0u, 42u, 0u, (uint32_t)i, keys.a[i], keys.b[i]);
#else
    uint32_t o[14];
    for (int i = 0; i < 7; i++)
        threefry2x32(0u, 42u, (uint32_t)i, (uint32_t)(i + 7), o[i], o[7 + i]);
    for (int i = 0; i < 7; i++) { keys.a[i] = o[2 * i]; keys.b[i] = o[2 * i + 1]; }
#endif

    cudaFuncSetAttribute(lstm_kernel, cudaFuncAttributeMaxDynamicSharedMemorySize,
                         LSTM_SMEM_BYTES);
    cudaFuncSetAttribute(heads_kernel, cudaFuncAttributeMaxDynamicSharedMemorySize,
                         HEADS_SMEM_BYTES);

    tokgate_kernel<<<VOCAB, 256>>>(embed, W_ih, b_ih, b_hh);
    lstm_kernel<<<dim3(BN / TB, 2), LSTM_THREADS, LSTM_SMEM_BYTES>>>(
        inst0, inst1, W_hh);
    heads_kernel<<<BN / HT, HT, HEADS_SMEM_BYTES>>>(
        canvas0, canvas1, refp, Wc, bc, Ws, bs, Wl, bl, Wr1, br1, Wr2, br2,
        Wp, bp, (float*)d_out, keys);
}

// round 7
// speedup vs baseline: 2.6485x; 1.0227x over previous
#include <cuda_runtime.h>
#include <cstdint>

#define BN 16384
#define SEQ 32
#define RNN 64
#define NG 256
#define VOCAB 1001
#define TBM 32             // samples per LSTM CTA
#define HT 64              // heads threads per block
#define THREEFRY_PARTITIONABLE 1

typedef unsigned long long u64;

__device__ float g_h[2 * BN * RNN];
__device__ float g_tokgate[VOCAB * NG];

// ================= threefry2x32 (exact JAX algorithm) =================
__host__ __device__ __forceinline__ uint32_t rotl32(uint32_t x, int d) {
    return (x << d) | (x >> (32 - d));
}
__host__ __device__ __forceinline__ void threefry2x32(uint32_t k0, uint32_t k1,
                                                      uint32_t c0, uint32_t c1,
                                                      uint32_t& o0, uint32_t& o1) {
    uint32_t ks2 = k0 ^ k1 ^ 0x1BD11BDAu;
    uint32_t x0 = c0 + k0, x1 = c1 + k1;
#define TF_R4(a,b,c,d) \
    x0 += x1; x1 = rotl32(x1,a); x1 ^= x0; \
    x0 += x1; x1 = rotl32(x1,b); x1 ^= x0; \
    x0 += x1; x1 = rotl32(x1,c); x1 ^= x0; \
    x0 += x1; x1 = rotl32(x1,d); x1 ^= x0;
    TF_R4(13,15,26,6);  x0 += k1;  x1 += ks2 + 1u;
    TF_R4(17,29,16,24); x0 += ks2; x1 += k0  + 2u;
    TF_R4(13,15,26,6);  x0 += k0;  x1 += k1  + 3u;
    TF_R4(17,29,16,24); x0 += k1;  x1 += ks2 + 4u;
    TF_R4(13,15,26,6);  x0 += ks2; x1 += k0  + 5u;
#undef TF_R4
    o0 = x0; o1 = x1;
}

struct Keys { uint32_t a[7]; uint32_t b[7]; };

__device__ __forceinline__ uint32_t jax_bits32(uint32_t k0, uint32_t k1,
                                               uint32_t idx, uint32_t half) {
#if THREEFRY_PARTITIONABLE
    uint32_t y0, y1;
    threefry2x32(k0, k1, 0u, idx, y0, y1);
    return y0 ^ y1;
#else
    uint32_t p = (idx < half) ? idx : idx - half;
    uint32_t y0, y1;
    threefry2x32(k0, k1, p, p + half, y0, y1);
    return (idx < half) ? y0 : y1;
#endif
}
__device__ __forceinline__ float jax_gumbel(uint32_t k0, uint32_t k1,
                                            uint32_t idx, uint32_t half) {
    uint32_t bits = jax_bits32(k0, k1, idx, half);
    float f = __uint_as_float((bits >> 9) | 0x3f800000u) - 1.0f;
    f = fmaxf(f, 1.17549435e-38f);
    return -logf(-logf(f));
}
__device__ __forceinline__ float sigf(float x) {
    return fmaf(0.5f, tanhf(0.5f * x), 0.5f);   // XLA logistic lowering
}
__device__ __forceinline__ uint32_t tf32_bits(float x) {
    uint32_t r; asm("cvt.rna.tf32.f32 %0, %1;" : "=r"(r) : "f"(x)); return r;
}

// mma.sync m16n8k8 tf32 (baseline PTX, drives HMMA tensor pipe on sm_103)
__device__ __forceinline__ void mma_tf32(float d[4], const uint32_t a[4],
                                         uint32_t b0, uint32_t b1) {
    asm volatile(
        "mma.sync.aligned.m16n8k8.row.col.f32.tf32.tf32.f32 "
        "{%0,%1,%2,%3}, {%4,%5,%6,%7}, {%8,%9}, {%0,%1,%2,%3};"
        : "+f"(d[0]), "+f"(d[1]), "+f"(d[2]), "+f"(d[3])
        : "r"(a[0]), "r"(a[1]), "r"(a[2]), "r"(a[3]), "r"(b0), "r"(b1));
}

// ================= tokgate precompute =================
// g_tokgate[v][c], c = 4u+g : embed[v] . W_ih[g*64+u] + b_ih + b_hh
__global__ void __launch_bounds__(256)
tokgate_kernel(const float* __restrict__ embed, const float* __restrict__ W_ih,
               const float* __restrict__ b_ih, const float* __restrict__ b_hh) {
    __shared__ float e[8][64];
    const int v0 = blockIdx.x * 8;
    const int tid = threadIdx.x;
    for (int i = tid; i < 8 * 64; i += 256) {
        int vv = v0 + (i >> 6);
        e[i >> 6][i & 63] = (vv < VOCAB) ? embed[vv * 64 + (i & 63)] : 0.f;
    }
    __syncthreads();
    const int c = tid, gg = c & 3, u = c >> 2;
    const int row = gg * 64 + u;
    float wreg[64];
    const float4* wp = (const float4*)(W_ih + row * 64);
#pragma unroll
    for (int i = 0; i < 16; i++) {
        float4 w4 = wp[i];
        wreg[4 * i] = w4.x; wreg[4 * i + 1] = w4.y;
        wreg[4 * i + 2] = w4.z; wreg[4 * i + 3] = w4.w;
    }
    const float bias = b_ih[row] + b_hh[row];
#pragma unroll
    for (int j = 0; j < 8; j++) {
        int v = v0 + j;
        if (v >= VOCAB) break;
        float d = bias;
#pragma unroll
        for (int k = 0; k < 64; k++) d = fmaf(e[j][k], wreg[k], d);
        g_tokgate[v * NG + c] = d;
    }
}

// ================= LSTM kernel (mma.sync tf32, 3-product compensation) =================
// smem (32-bit words):
//   Whi [64][264]          @ 0        (tf32 bits; col order c' below)
//   Wlo [64][264]          @ 16896
//   hsm [2buf][2spl][32][68] @ 33792  (tf32 bits of h)
//   tok [32][32] (int)     @ 42496
// total 43520 words = 174080 bytes
#define WSTR 264
#define HSTR 68
#define OFF_WHI 0
#define OFF_WLO (64 * WSTR)
#define OFF_HSM (2 * 64 * WSTR)
#define OFF_TOK (OFF_HSM + 2 * 2 * TBM * HSTR)
#define LSTM_SMEM_WORDS (OFF_TOK + TBM * SEQ)
#define LSTM_SMEM_BYTES (LSTM_SMEM_WORDS * 4)
// column order: c' = nb*64 + nt*8 + 4*up + g ; unit u = nb*16 + nt*2 + up

__global__ void __launch_bounds__(256, 1)
lstm_kernel(const int* __restrict__ inst0, const int* __restrict__ inst1,
            const float* __restrict__ W_hh) {
    extern __shared__ uint32_t smw[];
    uint32_t* Whi = smw + OFF_WHI;
    uint32_t* Wlo = smw + OFF_WLO;
    uint32_t* hsm = smw + OFF_HSM;            // [buf][split][s][HSTR]
    int*      tok = (int*)(smw + OFF_TOK);    // [s][t]

    const int tid  = threadIdx.x;
    const int wid  = tid >> 5, lane = tid & 31;
    const int gid  = lane >> 2, tig = lane & 3;
    const int mb   = wid & 1;                 // m-block: samples mb*16..mb*16+15
    const int nb   = wid >> 1;                // n-block: cols nb*64..nb*64+63
    const int base = blockIdx.x * TBM;
    const int* inst = (blockIdx.y == 0) ? inst0 : inst1;
    float* hout = g_h + blockIdx.y * (BN * RNN);

    // ---- stage W_hh split into tf32 hi/lo, permuted column order ----
    for (int idx = tid; idx < 64 * NG; idx += 256) {
        int k = idx >> 8, c = idx & 255;
        int cnb = c >> 6, cnt = (c >> 3) & 7, cup = (c >> 2) & 1, cg = c & 3;
        int u = cnb * 16 + cnt * 2 + cup;
        float w = W_hh[(cg * 64 + u) * 64 + k];
        uint32_t hb = tf32_bits(w);
        uint32_t lb = tf32_bits(w - __uint_as_float(hb));
        Whi[k * WSTR + c] = hb;
        Wlo[k * WSTR + c] = lb;
    }
    // tokens
    for (int idx = tid; idx < TBM * SEQ; idx += 256)
        tok[idx] = inst[base * SEQ + idx];
    // zero h buffer 0 (both splits)
    for (int idx = tid; idx < 2 * TBM * HSTR; idx += 256)
        hsm[idx] = 0u;
    __syncthreads();

    // thread's fixed sample row & unit-pair half
    const int row   = mb * 16 + gid + 8 * (tig & 1);
    const int upair = tig >> 1;
    float c_reg[8];
#pragma unroll
    for (int i = 0; i < 8; i++) c_reg[i] = 0.f;

    for (int t = 0; t < SEQ; t++) {
        const int rbuf = t & 1, wbuf = rbuf ^ 1;
        const uint32_t* Hhi = hsm + (rbuf * 2 + 0) * TBM * HSTR;
        const uint32_t* Hlo = hsm + (rbuf * 2 + 1) * TBM * HSTR;

        float d[8][4];
#pragma unroll
        for (int nt = 0; nt < 8; nt++)
#pragma unroll
            for (int j = 0; j < 4; j++) d[nt][j] = 0.f;

#pragma unroll
        for (int kc = 0; kc < 8; kc++) {
            const int k0 = kc * 8 + tig;
            uint32_t ahi[4], alo[4];
            ahi[0] = Hhi[(mb * 16 + gid)     * HSTR + k0];
            ahi[1] = Hhi[(mb * 16 + gid + 8) * HSTR + k0];
            ahi[2] = Hhi[(mb * 16 + gid)     * HSTR + k0 + 4];
            ahi[3] = Hhi[(mb * 16 + gid + 8) * HSTR + k0 + 4];
            alo[0] = Hlo[(mb * 16 + gid)     * HSTR + k0];
            alo[1] = Hlo[(mb * 16 + gid + 8) * HSTR + k0];
            alo[2] = Hlo[(mb * 16 + gid)     * HSTR + k0 + 4];
            alo[3] = Hlo[(mb * 16 + gid + 8) * HSTR + k0 + 4];

            const int bcol = nb * 64 + gid;
            uint32_t bh[8][2];
            // pass 1: hi . Whi  (cache Bhi frags)
#pragma unroll
            for (int nt = 0; nt < 8; nt++) {
                bh[nt][0] = Whi[k0 * WSTR + bcol + nt * 8];
                bh[nt][1] = Whi[(k0 + 4) * WSTR + bcol + nt * 8];
                mma_tf32(d[nt], ahi, bh[nt][0], bh[nt][1]);
            }
            // pass 2: lo . Whi  (reuse cached Bhi)
#pragma unroll
            for (int nt = 0; nt < 8; nt++)
                mma_tf32(d[nt], alo, bh[nt][0], bh[nt][1]);
            // pass 3: hi . Wlo
#pragma unroll
            for (int nt = 0; nt < 8; nt++) {
                uint32_t bl0 = Wlo[k0 * WSTR + bcol + nt * 8];
                uint32_t bl1 = Wlo[(k0 + 4) * WSTR + bcol + nt * 8];
                mma_tf32(d[nt], ahi, bl0, bl1);
            }
        }

        // ---- epilogue: quad-exchange, + tokgate, LSTM cell, store h hi/lo ----
        const int tv = tok[row * SEQ + t];
        const float* tgrow = g_tokgate + tv * NG;
        uint32_t* WHhi = hsm + (wbuf * 2 + 0) * TBM * HSTR;
        uint32_t* WHlo = hsm + (wbuf * 2 + 1) * TBM * HSTR;
        const bool e = (tig & 1) == 0;

#pragma unroll
        for (int nt = 0; nt < 8; nt++) {
            float r0 = __shfl_xor_sync(0xffffffffu, d[nt][0], 1);
            float r1 = __shfl_xor_sync(0xffffffffu, d[nt][1], 1);
            float r2 = __shfl_xor_sync(0xffffffffu, d[nt][2], 1);
            float r3 = __shfl_xor_sync(0xffffffffu, d[nt][3], 1);
            float ig = e ? d[nt][0] : r2;
            float fg = e ? d[nt][1] : r3;
            float gg = e ? r0 : d[nt][2];
            float og = e ? r1 : d[nt][3];
            const int u = nb * 16 + nt * 2 + upair;
            float4 tgv = *(const float4*)(tgrow + 4 * u);
            ig += tgv.x; fg += tgv.y; gg += tgv.z; og += tgv.w;
            float cb = sigf(fg) * c_reg[nt] + sigf(ig) * tanhf(gg);
            float h = sigf(og) * tanhf(cb);
            c_reg[nt] = cb;
            uint32_t hb = tf32_bits(h);
            WHhi[row * HSTR + u] = hb;
            WHlo[row * HSTR + u] = tf32_bits(h - __uint_as_float(hb));
            if (t == SEQ - 1) hout[(base + row) * RNN + u] = h;
        }
        __syncthreads();
    }
}

// ================= heads kernel =================
#define HW_WC   0
#define HW_BC   (HW_WC + 192)
#define HW_WS   (HW_BC + 4)
#define HW_BS   (HW_WS + 192)
#define HW_WL   (HW_BS + 4)
#define HW_BL   (HW_WL + 1600)
#define HW_WP   (HW_BL + 28)
#define HW_BP   (HW_WP + 512)
#define HW_WR1  (HW_BP + 8)
#define HW_BR1  (HW_WR1 + 2176)
#define HW_WR2  (HW_BR1 + 32)
#define HW_BR2  (HW_WR2 + 32)
#define HW_HB   (HW_BR2 + 4)
#define HEADS_SMEM_FLOATS (HW_HB + HT * 65)
#define HEADS_SMEM_BYTES  (HEADS_SMEM_FLOATS * 4)

__device__ const int c_offx[8] = {-1, 1, 0, 0, -1, -1, 1, 1};
__device__ const int c_offy[8] = {0, 0, 1, -1, -1, 1, -1, 1};

template <int V>
__device__ __forceinline__ int sample_lp(const float* lg, uint32_t k0, uint32_t k1,
                                         int b, float& lp) {
    const uint32_t half = (uint32_t)(BN * V / 2);
    int best = 0;
    float bestz = -1e30f, bestl = lg[0], m = -1e30f;
#pragma unroll
    for (int v = 0; v < V; v++) {
        float z = lg[v] + jax_gumbel(k0, k1, (uint32_t)(b * V + v), half);
        if (z > bestz) { bestz = z; best = v; bestl = lg[v]; }
        m = fmaxf(m, lg[v]);
    }
    float ssum = 0.f;
#pragma unroll
    for (int v = 0; v < V; v++) ssum += expf(lg[v] - m);
    lp = (bestl - m) - logf(ssum);
    return best;
}

__global__ void __launch_bounds__(HT)
heads_kernel(const int* __restrict__ canvas0, const int* __restrict__ canvas1,
             const int* __restrict__ refp,
             const float* __restrict__ Wc, const float* __restrict__ bc,
             const float* __restrict__ Ws, const float* __restrict__ bs,
             const float* __restrict__ Wl, const float* __restrict__ bl,
             const float* __restrict__ Wr1, const float* __restrict__ br1,
             const float* __restrict__ Wr2, const float* __restrict__ br2,
             const float* __restrict__ Wp, const float* __restrict__ bp,
             float* __restrict__ out, Keys keys) {
    extern __shared__ float sm[];
    const int tid = threadIdx.x;
    const int b = blockIdx.x * HT + tid;
    const int tile = blockIdx.x * HT;

    for (int i = tid; i < 192;  i += HT) sm[HW_WC + i] = Wc[i];
    for (int i = tid; i < 192;  i += HT) sm[HW_WS + i] = Ws[i];
    for (int i = tid; i < 1600; i += HT) sm[HW_WL + i] = Wl[i];
    for (int i = tid; i < 512;  i += HT) sm[HW_WP + i] = Wp[i];
    for (int i = tid; i < 2176; i += HT) sm[HW_WR1 + i] = Wr1[i];
    if (tid < 3)  sm[HW_BC + tid]  = bc[tid];
    if (tid < 3)  sm[HW_BS + tid]  = bs[tid];
    if (tid < 25) sm[HW_BL + tid]  = bl[tid];
    if (tid < 8)  sm[HW_BP + tid]  = bp[tid];
    if (tid < 32) sm[HW_BR1 + tid] = br1[tid];
    if (tid < 32) sm[HW_WR2 + tid] = Wr2[tid];
    if (tid == 0) sm[HW_BR2] = br2[0];

    float* hb = sm + HW_HB;
    for (int i = tid; i < HT * RNN; i += HT) {
        int s = i >> 6, k = i & 63;
        hb[s * 65 + k] = g_h[(tile + s) * RNN + k];
    }
    __syncthreads();

    // ======== dialog step 0 ========
    const float* h = hb + tid * 65;
    float lc[3], lsh[3], ll[25];
#pragma unroll
    for (int r = 0; r < 3; r++) {
        float d = 0.f, e = 0.f;
        for (int k = 0; k < 64; k++) {
            d = fmaf(h[k], sm[HW_WC + r * 64 + k], d);
            e = fmaf(h[k], sm[HW_WS + r * 64 + k], e);
        }
        lc[r] = d + sm[HW_BC + r];
        lsh[r] = e + sm[HW_BS + r];
    }
#pragma unroll 5
    for (int r = 0; r < 25; r++) {
        float d = 0.f;
        for (int k = 0; k < 64; k++) d = fmaf(h[k], sm[HW_WL + r * 64 + k], d);
        ll[r] = d + sm[HW_BL + r];
    }
    float clp0, slp0, llp0;
    int cs0  = sample_lp<3>(lc,  keys.a[0], keys.b[0], b, clp0);
    sample_lp<3>(lsh, keys.a[1], keys.b[1], b, slp0);
    int loc0 = sample_lp<25>(ll, keys.a[2], keys.b[2], b, llp0);

    int lclip = min(max(loc0, 0), 24);
    int4 pt = *(const int4*)(canvas1 + (b * 25 + lclip) * 4);
    bool ok0 = (loc0 >= 0) && (loc0 < 25) && ((pt.x + pt.y + pt.z + pt.w) >= 0);
    float loc_r0 = ok0 ? 1.f : -1.f;
    float col_r0 = ok0 ? ((cs0 == pt.x) ? 1.f : -1.f) : 0.f;

    __syncthreads();
    for (int i = tid; i < HT * RNN; i += HT) {
        int s = i >> 6, k = i & 63;
        hb[s * 65 + k] = g_h[BN * RNN + (tile + s) * RNN + k];
    }
    __syncthreads();

    // ======== dialog step 1 ========
    float lp8[8];
#pragma unroll
    for (int r = 0; r < 3; r++) {
        float d = 0.f, e = 0.f;
        for (int k = 0; k < 64; k++) {
            d = fmaf(h[k], sm[HW_WC + r * 64 + k], d);
            e = fmaf(h[k], sm[HW_WS + r * 64 + k], e);
        }
        lc[r] = d + sm[HW_BC + r];
        lsh[r] = e + sm[HW_BS + r];
    }
#pragma unroll 4
    for (int r = 0; r < 8; r++) {
        float d = 0.f;
        for (int k = 0; k < 64; k++) d = fmaf(h[k], sm[HW_WP + r * 64 + k], d);
        lp8[r] = d + sm[HW_BP + r];
    }
    float clp1, slp1, llp1, alp1;
    int cs1 = sample_lp<3>(lc,  keys.a[3], keys.b[3], b, clp1);
    sample_lp<3>(lsh, keys.a[4], keys.b[4], b, slp1);
    int ls1 = sample_lp<8>(lp8, keys.a[5], keys.b[5], b, llp1);

    float pre[32];
#pragma unroll 8
    for (int j = 0; j < 32; j++) {
        float d = 0.f;
        for (int k = 0; k < 64; k++) d = fmaf(h[k], sm[HW_WR1 + j * 68 + k], d);
        pre[j] = d + sm[HW_BR1 + j];
    }
    float al[25];
#pragma unroll
    for (int loc = 0; loc < 25; loc++) {
        int4 cv = *(const int4*)(canvas0 + (b * 25 + loc) * 4);
        float cx = (float)cv.x, cy = (float)cv.y, cz = (float)cv.z, cw = (float)cv.w;
        float a = sm[HW_BR2];
#pragma unroll
        for (int j = 0; j < 32; j++) {
            float v = pre[j];
            v = fmaf(cx, sm[HW_WR1 + j * 68 + 64], v);
            v = fmaf(cy, sm[HW_WR1 + j * 68 + 65], v);
            v = fmaf(cz, sm[HW_WR1 + j * 68 + 66], v);
            v = fmaf(cw, sm[HW_WR1 + j * 68 + 67], v);
            v = fmaxf(v, 0.f);
            a = fmaf(v, sm[HW_WR2 + j], a);
        }
        al[loc] = a;
    }
    int att = sample_lp<25>(al, keys.a[6], keys.b[6], b, alp1);

    int4 ro = *(const int4*)(canvas0 + (b * 25 + att) * 4);
    int4 rf = *(const int4*)(refp + b * 4);
    float att_rew = (ro.x == rf.x && ro.y == rf.y && ro.z == rf.z && ro.w == rf.w)
                        ? 1.f : -1.f;
    int loc1 = (ro.z + c_offx[ls1]) * 5 + (ro.w + c_offy[ls1]);
    int l1c = min(max(loc1, 0), 24);
    int4 pt1 = *(const int4*)(canvas1 + (b * 25 + l1c) * 4);
    bool ok1 = (loc1 >= 0) && (loc1 < 25) && ((pt1.x + pt1.y + pt1.z + pt1.w) >= 0);
    float loc_r1 = ok1 ? 1.f : -1.f;
    float col_r1 = ok1 ? ((cs1 == pt1.x) ? 1.f : -1.f) : 0.f;

    out[0 * BN + b] = clp0;
    out[1 * BN + b] = slp0;
    out[2 * BN + b] = llp0;
    out[3 * BN + b] = clp1;
    out[4 * BN + b] = slp1;
    out[5 * BN + b] = llp1;
    out[6 * BN + b] = alp1;
    out[(7 + 0) * BN + b] = loc_r0;
    out[(7 + 1) * BN + b] = col_r0;
    out[(7 + 2) * BN + b] = loc_r0;
    out[(7 + 3) * BN + b] = loc_r1;
    out[(7 + 4) * BN + b] = col_r1;
    out[(7 + 5) * BN + b] = loc_r1;
    out[(7 + 6) * BN + b] = att_rew;
}

// ================= launch =================
extern "C" void kernel_launch(void* const* d_in, const int* in_sizes, int n_in,
                              void* d_out, int out_size) {
    const int*   inst0   = (const int*)d_in[0];
    const int*   inst1   = (const int*)d_in[1];
    const int*   canvas0 = (const int*)d_in[2];
    const int*   canvas1 = (const int*)d_in[3];
    const int*   refp    = (const int*)d_in[4];
    const float* embed   = (const float*)d_in[5];
    const float* W_ih    = (const float*)d_in[6];
    const float* W_hh    = (const float*)d_in[7];
    const float* b_ih    = (const float*)d_in[8];
    const float* b_hh    = (const float*)d_in[9];
    const float* Wc      = (const float*)d_in[10];
    const float* bc      = (const float*)d_in[11];
    const float* Ws      = (const float*)d_in[12];
    const float* bs      = (const float*)d_in[13];
    const float* Wl      = (const float*)d_in[14];
    const float* bl      = (const float*)d_in[15];
    const float* Wr1     = (const float*)d_in[16];
    const float* br1     = (const float*)d_in[17];
    const float* Wr2     = (const float*)d_in[18];
    const float* br2     = (const float*)d_in[19];
    const float* Wp      = (const float*)d_in[20];
    const float* bp      = (const float*)d_in[21];

    Keys keys;
#if THREEFRY_PARTITIONABLE
    for (int i = 0; i < 7; i++)
        threefry2x32(0u, 42u, 0u, (uint32_t)i, keys.a[i], keys.b[i]);
#else
    uint32_t o[14];
    for (int i = 0; i < 7; i++)
        threefry2x32(0u, 42u, (uint32_t)i, (uint32_t)(i + 7), o[i], o[7 + i]);
    for (int i = 0; i < 7; i++) { keys.a[i] = o[2 * i]; keys.b[i] = o[2 * i + 1]; }
#endif

    cudaFuncSetAttribute(lstm_kernel, cudaFuncAttributeMaxDynamicSharedMemorySize,
                         LSTM_SMEM_BYTES);
    cudaFuncSetAttribute(heads_kernel, cudaFuncAttributeMaxDynamicSharedMemorySize,
                         HEADS_SMEM_BYTES);

    tokgate_kernel<<<(VOCAB + 7) / 8, 256>>>(embed, W_ih, b_ih, b_hh);
    lstm_kernel<<<dim3(BN / TBM, 2), 256, LSTM_SMEM_BYTES>>>(inst0, inst1, W_hh);
    heads_kernel<<<BN / HT, HT, HEADS_SMEM_BYTES>>>(
        canvas0, canvas1, refp, Wc, bc, Ws, bs, Wl, bl, Wr1, br1, Wr2, br2,
        Wp, bp, (float*)d_out, keys);
}

// round 8
// speedup vs baseline: 4.5295x; 1.7102x over previous
#include <cuda_runtime.h>
#include <cuda_fp16.h>
#include <cstdint>

#define BN 16384
#define SEQ 32
#define RNN 64
#define NG 256
#define VOCAB 1001
#define TBM 32             // samples per LSTM CTA
#define HT 64              // heads threads per block
#define THREEFRY_PARTITIONABLE 1

typedef unsigned long long u64;

__device__ float g_h[2 * BN * RNN];
__device__ float g_tokgate[VOCAB * NG];

// ================= threefry2x32 (exact JAX algorithm) =================
__host__ __device__ __forceinline__ uint32_t rotl32(uint32_t x, int d) {
    return (x << d) | (x >> (32 - d));
}
__host__ __device__ __forceinline__ void threefry2x32(uint32_t k0, uint32_t k1,
                                                      uint32_t c0, uint32_t c1,
                                                      uint32_t& o0, uint32_t& o1) {
    uint32_t ks2 = k0 ^ k1 ^ 0x1BD11BDAu;
    uint32_t x0 = c0 + k0, x1 = c1 + k1;
#define TF_R4(a,b,c,d) \
    x0 += x1; x1 = rotl32(x1,a); x1 ^= x0; \
    x0 += x1; x1 = rotl32(x1,b); x1 ^= x0; \
    x0 += x1; x1 = rotl32(x1,c); x1 ^= x0; \
    x0 += x1; x1 = rotl32(x1,d); x1 ^= x0;
    TF_R4(13,15,26,6);  x0 += k1;  x1 += ks2 + 1u;
    TF_R4(17,29,16,24); x0 += ks2; x1 += k0  + 2u;
    TF_R4(13,15,26,6);  x0 += k0;  x1 += k1  + 3u;
    TF_R4(17,29,16,24); x0 += k1;  x1 += ks2 + 4u;
    TF_R4(13,15,26,6);  x0 += ks2; x1 += k0  + 5u;
#undef TF_R4
    o0 = x0; o1 = x1;
}

struct Keys { uint32_t a[7]; uint32_t b[7]; };

__device__ __forceinline__ uint32_t jax_bits32(uint32_t k0, uint32_t k1,
                                               uint32_t idx, uint32_t half) {
#if THREEFRY_PARTITIONABLE
    uint32_t y0, y1;
    threefry2x32(k0, k1, 0u, idx, y0, y1);
    return y0 ^ y1;
#else
    uint32_t p = (idx < half) ? idx : idx - half;
    uint32_t y0, y1;
    threefry2x32(k0, k1, p, p + half, y0, y1);
    return (idx < half) ? y0 : y1;
#endif
}
__device__ __forceinline__ float jax_gumbel(uint32_t k0, uint32_t k1,
                                            uint32_t idx, uint32_t half) {
    uint32_t bits = jax_bits32(k0, k1, idx, half);
    float f = __uint_as_float((bits >> 9) | 0x3f800000u) - 1.0f;
    f = fmaxf(f, 1.17549435e-38f);
    return -logf(-logf(f));
}
__device__ __forceinline__ float sigf(float x) {
    return fmaf(0.5f, tanhf(0.5f * x), 0.5f);   // XLA logistic lowering
}

// mma.sync m16n8k16 f16 (baseline PTX; 2x MACs per instruction vs tf32 k8)
__device__ __forceinline__ void mma_f16(float d[4], const uint32_t a[4],
                                        uint32_t b0, uint32_t b1) {
    asm volatile(
        "mma.sync.aligned.m16n8k16.row.col.f32.f16.f16.f32 "
        "{%0,%1,%2,%3}, {%4,%5,%6,%7}, {%8,%9}, {%0,%1,%2,%3};"
        : "+f"(d[0]), "+f"(d[1]), "+f"(d[2]), "+f"(d[3])
        : "r"(a[0]), "r"(a[1]), "r"(a[2]), "r"(a[3]), "r"(b0), "r"(b1));
}

__device__ __forceinline__ uint32_t pack_h2(__half lo_h, __half hi_h) {
    __half2 h2 = __halves2half2(lo_h, hi_h);
    return *(uint32_t*)&h2;
}

// ================= tokgate precompute =================
// g_tokgate[v][c], c = 4u+g : embed[v] . W_ih[g*64+u] + b_ih + b_hh
__global__ void __launch_bounds__(256)
tokgate_kernel(const float* __restrict__ embed, const float* __restrict__ W_ih,
               const float* __restrict__ b_ih, const float* __restrict__ b_hh) {
    __shared__ float e[8][64];
    const int v0 = blockIdx.x * 8;
    const int tid = threadIdx.x;
    for (int i = tid; i < 8 * 64; i += 256) {
        int vv = v0 + (i >> 6);
        e[i >> 6][i & 63] = (vv < VOCAB) ? embed[vv * 64 + (i & 63)] : 0.f;
    }
    __syncthreads();
    const int c = tid, gg = c & 3, u = c >> 2;
    const int row = gg * 64 + u;
    float wreg[64];
    const float4* wp = (const float4*)(W_ih + row * 64);
#pragma unroll
    for (int i = 0; i < 16; i++) {
        float4 w4 = wp[i];
        wreg[4 * i] = w4.x; wreg[4 * i + 1] = w4.y;
        wreg[4 * i + 2] = w4.z; wreg[4 * i + 3] = w4.w;
    }
    const float bias = b_ih[row] + b_hh[row];
#pragma unroll
    for (int j = 0; j < 8; j++) {
        int v = v0 + j;
        if (v >= VOCAB) break;
        float d = bias;
#pragma unroll
        for (int k = 0; k < 64; k++) d = fmaf(e[j][k], wreg[k], d);
        g_tokgate[v * NG + c] = d;
    }
}

// ================= LSTM kernel (mma.sync f16 k16, 3-product compensation) =================
// smem (32-bit words), all fp16x2-packed along K/unit dim, stride 36:
//   Whi [256][36] @ 0       Wlo [256][36] @ 9216
//   Hhi [32][36]  @ 18432   Hlo [32][36]  @ 19584
//   tok [32][32]  @ 20736
// total 21760 words = 87040 bytes  -> 2 CTAs/SM
#define WSTR 36
#define OFF_WHI 0
#define OFF_WLO (256 * WSTR)
#define OFF_HHI (2 * 256 * WSTR)
#define OFF_HLO (OFF_HHI + TBM * WSTR)
#define OFF_TOK (OFF_HLO + TBM * WSTR)
#define LSTM_SMEM_WORDS (OFF_TOK + TBM * SEQ)
#define LSTM_SMEM_BYTES (LSTM_SMEM_WORDS * 4)
// column order: c' = nb*64 + nt*8 + 4*up + g ; unit u = nb*16 + nt*2 + up

__global__ void __launch_bounds__(256, 2)
lstm_kernel(const int* __restrict__ inst0, const int* __restrict__ inst1,
            const float* __restrict__ W_hh) {
    extern __shared__ uint32_t smw[];
    uint32_t* Whi = smw + OFF_WHI;
    uint32_t* Wlo = smw + OFF_WLO;
    uint32_t* Hhi = smw + OFF_HHI;
    uint32_t* Hlo = smw + OFF_HLO;
    int*      tok = (int*)(smw + OFF_TOK);    // [s][t]

    const int tid  = threadIdx.x;
    const int wid  = tid >> 5, lane = tid & 31;
    const int gid  = lane >> 2, tig = lane & 3;
    const int mb   = wid & 1;                 // m-block: samples mb*16..mb*16+15
    const int nb   = wid >> 1;                // n-block: cols nb*64..nb*64+63
    const int base = blockIdx.x * TBM;
    const int* inst = (blockIdx.y == 0) ? inst0 : inst1;
    float* hout = g_h + blockIdx.y * (BN * RNN);

    // ---- stage W_hh split into fp16 hi/lo, permuted column order, packed k-pairs ----
    for (int idx = tid; idx < NG * 32; idx += 256) {
        int c = idx >> 5, kp = idx & 31;
        int cnb = c >> 6, cnt = (c >> 3) & 7, cup = (c >> 2) & 1, cg = c & 3;
        int u = cnb * 16 + cnt * 2 + cup;
        const float* wr = W_hh + (cg * 64 + u) * 64 + 2 * kp;
        float w0 = wr[0], w1 = wr[1];
        __half h0 = __float2half_rn(w0), h1 = __float2half_rn(w1);
        __half l0 = __float2half_rn(w0 - __half2float(h0));
        __half l1 = __float2half_rn(w1 - __half2float(h1));
        Whi[c * WSTR + kp] = pack_h2(h0, h1);
        Wlo[c * WSTR + kp] = pack_h2(l0, l1);
    }
    // tokens + zero h
    for (int idx = tid; idx < TBM * SEQ; idx += 256)
        tok[idx] = inst[base * SEQ + idx];
    for (int idx = tid; idx < TBM * WSTR; idx += 256) {
        Hhi[idx] = 0u;
        Hlo[idx] = 0u;
    }
    __syncthreads();

    // thread's fixed sample row & unit-pair half
    const int row   = mb * 16 + gid + 8 * (tig & 1);
    const int upair = tig >> 1;
    const int m0    = mb * 16;
    const int cn0   = nb * 64;
    __half* HHIh = (__half*)Hhi;   // [row][72 halves]
    __half* HLOh = (__half*)Hlo;
    float c_reg[8];
#pragma unroll
    for (int i = 0; i < 8; i++) c_reg[i] = 0.f;

    for (int t = 0; t < SEQ; t++) {
        float d[8][4];
#pragma unroll
        for (int nt = 0; nt < 8; nt++)
#pragma unroll
            for (int j = 0; j < 4; j++) d[nt][j] = 0.f;

#pragma unroll
        for (int kt = 0; kt < 4; kt++) {
            const int kp0 = kt * 8 + tig;
            uint32_t ahi[4], alo[4];
            ahi[0] = Hhi[(m0 + gid)     * WSTR + kp0];
            ahi[1] = Hhi[(m0 + gid + 8) * WSTR + kp0];
            ahi[2] = Hhi[(m0 + gid)     * WSTR + kp0 + 4];
            ahi[3] = Hhi[(m0 + gid + 8) * WSTR + kp0 + 4];
            alo[0] = Hlo[(m0 + gid)     * WSTR + kp0];
            alo[1] = Hlo[(m0 + gid + 8) * WSTR + kp0];
            alo[2] = Hlo[(m0 + gid)     * WSTR + kp0 + 4];
            alo[3] = Hlo[(m0 + gid + 8) * WSTR + kp0 + 4];

#pragma unroll
            for (int nt = 0; nt < 8; nt++) {
                const int c = cn0 + nt * 8 + gid;
                uint32_t b0 = Whi[c * WSTR + kp0];
                uint32_t b1 = Whi[c * WSTR + kp0 + 4];
                mma_f16(d[nt], ahi, b0, b1);   // hi . Whi
                mma_f16(d[nt], alo, b0, b1);   // lo . Whi
                uint32_t bl0 = Wlo[c * WSTR + kp0];
                uint32_t bl1 = Wlo[c * WSTR + kp0 + 4];
                mma_f16(d[nt], ahi, bl0, bl1); // hi . Wlo
            }
        }
        __syncthreads();   // all reads of H done before rewrite

        // ---- epilogue: quad-exchange, + tokgate, LSTM cell, store h hi/lo ----
        const int tv = tok[row * SEQ + t];
        const float* tgrow = g_tokgate + tv * NG;
        const bool e = (tig & 1) == 0;

#pragma unroll
        for (int nt = 0; nt < 8; nt++) {
            float r0 = __shfl_xor_sync(0xffffffffu, d[nt][0], 1);
            float r1 = __shfl_xor_sync(0xffffffffu, d[nt][1], 1);
            float r2 = __shfl_xor_sync(0xffffffffu, d[nt][2], 1);
            float r3 = __shfl_xor_sync(0xffffffffu, d[nt][3], 1);
            float ig = e ? d[nt][0] : r2;
            float fg = e ? d[nt][1] : r3;
            float gg = e ? r0 : d[nt][2];
            float og = e ? r1 : d[nt][3];
            const int u = nb * 16 + nt * 2 + upair;
            float4 tgv = *(const float4*)(tgrow + 4 * u);
            ig += tgv.x; fg += tgv.y; gg += tgv.z; og += tgv.w;
            float cb = sigf(fg) * c_reg[nt] + sigf(ig) * tanhf(gg);
            float h = sigf(og) * tanhf(cb);
            c_reg[nt] = cb;
            __half hh = __float2half_rn(h);
            HHIh[row * (2 * WSTR) + u] = hh;
            HLOh[row * (2 * WSTR) + u] = __float2half_rn(h - __half2float(hh));
            if (t == SEQ - 1) hout[(base + row) * RNN + u] = h;
        }
        __syncthreads();   // h writes visible before next step's reads
    }
}

// ================= heads kernel =================
#define HW_WC   0
#define HW_BC   (HW_WC + 192)
#define HW_WS   (HW_BC + 4)
#define HW_BS   (HW_WS + 192)
#define HW_WL   (HW_BS + 4)
#define HW_BL   (HW_WL + 1600)
#define HW_WP   (HW_BL + 28)
#define HW_BP   (HW_WP + 512)
#define HW_WR1  (HW_BP + 8)
#define HW_BR1  (HW_WR1 + 2176)
#define HW_WR2  (HW_BR1 + 32)
#define HW_BR2  (HW_WR2 + 32)
#define HW_HB   (HW_BR2 + 4)
#define HEADS_SMEM_FLOATS (HW_HB + HT * 65)
#define HEADS_SMEM_BYTES  (HEADS_SMEM_FLOATS * 4)

__device__ const int c_offx[8] = {-1, 1, 0, 0, -1, -1, 1, 1};
__device__ const int c_offy[8] = {0, 0, 1, -1, -1, 1, -1, 1};

template <int V>
__device__ __forceinline__ int sample_lp(const float* lg, uint32_t k0, uint32_t k1,
                                         int b, float& lp) {
    const uint32_t half = (uint32_t)(BN * V / 2);
    int best = 0;
    float bestz = -1e30f, bestl = lg[0], m = -1e30f;
#pragma unroll
    for (int v = 0; v < V; v++) {
        float z = lg[v] + jax_gumbel(k0, k1, (uint32_t)(b * V + v), half);
        if (z > bestz) { bestz = z; best = v; bestl = lg[v]; }
        m = fmaxf(m, lg[v]);
    }
    float ssum = 0.f;
#pragma unroll
    for (int v = 0; v < V; v++) ssum += expf(lg[v] - m);
    lp = (bestl - m) - logf(ssum);
    return best;
}

__global__ void __launch_bounds__(HT)
heads_kernel(const int* __restrict__ canvas0, const int* __restrict__ canvas1,
             const int* __restrict__ refp,
             const float* __restrict__ Wc, const float* __restrict__ bc,
             const float* __restrict__ Ws, const float* __restrict__ bs,
             const float* __restrict__ Wl, const float* __restrict__ bl,
             const float* __restrict__ Wr1, const float* __restrict__ br1,
             const float* __restrict__ Wr2, const float* __restrict__ br2,
             const float* __restrict__ Wp, const float* __restrict__ bp,
             float* __restrict__ out, Keys keys) {
    extern __shared__ float sm[];
    const int tid = threadIdx.x;
    const int b = blockIdx.x * HT + tid;
    const int tile = blockIdx.x * HT;

    for (int i = tid; i < 192;  i += HT) sm[HW_WC + i] = Wc[i];
    for (int i = tid; i < 192;  i += HT) sm[HW_WS + i] = Ws[i];
    for (int i = tid; i < 1600; i += HT) sm[HW_WL + i] = Wl[i];
    for (int i = tid; i < 512;  i += HT) sm[HW_WP + i] = Wp[i];
    for (int i = tid; i < 2176; i += HT) sm[HW_WR1 + i] = Wr1[i];
    if (tid < 3)  sm[HW_BC + tid]  = bc[tid];
    if (tid < 3)  sm[HW_BS + tid]  = bs[tid];
    if (tid < 25) sm[HW_BL + tid]  = bl[tid];
    if (tid < 8)  sm[HW_BP + tid]  = bp[tid];
    if (tid < 32) sm[HW_BR1 + tid] = br1[tid];
    if (tid < 32) sm[HW_WR2 + tid] = Wr2[tid];
    if (tid == 0) sm[HW_BR2] = br2[0];

    float* hb = sm + HW_HB;
    for (int i = tid; i < HT * RNN; i += HT) {
        int s = i >> 6, k = i & 63;
        hb[s * 65 + k] = g_h[(tile + s) * RNN + k];
    }
    __syncthreads();

    // ======== dialog step 0 ========
    const float* h = hb + tid * 65;
    float lc[3], lsh[3], ll[25];
#pragma unroll
    for (int r = 0; r < 3; r++) {
        float d = 0.f, e = 0.f;
        for (int k = 0; k < 64; k++) {
            d = fmaf(h[k], sm[HW_WC + r * 64 + k], d);
            e = fmaf(h[k], sm[HW_WS + r * 64 + k], e);
        }
        lc[r] = d + sm[HW_BC + r];
        lsh[r] = e + sm[HW_BS + r];
    }
#pragma unroll 5
    for (int r = 0; r < 25; r++) {
        float d = 0.f;
        for (int k = 0; k < 64; k++) d = fmaf(h[k], sm[HW_WL + r * 64 + k], d);
        ll[r] = d + sm[HW_BL + r];
    }
    float clp0, slp0, llp0;
    int cs0  = sample_lp<3>(lc,  keys.a[0], keys.b[0], b, clp0);
    sample_lp<3>(lsh, keys.a[1], keys.b[1], b, slp0);
    int loc0 = sample_lp<25>(ll, keys.a[2], keys.b[2], b, llp0);

    int lclip = min(max(loc0, 0), 24);
    int4 pt = *(const int4*)(canvas1 + (b * 25 + lclip) * 4);
    bool ok0 = (loc0 >= 0) && (loc0 < 25) && ((pt.x + pt.y + pt.z + pt.w) >= 0);
    float loc_r0 = ok0 ? 1.f : -1.f;
    float col_r0 = ok0 ? ((cs0 == pt.x) ? 1.f : -1.f) : 0.f;

    __syncthreads();
    for (int i = tid; i < HT * RNN; i += HT) {
        int s = i >> 6, k = i & 63;
        hb[s * 65 + k] = g_h[BN * RNN + (tile + s) * RNN + k];
    }
    __syncthreads();

    // ======== dialog step 1 ========
    float lp8[8];
#pragma unroll
    for (int r = 0; r < 3; r++) {
        float d = 0.f, e = 0.f;
        for (int k = 0; k < 64; k++) {
            d = fmaf(h[k], sm[HW_WC + r * 64 + k], d);
            e = fmaf(h[k], sm[HW_WS + r * 64 + k], e);
        }
        lc[r] = d + sm[HW_BC + r];
        lsh[r] = e + sm[HW_BS + r];
    }
#pragma unroll 4
    for (int r = 0; r < 8; r++) {
        float d = 0.f;
        for (int k = 0; k < 64; k++) d = fmaf(h[k], sm[HW_WP + r * 64 + k], d);
        lp8[r] = d + sm[HW_BP + r];
    }
    float clp1, slp1, llp1, alp1;
    int cs1 = sample_lp<3>(lc,  keys.a[3], keys.b[3], b, clp1);
    sample_lp<3>(lsh, keys.a[4], keys.b[4], b, slp1);
    int ls1 = sample_lp<8>(lp8, keys.a[5], keys.b[5], b, llp1);

    float pre[32];
#pragma unroll 8
    for (int j = 0; j < 32; j++) {
        float d = 0.f;
        for (int k = 0; k < 64; k++) d = fmaf(h[k], sm[HW_WR1 + j * 68 + k], d);
        pre[j] = d + sm[HW_BR1 + j];
    }
    float al[25];
#pragma unroll
    for (int loc = 0; loc < 25; loc++) {
        int4 cv = *(const int4*)(canvas0 + (b * 25 + loc) * 4);
        float cx = (float)cv.x, cy = (float)cv.y, cz = (float)cv.z, cw = (float)cv.w;
        float a = sm[HW_BR2];
#pragma unroll
        for (int j = 0; j < 32; j++) {
            float v = pre[j];
            v = fmaf(cx, sm[HW_WR1 + j * 68 + 64], v);
            v = fmaf(cy, sm[HW_WR1 + j * 68 + 65], v);
            v = fmaf(cz, sm[HW_WR1 + j * 68 + 66], v);
            v = fmaf(cw, sm[HW_WR1 + j * 68 + 67], v);
            v = fmaxf(v, 0.f);
            a = fmaf(v, sm[HW_WR2 + j], a);
        }
        al[loc] = a;
    }
    int att = sample_lp<25>(al, keys.a[6], keys.b[6], b, alp1);

    int4 ro = *(const int4*)(canvas0 + (b * 25 + att) * 4);
    int4 rf = *(const int4*)(refp + b * 4);
    float att_rew = (ro.x == rf.x && ro.y == rf.y && ro.z == rf.z && ro.w == rf.w)
                        ? 1.f : -1.f;
    int loc1 = (ro.z + c_offx[ls1]) * 5 + (ro.w + c_offy[ls1]);
    int l1c = min(max(loc1, 0), 24);
    int4 pt1 = *(const int4*)(canvas1 + (b * 25 + l1c) * 4);
    bool ok1 = (loc1 >= 0) && (loc1 < 25) && ((pt1.x + pt1.y + pt1.z + pt1.w) >= 0);
    float loc_r1 = ok1 ? 1.f : -1.f;
    float col_r1 = ok1 ? ((cs1 == pt1.x) ? 1.f : -1.f) : 0.f;

    out[0 * BN + b] = clp0;
    out[1 * BN + b] = slp0;
    out[2 * BN + b] = llp0;
    out[3 * BN + b] = clp1;
    out[4 * BN + b] = slp1;
    out[5 * BN + b] = llp1;
    out[6 * BN + b] = alp1;
    out[(7 + 0) * BN + b] = loc_r0;
    out[(7 + 1) * BN + b] = col_r0;
    out[(7 + 2) * BN + b] = loc_r0;
    out[(7 + 3) * BN + b] = loc_r1;
    out[(7 + 4) * BN + b] = col_r1;
    out[(7 + 5) * BN + b] = loc_r1;
    out[(7 + 6) * BN + b] = att_rew;
}

// ================= launch =================
extern "C" void kernel_launch(void* const* d_in, const int* in_sizes, int n_in,
                              void* d_out, int out_size) {
    const int*   inst0   = (const int*)d_in[0];
    const int*   inst1   = (const int*)d_in[1];
    const int*   canvas0 = (const int*)d_in[2];
    const int*   canvas1 = (const int*)d_in[3];
    const int*   refp    = (const int*)d_in[4];
    const float* embed   = (const float*)d_in[5];
    const float* W_ih    = (const float*)d_in[6];
    const float* W_hh    = (const float*)d_in[7];
    const float* b_ih    = (const float*)d_in[8];
    const float* b_hh    = (const float*)d_in[9];
    const float* Wc      = (const float*)d_in[10];
    const float* bc      = (const float*)d_in[11];
    const float* Ws      = (const float*)d_in[12];
    const float* bs      = (const float*)d_in[13];
    const float* Wl      = (const float*)d_in[14];
    const float* bl      = (const float*)d_in[15];
    const float* Wr1     = (const float*)d_in[16];
    const float* br1     = (const float*)d_in[17];
    const float* Wr2     = (const float*)d_in[18];
    const float* br2     = (const float*)d_in[19];
    const float* Wp      = (const float*)d_in[20];
    const float* bp      = (const float*)d_in[21];

    Keys keys;
#if THREEFRY_PARTITIONABLE
    for (int i = 0; i < 7; i++)
        threefry2x32(0u, 42u, 0u, (uint32_t)i, keys.a[i], keys.b[i]);
#else
    uint32_t o[14];
    for (int i = 0; i < 7; i++)
        threefry2x32(0u, 42u, (uint32_t)i, (uint32_t)(i + 7), o[i], o[7 + i]);
    for (int i = 0; i < 7; i++) { keys.a[i] = o[2 * i]; keys.b[i] = o[2 * i + 1]; }
#endif

    cudaFuncSetAttribute(lstm_kernel, cudaFuncAttributeMaxDynamicSharedMemorySize,
                         LSTM_SMEM_BYTES);
    cudaFuncSetAttribute(heads_kernel, cudaFuncAttributeMaxDynamicSharedMemorySize,
                         HEADS_SMEM_BYTES);

    tokgate_kernel<<<(VOCAB + 7) / 8, 256>>>(embed, W_ih, b_ih, b_hh);
    lstm_kernel<<<dim3(BN / TBM, 2), 256, LSTM_SMEM_BYTES>>>(inst0, inst1, W_hh);
    heads_kernel<<<BN / HT, HT, HEADS_SMEM_BYTES>>>(
        canvas0, canvas1, refp, Wc, bc, Ws, bs, Wl, bl, Wr1, br1, Wr2, br2,
        Wp, bp, (float*)d_out, keys);
}

// round 9
// speedup vs baseline: 4.7315x; 1.0446x over previous
#include <cuda_runtime.h>
#include <cuda_fp16.h>
#include <cstdint>

#define BN 16384
#define SEQ 32
#define RNN 64
#define NG 256
#define VOCAB 1001
#define TBM 32             // samples per LSTM CTA
#define HT 64              // heads threads per block
#define THREEFRY_PARTITIONABLE 1

typedef unsigned long long u64;

__device__ float g_h[2 * BN * RNN];
__device__ float g_tokgate[VOCAB * NG];

// ================= threefry2x32 (exact JAX algorithm) =================
__host__ __device__ __forceinline__ uint32_t rotl32(uint32_t x, int d) {
    return (x << d) | (x >> (32 - d));
}
__host__ __device__ __forceinline__ void threefry2x32(uint32_t k0, uint32_t k1,
                                                      uint32_t c0, uint32_t c1,
                                                      uint32_t& o0, uint32_t& o1) {
    uint32_t ks2 = k0 ^ k1 ^ 0x1BD11BDAu;
    uint32_t x0 = c0 + k0, x1 = c1 + k1;
#define TF_R4(a,b,c,d) \
    x0 += x1; x1 = rotl32(x1,a); x1 ^= x0; \
    x0 += x1; x1 = rotl32(x1,b); x1 ^= x0; \
    x0 += x1; x1 = rotl32(x1,c); x1 ^= x0; \
    x0 += x1; x1 = rotl32(x1,d); x1 ^= x0;
    TF_R4(13,15,26,6);  x0 += k1;  x1 += ks2 + 1u;
    TF_R4(17,29,16,24); x0 += ks2; x1 += k0  + 2u;
    TF_R4(13,15,26,6);  x0 += k0;  x1 += k1  + 3u;
    TF_R4(17,29,16,24); x0 += k1;  x1 += ks2 + 4u;
    TF_R4(13,15,26,6);  x0 += ks2; x1 += k0  + 5u;
#undef TF_R4
    o0 = x0; o1 = x1;
}

struct Keys { uint32_t a[7]; uint32_t b[7]; };

__device__ __forceinline__ uint32_t jax_bits32(uint32_t k0, uint32_t k1,
                                               uint32_t idx, uint32_t half) {
#if THREEFRY_PARTITIONABLE
    uint32_t y0, y1;
    threefry2x32(k0, k1, 0u, idx, y0, y1);
    return y0 ^ y1;
#else
    uint32_t p = (idx < half) ? idx : idx - half;
    uint32_t y0, y1;
    threefry2x32(k0, k1, p, p + half, y0, y1);
    return (idx < half) ? y0 : y1;
#endif
}
__device__ __forceinline__ float jax_gumbel(uint32_t k0, uint32_t k1,
                                            uint32_t idx, uint32_t half) {
    uint32_t bits = jax_bits32(k0, k1, idx, half);
    float f = __uint_as_float((bits >> 9) | 0x3f800000u) - 1.0f;
    f = fmaxf(f, 1.17549435e-38f);
    return -logf(-logf(f));
}
__device__ __forceinline__ float sigf(float x) {
    return fmaf(0.5f, tanhf(0.5f * x), 0.5f);   // XLA logistic lowering
}

// mma.sync m16n8k16 f16 (baseline PTX)
__device__ __forceinline__ void mma_f16(float d[4], const uint32_t a[4],
                                        uint32_t b0, uint32_t b1) {
    asm volatile(
        "mma.sync.aligned.m16n8k16.row.col.f32.f16.f16.f32 "
        "{%0,%1,%2,%3}, {%4,%5,%6,%7}, {%8,%9}, {%0,%1,%2,%3};"
        : "+f"(d[0]), "+f"(d[1]), "+f"(d[2]), "+f"(d[3])
        : "r"(a[0]), "r"(a[1]), "r"(a[2]), "r"(a[3]), "r"(b0), "r"(b1));
}

__device__ __forceinline__ uint32_t pack_h2(__half lo_h, __half hi_h) {
    __half2 h2 = __halves2half2(lo_h, hi_h);
    return *(uint32_t*)&h2;
}

// ================= tokgate precompute =================
// g_tokgate[v][c], c = 4u+g : embed[v] . W_ih[g*64+u] + b_ih + b_hh
__global__ void __launch_bounds__(256)
tokgate_kernel(const float* __restrict__ embed, const float* __restrict__ W_ih,
               const float* __restrict__ b_ih, const float* __restrict__ b_hh) {
    __shared__ float e[8][64];
    const int v0 = blockIdx.x * 8;
    const int tid = threadIdx.x;
    for (int i = tid; i < 8 * 64; i += 256) {
        int vv = v0 + (i >> 6);
        e[i >> 6][i & 63] = (vv < VOCAB) ? embed[vv * 64 + (i & 63)] : 0.f;
    }
    __syncthreads();
    const int c = tid, gg = c & 3, u = c >> 2;
    const int row = gg * 64 + u;
    float wreg[64];
    const float4* wp = (const float4*)(W_ih + row * 64);
#pragma unroll
    for (int i = 0; i < 16; i++) {
        float4 w4 = wp[i];
        wreg[4 * i] = w4.x; wreg[4 * i + 1] = w4.y;
        wreg[4 * i + 2] = w4.z; wreg[4 * i + 3] = w4.w;
    }
    const float bias = b_ih[row] + b_hh[row];
#pragma unroll
    for (int j = 0; j < 8; j++) {
        int v = v0 + j;
        if (v >= VOCAB) break;
        float d = bias;
#pragma unroll
        for (int k = 0; k < 64; k++) d = fmaf(e[j][k], wreg[k], d);
        g_tokgate[v * NG + c] = d;
    }
}

// ================= LSTM kernel (mma.sync f16 k16, 3-product compensation) =================
// smem (32-bit words), fp16x2-packed along K, stride 36:
//   Whi [256][36] @ 0       Wlo [256][36] @ 9216
//   Hhi [32][36]  @ 18432   Hlo [32][36]  @ 19584
//   tok [32][32]  @ 20736
// total 21760 words = 87040 bytes  -> 2 CTAs/SM
#define WSTR 36
#define OFF_WHI 0
#define OFF_WLO (256 * WSTR)
#define OFF_HHI (2 * 256 * WSTR)
#define OFF_HLO (OFF_HHI + TBM * WSTR)
#define OFF_TOK (OFF_HLO + TBM * WSTR)
#define LSTM_SMEM_WORDS (OFF_TOK + TBM * SEQ)
#define LSTM_SMEM_BYTES (LSTM_SMEM_WORDS * 4)
// column order: c' = nb*64 + nt*8 + 4*up + g ; unit u = nb*16 + nt*2 + up

__global__ void __launch_bounds__(256, 2)
lstm_kernel(const int* __restrict__ inst0, const int* __restrict__ inst1,
            const float* __restrict__ W_hh) {
    extern __shared__ uint32_t smw[];
    uint32_t* Whi = smw + OFF_WHI;
    uint32_t* Wlo = smw + OFF_WLO;
    uint32_t* Hhi = smw + OFF_HHI;
    uint32_t* Hlo = smw + OFF_HLO;
    int*      tok = (int*)(smw + OFF_TOK);    // [s][t]

    const int tid  = threadIdx.x;
    const int wid  = tid >> 5, lane = tid & 31;
    const int gid  = lane >> 2, tig = lane & 3;
    const int mb   = wid & 1;                 // m-block: samples mb*16..mb*16+15
    const int nb   = wid >> 1;                // n-block: cols nb*64..nb*64+63
    const int base = blockIdx.x * TBM;
    const int* inst = (blockIdx.y == 0) ? inst0 : inst1;
    float* hout = g_h + blockIdx.y * (BN * RNN);

    // ---- stage W_hh split into fp16 hi/lo, permuted column order, packed k-pairs ----
    for (int idx = tid; idx < NG * 32; idx += 256) {
        int c = idx >> 5, kp = idx & 31;
        int cnb = c >> 6, cnt = (c >> 3) & 7, cup = (c >> 2) & 1, cg = c & 3;
        int u = cnb * 16 + cnt * 2 + cup;
        const float* wr = W_hh + (cg * 64 + u) * 64 + 2 * kp;
        float w0 = wr[0], w1 = wr[1];
        __half h0 = __float2half_rn(w0), h1 = __float2half_rn(w1);
        __half l0 = __float2half_rn(w0 - __half2float(h0));
        __half l1 = __float2half_rn(w1 - __half2float(h1));
        Whi[c * WSTR + kp] = pack_h2(h0, h1);
        Wlo[c * WSTR + kp] = pack_h2(l0, l1);
    }
    // tokens
    for (int idx = tid; idx < TBM * SEQ; idx += 256)
        tok[idx] = inst[base * SEQ + idx];
    __syncthreads();

    // thread's fixed sample row & unit-pair half
    const int row   = mb * 16 + gid + 8 * (tig & 1);
    const int upair = tig >> 1;
    const int m0    = mb * 16;
    const int cn0   = nb * 64;
    __half* HHIh = (__half*)Hhi;   // [row][72 halves]
    __half* HLOh = (__half*)Hlo;
    float c_reg[8];
#pragma unroll
    for (int i = 0; i < 8; i++) c_reg[i] = 0.f;

    for (int t = 0; t < SEQ; t++) {
        float d[8][4];
#pragma unroll
        for (int nt = 0; nt < 8; nt++)
#pragma unroll
            for (int j = 0; j < 4; j++) d[nt][j] = 0.f;

        if (t > 0) {   // h_{-1} = 0: gates at t=0 are tokgate only
#pragma unroll
            for (int kt = 0; kt < 4; kt++) {
                const int kp0 = kt * 8 + tig;
                uint32_t ahi[4], alo[4];
                ahi[0] = Hhi[(m0 + gid)     * WSTR + kp0];
                ahi[1] = Hhi[(m0 + gid + 8) * WSTR + kp0];
                ahi[2] = Hhi[(m0 + gid)     * WSTR + kp0 + 4];
                ahi[3] = Hhi[(m0 + gid + 8) * WSTR + kp0 + 4];
                alo[0] = Hlo[(m0 + gid)     * WSTR + kp0];
                alo[1] = Hlo[(m0 + gid + 8) * WSTR + kp0];
                alo[2] = Hlo[(m0 + gid)     * WSTR + kp0 + 4];
                alo[3] = Hlo[(m0 + gid + 8) * WSTR + kp0 + 4];

                // pass-outer / nt-inner: dependency distance 8 between MMAs
                // hitting the same accumulator (was 1 -> latency-bound).
                uint32_t bh[8][2];
#pragma unroll
                for (int nt = 0; nt < 8; nt++) {
                    const int c = cn0 + nt * 8 + gid;
                    bh[nt][0] = Whi[c * WSTR + kp0];
                    bh[nt][1] = Whi[c * WSTR + kp0 + 4];
                    mma_f16(d[nt], ahi, bh[nt][0], bh[nt][1]);   // hi . Whi
                }
#pragma unroll
                for (int nt = 0; nt < 8; nt++)
                    mma_f16(d[nt], alo, bh[nt][0], bh[nt][1]);   // lo . Whi
#pragma unroll
                for (int nt = 0; nt < 8; nt++) {
                    const int c = cn0 + nt * 8 + gid;
                    uint32_t bl0 = Wlo[c * WSTR + kp0];
                    uint32_t bl1 = Wlo[c * WSTR + kp0 + 4];
                    mma_f16(d[nt], ahi, bl0, bl1);               // hi . Wlo
                }
            }
        }
        __syncthreads();   // all reads of H done before rewrite

        // ---- epilogue: quad-exchange, + tokgate, LSTM cell, store h hi/lo ----
        const int tv = tok[row * SEQ + t];
        const float* tgrow = g_tokgate + tv * NG;
        const bool e = (tig & 1) == 0;

#pragma unroll
        for (int nt = 0; nt < 8; nt++) {
            float r0 = __shfl_xor_sync(0xffffffffu, d[nt][0], 1);
            float r1 = __shfl_xor_sync(0xffffffffu, d[nt][1], 1);
            float r2 = __shfl_xor_sync(0xffffffffu, d[nt][2], 1);
            float r3 = __shfl_xor_sync(0xffffffffu, d[nt][3], 1);
            float ig = e ? d[nt][0] : r2;
            float fg = e ? d[nt][1] : r3;
            float gg = e ? r0 : d[nt][2];
            float og = e ? r1 : d[nt][3];
            const int u = nb * 16 + nt * 2 + upair;
            float4 tgv = *(const float4*)(tgrow + 4 * u);
            ig += tgv.x; fg += tgv.y; gg += tgv.z; og += tgv.w;
            float cb = sigf(fg) * c_reg[nt] + sigf(ig) * tanhf(gg);
            float h = sigf(og) * tanhf(cb);
            c_reg[nt] = cb;
            __half hh = __float2half_rn(h);
            HHIh[row * (2 * WSTR) + u] = hh;
            HLOh[row * (2 * WSTR) + u] = __float2half_rn(h - __half2float(hh));
            if (t == SEQ - 1) hout[(base + row) * RNN + u] = h;
        }
        __syncthreads();   // h writes visible before next step's reads
    }
}

// ================= heads kernel (dialog-split: grid.y = 0/1) =================
#define HW_WC   0
#define HW_BC   (HW_WC + 192)
#define HW_WS   (HW_BC + 4)
#define HW_BS   (HW_WS + 192)
#define HW_WL   (HW_BS + 4)
#define HW_BL   (HW_WL + 1600)
#define HW_WP   (HW_BL + 28)
#define HW_BP   (HW_WP + 512)
#define HW_WR1  (HW_BP + 8)
#define HW_BR1  (HW_WR1 + 2176)
#define HW_WR2  (HW_BR1 + 32)
#define HW_BR2  (HW_WR2 + 32)
#define HW_HB   (HW_BR2 + 4)
#define HEADS_SMEM_FLOATS (HW_HB + HT * 65)
#define HEADS_SMEM_BYTES  (HEADS_SMEM_FLOATS * 4)

__device__ const int c_offx[8] = {-1, 1, 0, 0, -1, -1, 1, 1};
__device__ const int c_offy[8] = {0, 0, 1, -1, -1, 1, -1, 1};

template <int V>
__device__ __forceinline__ int sample_lp(const float* lg, uint32_t k0, uint32_t k1,
                                         int b, float& lp) {
    const uint32_t half = (uint32_t)(BN * V / 2);
    int best = 0;
    float bestz = -1e30f, bestl = lg[0], m = -1e30f;
#pragma unroll
    for (int v = 0; v < V; v++) {
        float z = lg[v] + jax_gumbel(k0, k1, (uint32_t)(b * V + v), half);
        if (z > bestz) { bestz = z; best = v; bestl = lg[v]; }
        m = fmaxf(m, lg[v]);
    }
    float ssum = 0.f;
#pragma unroll
    for (int v = 0; v < V; v++) ssum += expf(lg[v] - m);
    lp = (bestl - m) - logf(ssum);
    return best;
}

__global__ void __launch_bounds__(HT)
heads_kernel(const int* __restrict__ canvas0, const int* __restrict__ canvas1,
             const int* __restrict__ refp,
             const float* __restrict__ Wc, const float* __restrict__ bc,
             const float* __restrict__ Ws, const float* __restrict__ bs,
             const float* __restrict__ Wl, const float* __restrict__ bl,
             const float* __restrict__ Wr1, const float* __restrict__ br1,
             const float* __restrict__ Wr2, const float* __restrict__ br2,
             const float* __restrict__ Wp, const float* __restrict__ bp,
             float* __restrict__ out, Keys keys) {
    extern __shared__ float sm[];
    const int tid = threadIdx.x;
    const int b = blockIdx.x * HT + tid;
    const int tile = blockIdx.x * HT;
    const int dialog = blockIdx.y;

    // common weights
    for (int i = tid; i < 192;  i += HT) sm[HW_WC + i] = Wc[i];
    for (int i = tid; i < 192;  i += HT) sm[HW_WS + i] = Ws[i];
    if (tid < 3)  sm[HW_BC + tid]  = bc[tid];
    if (tid < 3)  sm[HW_BS + tid]  = bs[tid];
    if (dialog == 0) {
        for (int i = tid; i < 1600; i += HT) sm[HW_WL + i] = Wl[i];
        if (tid < 25) sm[HW_BL + tid]  = bl[tid];
    } else {
        for (int i = tid; i < 512;  i += HT) sm[HW_WP + i] = Wp[i];
        for (int i = tid; i < 2176; i += HT) sm[HW_WR1 + i] = Wr1[i];
        if (tid < 8)  sm[HW_BP + tid]  = bp[tid];
        if (tid < 32) sm[HW_BR1 + tid] = br1[tid];
        if (tid < 32) sm[HW_WR2 + tid] = Wr2[tid];
        if (tid == 0) sm[HW_BR2] = br2[0];
    }

    float* hb = sm + HW_HB;
    for (int i = tid; i < HT * RNN; i += HT) {
        int s = i >> 6, k = i & 63;
        hb[s * 65 + k] = g_h[dialog * (BN * RNN) + (tile + s) * RNN + k];
    }
    __syncthreads();

    const float* h = hb + tid * 65;

    // color/shape logits (both dialogs)
    float lc[3], lsh[3];
#pragma unroll
    for (int r = 0; r < 3; r++) {
        float d = 0.f, ee = 0.f;
        for (int k = 0; k < 64; k++) {
            d = fmaf(h[k], sm[HW_WC + r * 64 + k], d);
            ee = fmaf(h[k], sm[HW_WS + r * 64 + k], ee);
        }
        lc[r] = d + sm[HW_BC + r];
        lsh[r] = ee + sm[HW_BS + r];
    }

    if (dialog == 0) {
        float ll[25];
#pragma unroll 5
        for (int r = 0; r < 25; r++) {
            float d = 0.f;
            for (int k = 0; k < 64; k++) d = fmaf(h[k], sm[HW_WL + r * 64 + k], d);
            ll[r] = d + sm[HW_BL + r];
        }
        float clp0, slp0, llp0;
        int cs0  = sample_lp<3>(lc,  keys.a[0], keys.b[0], b, clp0);
        sample_lp<3>(lsh, keys.a[1], keys.b[1], b, slp0);
        int loc0 = sample_lp<25>(ll, keys.a[2], keys.b[2], b, llp0);

        int lclip = min(max(loc0, 0), 24);
        int4 pt = *(const int4*)(canvas1 + (b * 25 + lclip) * 4);
        bool ok0 = (loc0 >= 0) && (loc0 < 25) && ((pt.x + pt.y + pt.z + pt.w) >= 0);
        float loc_r0 = ok0 ? 1.f : -1.f;
        float col_r0 = ok0 ? ((cs0 == pt.x) ? 1.f : -1.f) : 0.f;

        out[0 * BN + b] = clp0;
        out[1 * BN + b] = slp0;
        out[2 * BN + b] = llp0;
        out[(7 + 0) * BN + b] = loc_r0;
        out[(7 + 1) * BN + b] = col_r0;
        out[(7 + 2) * BN + b] = loc_r0;
    } else {
        float lp8[8];
#pragma unroll 4
        for (int r = 0; r < 8; r++) {
            float d = 0.f;
            for (int k = 0; k < 64; k++) d = fmaf(h[k], sm[HW_WP + r * 64 + k], d);
            lp8[r] = d + sm[HW_BP + r];
        }
        float clp1, slp1, llp1, alp1;
        int cs1 = sample_lp<3>(lc,  keys.a[3], keys.b[3], b, clp1);
        sample_lp<3>(lsh, keys.a[4], keys.b[4], b, slp1);
        int ls1 = sample_lp<8>(lp8, keys.a[5], keys.b[5], b, llp1);

        float pre[32];
#pragma unroll 8
        for (int j = 0; j < 32; j++) {
            float d = 0.f;
            for (int k = 0; k < 64; k++) d = fmaf(h[k], sm[HW_WR1 + j * 68 + k], d);
            pre[j] = d + sm[HW_BR1 + j];
        }
        float al[25];
#pragma unroll
        for (int loc = 0; loc < 25; loc++) {
            int4 cv = *(const int4*)(canvas0 + (b * 25 + loc) * 4);
            float cx = (float)cv.x, cy = (float)cv.y, cz = (float)cv.z, cw = (float)cv.w;
            float a = sm[HW_BR2];
#pragma unroll
            for (int j = 0; j < 32; j++) {
                float v = pre[j];
                v = fmaf(cx, sm[HW_WR1 + j * 68 + 64], v);
                v = fmaf(cy, sm[HW_WR1 + j * 68 + 65], v);
                v = fmaf(cz, sm[HW_WR1 + j * 68 + 66], v);
                v = fmaf(cw, sm[HW_WR1 + j * 68 + 67], v);
                v = fmaxf(v, 0.f);
                a = fmaf(v, sm[HW_WR2 + j], a);
            }
            al[loc] = a;
        }
        int att = sample_lp<25>(al, keys.a[6], keys.b[6], b, alp1);

        int4 ro = *(const int4*)(canvas0 + (b * 25 + att) * 4);
        int4 rf = *(const int4*)(refp + b * 4);
        float att_rew = (ro.x == rf.x && ro.y == rf.y && ro.z == rf.z && ro.w == rf.w)
                            ? 1.f : -1.f;
        int loc1 = (ro.z + c_offx[ls1]) * 5 + (ro.w + c_offy[ls1]);
        int l1c = min(max(loc1, 0), 24);
        int4 pt1 = *(const int4*)(canvas1 + (b * 25 + l1c) * 4);
        bool ok1 = (loc1 >= 0) && (loc1 < 25) && ((pt1.x + pt1.y + pt1.z + pt1.w) >= 0);
        float loc_r1 = ok1 ? 1.f : -1.f;
        float col_r1 = ok1 ? ((cs1 == pt1.x) ? 1.f : -1.f) : 0.f;

        out[3 * BN + b] = clp1;
        out[4 * BN + b] = slp1;
        out[5 * BN + b] = llp1;
        out[6 * BN + b] = alp1;
        out[(7 + 3) * BN + b] = loc_r1;
        out[(7 + 4) * BN + b] = col_r1;
        out[(7 + 5) * BN + b] = loc_r1;
        out[(7 + 6) * BN + b] = att_rew;
    }
}

// ================= launch =================
extern "C" void kernel_launch(void* const* d_in, const int* in_sizes, int n_in,
                              void* d_out, int out_size) {
    const int*   inst0   = (const int*)d_in[0];
    const int*   inst1   = (const int*)d_in[1];
    const int*   canvas0 = (const int*)d_in[2];
    const int*   canvas1 = (const int*)d_in[3];
    const int*   refp    = (const int*)d_in[4];
    const float* embed   = (const float*)d_in[5];
    const float* W_ih    = (const float*)d_in[6];
    const float* W_hh    = (const float*)d_in[7];
    const float* b_ih    = (const float*)d_in[8];
    const float* b_hh    = (const float*)d_in[9];
    const float* Wc      = (const float*)d_in[10];
    const float* bc      = (const float*)d_in[11];
    const float* Ws      = (const float*)d_in[12];
    const float* bs      = (const float*)d_in[13];
    const float* Wl      = (const float*)d_in[14];
    const float* bl      = (const float*)d_in[15];
    const float* Wr1     = (const float*)d_in[16];
    const float* br1     = (const float*)d_in[17];
    const float* Wr2     = (const float*)d_in[18];
    const float* br2     = (const float*)d_in[19];
    const float* Wp      = (const float*)d_in[20];
    const float* bp      = (const float*)d_in[21];

    Keys keys;
#if THREEFRY_PARTITIONABLE
    for (int i = 0; i < 7; i++)
        threefry2x32(0u, 42u, 0u, (uint32_t)i, keys.a[i], keys.b[i]);
#else
    uint32_t o[14];
    for (int i = 0; i < 7; i++)
        threefry2x32(0u, 42u, (uint32_t)i, (uint32_t)(i + 7), o[i], o[7 + i]);
    for (int i = 0; i < 7; i++) { keys.a[i] = o[2 * i]; keys.b[i] = o[2 * i + 1]; }
#endif

    cudaFuncSetAttribute(lstm_kernel, cudaFuncAttributeMaxDynamicSharedMemorySize,
                         LSTM_SMEM_BYTES);
    cudaFuncSetAttribute(heads_kernel, cudaFuncAttributeMaxDynamicSharedMemorySize,
                         HEADS_SMEM_BYTES);

    tokgate_kernel<<<(VOCAB + 7) / 8, 256>>>(embed, W_ih, b_ih, b_hh);
    lstm_kernel<<<dim3(BN / TBM, 2), 256, LSTM_SMEM_BYTES>>>(inst0, inst1, W_hh);
    heads_kernel<<<dim3(BN / HT, 2), HT, HEADS_SMEM_BYTES>>>(
        canvas0, canvas1, refp, Wc, bc, Ws, bs, Wl, bl, Wr1, br1, Wr2, br2,
        Wp, bp, (float*)d_out, keys);
}

// round 10
// speedup vs baseline: 4.9694x; 1.0503x over previous
#include <cuda_runtime.h>
#include <cuda_fp16.h>
#include <cstdint>

#define BN 16384
#define SEQ 32
#define RNN 64
#define NG 256
#define VOCAB 1001
#define TBM 32             // samples per LSTM CTA
#define HT 64              // heads threads per block
#define THREEFRY_PARTITIONABLE 1

typedef unsigned long long u64;

__device__ float g_h[2 * BN * RNN];
__device__ float g_tokgate[VOCAB * NG];

// ================= threefry2x32 (exact JAX algorithm) =================
__host__ __device__ __forceinline__ uint32_t rotl32(uint32_t x, int d) {
    return (x << d) | (x >> (32 - d));
}
__host__ __device__ __forceinline__ void threefry2x32(uint32_t k0, uint32_t k1,
                                                      uint32_t c0, uint32_t c1,
                                                      uint32_t& o0, uint32_t& o1) {
    uint32_t ks2 = k0 ^ k1 ^ 0x1BD11BDAu;
    uint32_t x0 = c0 + k0, x1 = c1 + k1;
#define TF_R4(a,b,c,d) \
    x0 += x1; x1 = rotl32(x1,a); x1 ^= x0; \
    x0 += x1; x1 = rotl32(x1,b); x1 ^= x0; \
    x0 += x1; x1 = rotl32(x1,c); x1 ^= x0; \
    x0 += x1; x1 = rotl32(x1,d); x1 ^= x0;
    TF_R4(13,15,26,6);  x0 += k1;  x1 += ks2 + 1u;
    TF_R4(17,29,16,24); x0 += ks2; x1 += k0  + 2u;
    TF_R4(13,15,26,6);  x0 += k0;  x1 += k1  + 3u;
    TF_R4(17,29,16,24); x0 += k1;  x1 += ks2 + 4u;
    TF_R4(13,15,26,6);  x0 += ks2; x1 += k0  + 5u;
#undef TF_R4
    o0 = x0; o1 = x1;
}

struct Keys { uint32_t a[7]; uint32_t b[7]; };

__device__ __forceinline__ uint32_t jax_bits32(uint32_t k0, uint32_t k1,
                                               uint32_t idx, uint32_t half) {
#if THREEFRY_PARTITIONABLE
    uint32_t y0, y1;
    threefry2x32(k0, k1, 0u, idx, y0, y1);
    return y0 ^ y1;
#else
    uint32_t p = (idx < half) ? idx : idx - half;
    uint32_t y0, y1;
    threefry2x32(k0, k1, p, p + half, y0, y1);
    return (idx < half) ? y0 : y1;
#endif
}
__device__ __forceinline__ float jax_gumbel(uint32_t k0, uint32_t k1,
                                            uint32_t idx, uint32_t half) {
    uint32_t bits = jax_bits32(k0, k1, idx, half);
    float f = __uint_as_float((bits >> 9) | 0x3f800000u) - 1.0f;
    f = fmaxf(f, 1.17549435e-38f);
    return -logf(-logf(f));
}
__device__ __forceinline__ float sigf(float x) {
    return fmaf(0.5f, tanhf(0.5f * x), 0.5f);   // exact path (heads unused here)
}

// ---- MUFU-based fast activations (LSTM epilogue only) ----
// __expf -> MUFU.EX2, __fdividef -> MUFU.RCP: ~2-5e-7 rel err, off the FMA pipe.
__device__ __forceinline__ float fsig(float x) {
    return __fdividef(1.0f, 1.0f + __expf(-x));
}
__device__ __forceinline__ float ftanh(float x) {
    float xc = fminf(fmaxf(x, -12.0f), 12.0f);   // tanh(|12|) rounds to ±1 in fp32
    float t = __expf(2.0f * xc);
    return __fdividef(t - 1.0f, t + 1.0f);
}

// mma.sync m16n8k16 f16 (baseline PTX)
__device__ __forceinline__ void mma_f16(float d[4], const uint32_t a[4],
                                        uint32_t b0, uint32_t b1) {
    asm volatile(
        "mma.sync.aligned.m16n8k16.row.col.f32.f16.f16.f32 "
        "{%0,%1,%2,%3}, {%4,%5,%6,%7}, {%8,%9}, {%0,%1,%2,%3};"
        : "+f"(d[0]), "+f"(d[1]), "+f"(d[2]), "+f"(d[3])
        : "r"(a[0]), "r"(a[1]), "r"(a[2]), "r"(a[3]), "r"(b0), "r"(b1));
}

__device__ __forceinline__ uint32_t pack_h2(__half lo_h, __half hi_h) {
    __half2 h2 = __halves2half2(lo_h, hi_h);
    return *(uint32_t*)&h2;
}

// ================= tokgate precompute =================
// g_tokgate[v][c], c = 4u+g : embed[v] . W_ih[g*64+u] + b_ih + b_hh
__global__ void __launch_bounds__(256)
tokgate_kernel(const float* __restrict__ embed, const float* __restrict__ W_ih,
               const float* __restrict__ b_ih, const float* __restrict__ b_hh) {
    __shared__ float e[8][64];
    const int v0 = blockIdx.x * 8;
    const int tid = threadIdx.x;
    for (int i = tid; i < 8 * 64; i += 256) {
        int vv = v0 + (i >> 6);
        e[i >> 6][i & 63] = (vv < VOCAB) ? embed[vv * 64 + (i & 63)] : 0.f;
    }
    __syncthreads();
    const int c = tid, gg = c & 3, u = c >> 2;
    const int row = gg * 64 + u;
    float wreg[64];
    const float4* wp = (const float4*)(W_ih + row * 64);
#pragma unroll
    for (int i = 0; i < 16; i++) {
        float4 w4 = wp[i];
        wreg[4 * i] = w4.x; wreg[4 * i + 1] = w4.y;
        wreg[4 * i + 2] = w4.z; wreg[4 * i + 3] = w4.w;
    }
    const float bias = b_ih[row] + b_hh[row];
#pragma unroll
    for (int j = 0; j < 8; j++) {
        int v = v0 + j;
        if (v >= VOCAB) break;
        float d = bias;
#pragma unroll
        for (int k = 0; k < 64; k++) d = fmaf(e[j][k], wreg[k], d);
        g_tokgate[v * NG + c] = d;
    }
}

// ================= LSTM kernel (mma.sync f16 k16, 3-product compensation) =================
// smem (32-bit words), fp16x2-packed along K, stride 36:
//   Whi [256][36] @ 0       Wlo [256][36] @ 9216
//   Hhi [32][36]  @ 18432   Hlo [32][36]  @ 19584
//   tok [32][32]  @ 20736
// total 21760 words = 87040 bytes  -> 2 CTAs/SM
#define WSTR 36
#define OFF_WHI 0
#define OFF_WLO (256 * WSTR)
#define OFF_HHI (2 * 256 * WSTR)
#define OFF_HLO (OFF_HHI + TBM * WSTR)
#define OFF_TOK (OFF_HLO + TBM * WSTR)
#define LSTM_SMEM_WORDS (OFF_TOK + TBM * SEQ)
#define LSTM_SMEM_BYTES (LSTM_SMEM_WORDS * 4)
// column order: c' = nb*64 + nt*8 + 4*up + g ; unit u = nb*16 + nt*2 + up

__global__ void __launch_bounds__(256, 2)
lstm_kernel(const int* __restrict__ inst0, const int* __restrict__ inst1,
            const float* __restrict__ W_hh) {
    extern __shared__ uint32_t smw[];
    uint32_t* Whi = smw + OFF_WHI;
    uint32_t* Wlo = smw + OFF_WLO;
    uint32_t* Hhi = smw + OFF_HHI;
    uint32_t* Hlo = smw + OFF_HLO;
    int*      tok = (int*)(smw + OFF_TOK);    // [s][t]

    const int tid  = threadIdx.x;
    const int wid  = tid >> 5, lane = tid & 31;
    const int gid  = lane >> 2, tig = lane & 3;
    const int mb   = wid & 1;                 // m-block: samples mb*16..mb*16+15
    const int nb   = wid >> 1;                // n-block: cols nb*64..nb*64+63
    const int base = blockIdx.x * TBM;
    const int* inst = (blockIdx.y == 0) ? inst0 : inst1;
    float* hout = g_h + blockIdx.y * (BN * RNN);

    // ---- stage W_hh split into fp16 hi/lo, permuted column order, packed k-pairs ----
    for (int idx = tid; idx < NG * 32; idx += 256) {
        int c = idx >> 5, kp = idx & 31;
        int cnb = c >> 6, cnt = (c >> 3) & 7, cup = (c >> 2) & 1, cg = c & 3;
        int u = cnb * 16 + cnt * 2 + cup;
        const float* wr = W_hh + (cg * 64 + u) * 64 + 2 * kp;
        float w0 = wr[0], w1 = wr[1];
        __half h0 = __float2half_rn(w0), h1 = __float2half_rn(w1);
        __half l0 = __float2half_rn(w0 - __half2float(h0));
        __half l1 = __float2half_rn(w1 - __half2float(h1));
        Whi[c * WSTR + kp] = pack_h2(h0, h1);
        Wlo[c * WSTR + kp] = pack_h2(l0, l1);
    }
    // tokens
    for (int idx = tid; idx < TBM * SEQ; idx += 256)
        tok[idx] = inst[base * SEQ + idx];
    __syncthreads();

    // thread's fixed sample row & unit-pair half
    const int row   = mb * 16 + gid + 8 * (tig & 1);
    const int upair = tig >> 1;
    const int m0    = mb * 16;
    const int cn0   = nb * 64;
    __half* HHIh = (__half*)Hhi;   // [row][72 halves]
    __half* HLOh = (__half*)Hlo;
    float c_reg[8];
#pragma unroll
    for (int i = 0; i < 8; i++) c_reg[i] = 0.f;

    for (int t = 0; t < SEQ; t++) {
        float d[8][4];
#pragma unroll
        for (int nt = 0; nt < 8; nt++)
#pragma unroll
            for (int j = 0; j < 4; j++) d[nt][j] = 0.f;

        if (t > 0) {   // h_{-1} = 0: gates at t=0 are tokgate only
#pragma unroll
            for (int kt = 0; kt < 4; kt++) {
                const int kp0 = kt * 8 + tig;
                uint32_t ahi[4], alo[4];
                ahi[0] = Hhi[(m0 + gid)     * WSTR + kp0];
                ahi[1] = Hhi[(m0 + gid + 8) * WSTR + kp0];
                ahi[2] = Hhi[(m0 + gid)     * WSTR + kp0 + 4];
                ahi[3] = Hhi[(m0 + gid + 8) * WSTR + kp0 + 4];
                alo[0] = Hlo[(m0 + gid)     * WSTR + kp0];
                alo[1] = Hlo[(m0 + gid + 8) * WSTR + kp0];
                alo[2] = Hlo[(m0 + gid)     * WSTR + kp0 + 4];
                alo[3] = Hlo[(m0 + gid + 8) * WSTR + kp0 + 4];

                uint32_t bh[8][2];
#pragma unroll
                for (int nt = 0; nt < 8; nt++) {
                    const int c = cn0 + nt * 8 + gid;
                    bh[nt][0] = Whi[c * WSTR + kp0];
                    bh[nt][1] = Whi[c * WSTR + kp0 + 4];
                    mma_f16(d[nt], ahi, bh[nt][0], bh[nt][1]);   // hi . Whi
                }
#pragma unroll
                for (int nt = 0; nt < 8; nt++)
                    mma_f16(d[nt], alo, bh[nt][0], bh[nt][1]);   // lo . Whi
#pragma unroll
                for (int nt = 0; nt < 8; nt++) {
                    const int c = cn0 + nt * 8 + gid;
                    uint32_t bl0 = Wlo[c * WSTR + kp0];
                    uint32_t bl1 = Wlo[c * WSTR + kp0 + 4];
                    mma_f16(d[nt], ahi, bl0, bl1);               // hi . Wlo
                }
            }
        }
        __syncthreads();   // all reads of H done before rewrite

        // ---- epilogue: 2-shfl quad-exchange, + tokgate, LSTM cell (MUFU), store ----
        const int tv = tok[row * SEQ + t];
        const float* tgrow = g_tokgate + tv * NG;
        const bool e = (tig & 1) == 0;

#pragma unroll
        for (int nt = 0; nt < 8; nt++) {
            // lane e needs partner o's (d0,d1); lane o needs partner e's (d2,d3).
            float x0 = e ? d[nt][2] : d[nt][0];
            float x1 = e ? d[nt][3] : d[nt][1];
            float s0 = __shfl_xor_sync(0xffffffffu, x0, 1);
            float s1 = __shfl_xor_sync(0xffffffffu, x1, 1);
            float ig = e ? d[nt][0] : s0;
            float fg = e ? d[nt][1] : s1;
            float gg = e ? s0 : d[nt][2];
            float og = e ? s1 : d[nt][3];
            const int u = nb * 16 + nt * 2 + upair;
            float4 tgv = *(const float4*)(tgrow + 4 * u);
            ig += tgv.x; fg += tgv.y; gg += tgv.z; og += tgv.w;
            float cb = fsig(fg) * c_reg[nt] + fsig(ig) * ftanh(gg);
            float h = fsig(og) * ftanh(cb);
            c_reg[nt] = cb;
            __half hh = __float2half_rn(h);
            HHIh[row * (2 * WSTR) + u] = hh;
            HLOh[row * (2 * WSTR) + u] = __float2half_rn(h - __half2float(hh));
            if (t == SEQ - 1) hout[(base + row) * RNN + u] = h;
        }
        __syncthreads();   // h writes visible before next step's reads
    }
}

// ================= heads kernel (dialog-split: grid.y = 0/1) =================
#define HW_WC   0
#define HW_BC   (HW_WC + 192)
#define HW_WS   (HW_BC + 4)
#define HW_BS   (HW_WS + 192)
#define HW_WL   (HW_BS + 4)
#define HW_BL   (HW_WL + 1600)
#define HW_WP   (HW_BL + 28)
#define HW_BP   (HW_WP + 512)
#define HW_WR1  (HW_BP + 8)
#define HW_BR1  (HW_WR1 + 2176)
#define HW_WR2  (HW_BR1 + 32)
#define HW_BR2  (HW_WR2 + 32)
#define HW_HB   (HW_BR2 + 4)
#define HEADS_SMEM_FLOATS (HW_HB + HT * 65)
#define HEADS_SMEM_BYTES  (HEADS_SMEM_FLOATS * 4)

__device__ const int c_offx[8] = {-1, 1, 0, 0, -1, -1, 1, 1};
__device__ const int c_offy[8] = {0, 0, 1, -1, -1, 1, -1, 1};

template <int V>
__device__ __forceinline__ int sample_lp(const float* lg, uint32_t k0, uint32_t k1,
                                         int b, float& lp) {
    const uint32_t half = (uint32_t)(BN * V / 2);
    int best = 0;
    float bestz = -1e30f, bestl = lg[0], m = -1e30f;
#pragma unroll
    for (int v = 0; v < V; v++) {
        float z = lg[v] + jax_gumbel(k0, k1, (uint32_t)(b * V + v), half);
        if (z > bestz) { bestz = z; best = v; bestl = lg[v]; }
        m = fmaxf(m, lg[v]);
    }
    float ssum = 0.f;
#pragma unroll
    for (int v = 0; v < V; v++) ssum += expf(lg[v] - m);
    lp = (bestl - m) - logf(ssum);
    return best;
}

__global__ void __launch_bounds__(HT)
heads_kernel(const int* __restrict__ canvas0, const int* __restrict__ canvas1,
             const int* __restrict__ refp,
             const float* __restrict__ Wc, const float* __restrict__ bc,
             const float* __restrict__ Ws, const float* __restrict__ bs,
             const float* __restrict__ Wl, const float* __restrict__ bl,
             const float* __restrict__ Wr1, const float* __restrict__ br1,
             const float* __restrict__ Wr2, const float* __restrict__ br2,
             const float* __restrict__ Wp, const float* __restrict__ bp,
             float* __restrict__ out, Keys keys) {
    extern __shared__ float sm[];
    const int tid = threadIdx.x;
    const int b = blockIdx.x * HT + tid;
    const int tile = blockIdx.x * HT;
    const int dialog = blockIdx.y;

    // common weights
    for (int i = tid; i < 192;  i += HT) sm[HW_WC + i] = Wc[i];
    for (int i = tid; i < 192;  i += HT) sm[HW_WS + i] = Ws[i];
    if (tid < 3)  sm[HW_BC + tid]  = bc[tid];
    if (tid < 3)  sm[HW_BS + tid]  = bs[tid];
    if (dialog == 0) {
        for (int i = tid; i < 1600; i += HT) sm[HW_WL + i] = Wl[i];
        if (tid < 25) sm[HW_BL + tid]  = bl[tid];
    } else {
        for (int i = tid; i < 512;  i += HT) sm[HW_WP + i] = Wp[i];
        for (int i = tid; i < 2176; i += HT) sm[HW_WR1 + i] = Wr1[i];
        if (tid < 8)  sm[HW_BP + tid]  = bp[tid];
        if (tid < 32) sm[HW_BR1 + tid] = br1[tid];
        if (tid < 32) sm[HW_WR2 + tid] = Wr2[tid];
        if (tid == 0) sm[HW_BR2] = br2[0];
    }

    float* hb = sm + HW_HB;
    for (int i = tid; i < HT * RNN; i += HT) {
        int s = i >> 6, k = i & 63;
        hb[s * 65 + k] = g_h[dialog * (BN * RNN) + (tile + s) * RNN + k];
    }
    __syncthreads();

    const float* h = hb + tid * 65;

    // color/shape logits (both dialogs)
    float lc[3], lsh[3];
#pragma unroll
    for (int r = 0; r < 3; r++) {
        float d = 0.f, ee = 0.f;
        for (int k = 0; k < 64; k++) {
            d = fmaf(h[k], sm[HW_WC + r * 64 + k], d);
            ee = fmaf(h[k], sm[HW_WS + r * 64 + k], ee);
        }
        lc[r] = d + sm[HW_BC + r];
        lsh[r] = ee + sm[HW_BS + r];
    }

    if (dialog == 0) {
        float ll[25];
#pragma unroll 5
        for (int r = 0; r < 25; r++) {
            float d = 0.f;
            for (int k = 0; k < 64; k++) d = fmaf(h[k], sm[HW_WL + r * 64 + k], d);
            ll[r] = d + sm[HW_BL + r];
        }
        float clp0, slp0, llp0;
        int cs0  = sample_lp<3>(lc,  keys.a[0], keys.b[0], b, clp0);
        sample_lp<3>(lsh, keys.a[1], keys.b[1], b, slp0);
        int loc0 = sample_lp<25>(ll, keys.a[2], keys.b[2], b, llp0);

        int lclip = min(max(loc0, 0), 24);
        int4 pt = *(const int4*)(canvas1 + (b * 25 + lclip) * 4);
        bool ok0 = (loc0 >= 0) && (loc0 < 25) && ((pt.x + pt.y + pt.z + pt.w) >= 0);
        float loc_r0 = ok0 ? 1.f : -1.f;
        float col_r0 = ok0 ? ((cs0 == pt.x) ? 1.f : -1.f) : 0.f;

        out[0 * BN + b] = clp0;
        out[1 * BN + b] = slp0;
        out[2 * BN + b] = llp0;
        out[(7 + 0) * BN + b] = loc_r0;
        out[(7 + 1) * BN + b] = col_r0;
        out[(7 + 2) * BN + b] = loc_r0;
    } else {
        float lp8[8];
#pragma unroll 4
        for (int r = 0; r < 8; r++) {
            float d = 0.f;
            for (int k = 0; k < 64; k++) d = fmaf(h[k], sm[HW_WP + r * 64 + k], d);
            lp8[r] = d + sm[HW_BP + r];
        }
        float clp1, slp1, llp1, alp1;
        int cs1 = sample_lp<3>(lc,  keys.a[3], keys.b[3], b, clp1);
        sample_lp<3>(lsh, keys.a[4], keys.b[4], b, slp1);
        int ls1 = sample_lp<8>(lp8, keys.a[5], keys.b[5], b, llp1);

        float pre[32];
#pragma unroll 8
        for (int j = 0; j < 32; j++) {
            float d = 0.f;
            for (int k = 0; k < 64; k++) d = fmaf(h[k], sm[HW_WR1 + j * 68 + k], d);
            pre[j] = d + sm[HW_BR1 + j];
        }
        float al[25];
#pragma unroll
        for (int loc = 0; loc < 25; loc++) {
            int4 cv = *(const int4*)(canvas0 + (b * 25 + loc) * 4);
            float cx = (float)cv.x, cy = (float)cv.y, cz = (float)cv.z, cw = (float)cv.w;
            float a = sm[HW_BR2];
#pragma unroll
            for (int j = 0; j < 32; j++) {
                float v = pre[j];
                v = fmaf(cx, sm[HW_WR1 + j * 68 + 64], v);
                v = fmaf(cy, sm[HW_WR1 + j * 68 + 65], v);
                v = fmaf(cz, sm[HW_WR1 + j * 68 + 66], v);
                v = fmaf(cw, sm[HW_WR1 + j * 68 + 67], v);
                v = fmaxf(v, 0.f);
                a = fmaf(v, sm[HW_WR2 + j], a);
            }
            al[loc] = a;
        }
        int att = sample_lp<25>(al, keys.a[6], keys.b[6], b, alp1);

        int4 ro = *(const int4*)(canvas0 + (b * 25 + att) * 4);
        int4 rf = *(const int4*)(refp + b * 4);
        float att_rew = (ro.x == rf.x && ro.y == rf.y && ro.z == rf.z && ro.w == rf.w)
                            ? 1.f : -1.f;
        int loc1 = (ro.z + c_offx[ls1]) * 5 + (ro.w + c_offy[ls1]);
        int l1c = min(max(loc1, 0), 24);
        int4 pt1 = *(const int4*)(canvas1 + (b * 25 + l1c) * 4);
        bool ok1 = (loc1 >= 0) && (loc1 < 25) && ((pt1.x + pt1.y + pt1.z + pt1.w) >= 0);
        float loc_r1 = ok1 ? 1.f : -1.f;
        float col_r1 = ok1 ? ((cs1 == pt1.x) ? 1.f : -1.f) : 0.f;

        out[3 * BN + b] = clp1;
        out[4 * BN + b] = slp1;
        out[5 * BN + b] = llp1;
        out[6 * BN + b] = alp1;
        out[(7 + 3) * BN + b] = loc_r1;
        out[(7 + 4) * BN + b] = col_r1;
        out[(7 + 5) * BN + b] = loc_r1;
        out[(7 + 6) * BN + b] = att_rew;
    }
}

// ================= launch =================
extern "C" void kernel_launch(void* const* d_in, const int* in_sizes, int n_in,
                              void* d_out, int out_size) {
    const int*   inst0   = (const int*)d_in[0];
    const int*   inst1   = (const int*)d_in[1];
    const int*   canvas0 = (const int*)d_in[2];
    const int*   canvas1 = (const int*)d_in[3];
    const int*   refp    = (const int*)d_in[4];
    const float* embed   = (const float*)d_in[5];
    const float* W_ih    = (const float*)d_in[6];
    const float* W_hh    = (const float*)d_in[7];
    const float* b_ih    = (const float*)d_in[8];
    const float* b_hh    = (const float*)d_in[9];
    const float* Wc      = (const float*)d_in[10];
    const float* bc      = (const float*)d_in[11];
    const float* Ws      = (const float*)d_in[12];
    const float* bs      = (const float*)d_in[13];
    const float* Wl      = (const float*)d_in[14];
    const float* bl      = (const float*)d_in[15];
    const float* Wr1     = (const float*)d_in[16];
    const float* br1     = (const float*)d_in[17];
    const float* Wr2     = (const float*)d_in[18];
    const float* br2     = (const float*)d_in[19];
    const float* Wp      = (const float*)d_in[20];
    const float* bp      = (const float*)d_in[21];

    Keys keys;
#if THREEFRY_PARTITIONABLE
    for (int i = 0; i < 7; i++)
        threefry2x32(0u, 42u, 0u, (uint32_t)i, keys.a[i], keys.b[i]);
#else
    uint32_t o[14];
    for (int i = 0; i < 7; i++)
        threefry2x32(0u, 42u, (uint32_t)i, (uint32_t)(i + 7), o[i], o[7 + i]);
    for (int i = 0; i < 7; i++) { keys.a[i] = o[2 * i]; keys.b[i] = o[2 * i + 1]; }
#endif

    cudaFuncSetAttribute(lstm_kernel, cudaFuncAttributeMaxDynamicSharedMemorySize,
                         LSTM_SMEM_BYTES);
    cudaFuncSetAttribute(heads_kernel, cudaFuncAttributeMaxDynamicSharedMemorySize,
                         HEADS_SMEM_BYTES);

    tokgate_kernel<<<(VOCAB + 7) / 8, 256>>>(embed, W_ih, b_ih, b_hh);
    lstm_kernel<<<dim3(BN / TBM, 2), 256, LSTM_SMEM_BYTES>>>(inst0, inst1, W_hh);
    heads_kernel<<<dim3(BN / HT, 2), HT, HEADS_SMEM_BYTES>>>(
        canvas0, canvas1, refp, Wc, bc, Ws, bs, Wl, bl, Wr1, br1, Wr2, br2,
        Wp, bp, (float*)d_out, keys);
}

// round 11
// speedup vs baseline: 5.4479x; 1.0963x over previous
#include <cuda_runtime.h>
#include <cuda_fp16.h>
#include <cstdint>

#define BN 16384
#define SEQ 32
#define RNN 64
#define NG 256
#define VOCAB 1001
#define TBM 32             // samples per LSTM CTA
#define HT 64              // heads threads per block
#define EXACT_FROM 26      // steps >= this use full 3-product compensation
#define THREEFRY_PARTITIONABLE 1

typedef unsigned long long u64;

__device__ float g_h[2 * BN * RNN];
__device__ float g_tokgate[VOCAB * NG];

// ================= threefry2x32 (exact JAX algorithm) =================
__host__ __device__ __forceinline__ uint32_t rotl32(uint32_t x, int d) {
    return (x << d) | (x >> (32 - d));
}
__host__ __device__ __forceinline__ void threefry2x32(uint32_t k0, uint32_t k1,
                                                      uint32_t c0, uint32_t c1,
                                                      uint32_t& o0, uint32_t& o1) {
    uint32_t ks2 = k0 ^ k1 ^ 0x1BD11BDAu;
    uint32_t x0 = c0 + k0, x1 = c1 + k1;
#define TF_R4(a,b,c,d) \
    x0 += x1; x1 = rotl32(x1,a); x1 ^= x0; \
    x0 += x1; x1 = rotl32(x1,b); x1 ^= x0; \
    x0 += x1; x1 = rotl32(x1,c); x1 ^= x0; \
    x0 += x1; x1 = rotl32(x1,d); x1 ^= x0;
    TF_R4(13,15,26,6);  x0 += k1;  x1 += ks2 + 1u;
    TF_R4(17,29,16,24); x0 += ks2; x1 += k0  + 2u;
    TF_R4(13,15,26,6);  x0 += k0;  x1 += k1  + 3u;
    TF_R4(17,29,16,24); x0 += k1;  x1 += ks2 + 4u;
    TF_R4(13,15,26,6);  x0 += ks2; x1 += k0  + 5u;
#undef TF_R4
    o0 = x0; o1 = x1;
}

struct Keys { uint32_t a[7]; uint32_t b[7]; };

__device__ __forceinline__ uint32_t jax_bits32(uint32_t k0, uint32_t k1,
                                               uint32_t idx, uint32_t half) {
#if THREEFRY_PARTITIONABLE
    uint32_t y0, y1;
    threefry2x32(k0, k1, 0u, idx, y0, y1);
    return y0 ^ y1;
#else
    uint32_t p = (idx < half) ? idx : idx - half;
    uint32_t y0, y1;
    threefry2x32(k0, k1, p, p + half, y0, y1);
    return (idx < half) ? y0 : y1;
#endif
}
__device__ __forceinline__ float jax_gumbel(uint32_t k0, uint32_t k1,
                                            uint32_t idx, uint32_t half) {
    uint32_t bits = jax_bits32(k0, k1, idx, half);
    float f = __uint_as_float((bits >> 9) | 0x3f800000u) - 1.0f;
    f = fmaxf(f, 1.17549435e-38f);
    return -logf(-logf(f));
}
__device__ __forceinline__ float sigf(float x) {
    return fmaf(0.5f, tanhf(0.5f * x), 0.5f);   // exact path (heads)
}

// ---- MUFU-based fast activations (LSTM epilogue only) ----
__device__ __forceinline__ float fsig(float x) {
    return __fdividef(1.0f, 1.0f + __expf(-x));
}
__device__ __forceinline__ float ftanh(float x) {
    float xc = fminf(fmaxf(x, -12.0f), 12.0f);
    float t = __expf(2.0f * xc);
    return __fdividef(t - 1.0f, t + 1.0f);
}

// mma.sync m16n8k16 f16 (baseline PTX)
__device__ __forceinline__ void mma_f16(float d[4], const uint32_t a[4],
                                        uint32_t b0, uint32_t b1) {
    asm volatile(
        "mma.sync.aligned.m16n8k16.row.col.f32.f16.f16.f32 "
        "{%0,%1,%2,%3}, {%4,%5,%6,%7}, {%8,%9}, {%0,%1,%2,%3};"
        : "+f"(d[0]), "+f"(d[1]), "+f"(d[2]), "+f"(d[3])
        : "r"(a[0]), "r"(a[1]), "r"(a[2]), "r"(a[3]), "r"(b0), "r"(b1));
}

__device__ __forceinline__ uint32_t pack_h2(__half lo_h, __half hi_h) {
    __half2 h2 = __halves2half2(lo_h, hi_h);
    return *(uint32_t*)&h2;
}

// ================= tokgate precompute =================
__global__ void __launch_bounds__(256)
tokgate_kernel(const float* __restrict__ embed, const float* __restrict__ W_ih,
               const float* __restrict__ b_ih, const float* __restrict__ b_hh) {
    __shared__ float e[8][64];
    const int v0 = blockIdx.x * 8;
    const int tid = threadIdx.x;
    for (int i = tid; i < 8 * 64; i += 256) {
        int vv = v0 + (i >> 6);
        e[i >> 6][i & 63] = (vv < VOCAB) ? embed[vv * 64 + (i & 63)] : 0.f;
    }
    __syncthreads();
    const int c = tid, gg = c & 3, u = c >> 2;
    const int row = gg * 64 + u;
    float wreg[64];
    const float4* wp = (const float4*)(W_ih + row * 64);
#pragma unroll
    for (int i = 0; i < 16; i++) {
        float4 w4 = wp[i];
        wreg[4 * i] = w4.x; wreg[4 * i + 1] = w4.y;
        wreg[4 * i + 2] = w4.z; wreg[4 * i + 3] = w4.w;
    }
    const float bias = b_ih[row] + b_hh[row];
#pragma unroll
    for (int j = 0; j < 8; j++) {
        int v = v0 + j;
        if (v >= VOCAB) break;
        float d = bias;
#pragma unroll
        for (int k = 0; k < 64; k++) d = fmaf(e[j][k], wreg[k], d);
        g_tokgate[v * NG + c] = d;
    }
}

// ================= LSTM kernel =================
// Precision schedule: contractive recurrence (forget gate ~0.5) damps early-step
// gate errors by ~0.6^(31-t); steps < EXACT_FROM use 1 fp16 product (error ~1e-5
// -> ~2e-7 at output), steps >= EXACT_FROM use full 3-product compensation.
#define WSTR 36
#define OFF_WHI 0
#define OFF_WLO (256 * WSTR)
#define OFF_HHI (2 * 256 * WSTR)
#define OFF_HLO (OFF_HHI + TBM * WSTR)
#define OFF_TOK (OFF_HLO + TBM * WSTR)
#define LSTM_SMEM_WORDS (OFF_TOK + TBM * SEQ)
#define LSTM_SMEM_BYTES (LSTM_SMEM_WORDS * 4)
// column order: c' = nb*64 + nt*8 + 4*up + g ; unit u = nb*16 + nt*2 + up

__global__ void __launch_bounds__(256, 2)
lstm_kernel(const int* __restrict__ inst0, const int* __restrict__ inst1,
            const float* __restrict__ W_hh) {
    extern __shared__ uint32_t smw[];
    uint32_t* Whi = smw + OFF_WHI;
    uint32_t* Wlo = smw + OFF_WLO;
    uint32_t* Hhi = smw + OFF_HHI;
    uint32_t* Hlo = smw + OFF_HLO;
    int*      tok = (int*)(smw + OFF_TOK);    // [s][t]

    const int tid  = threadIdx.x;
    const int wid  = tid >> 5, lane = tid & 31;
    const int gid  = lane >> 2, tig = lane & 3;
    const int mb   = wid & 1;
    const int nb   = wid >> 1;
    const int base = blockIdx.x * TBM;
    const int* inst = (blockIdx.y == 0) ? inst0 : inst1;
    float* hout = g_h + blockIdx.y * (BN * RNN);

    // ---- stage W_hh split into fp16 hi/lo, permuted column order, packed k-pairs ----
    for (int idx = tid; idx < NG * 32; idx += 256) {
        int c = idx >> 5, kp = idx & 31;
        int cnb = c >> 6, cnt = (c >> 3) & 7, cup = (c >> 2) & 1, cg = c & 3;
        int u = cnb * 16 + cnt * 2 + cup;
        const float* wr = W_hh + (cg * 64 + u) * 64 + 2 * kp;
        float w0 = wr[0], w1 = wr[1];
        __half h0 = __float2half_rn(w0), h1 = __float2half_rn(w1);
        __half l0 = __float2half_rn(w0 - __half2float(h0));
        __half l1 = __float2half_rn(w1 - __half2float(h1));
        Whi[c * WSTR + kp] = pack_h2(h0, h1);
        Wlo[c * WSTR + kp] = pack_h2(l0, l1);
    }
    for (int idx = tid; idx < TBM * SEQ; idx += 256)
        tok[idx] = inst[base * SEQ + idx];
    __syncthreads();

    const int row   = mb * 16 + gid + 8 * (tig & 1);
    const int upair = tig >> 1;
    const int m0    = mb * 16;
    const int cn0   = nb * 64;
    __half* HHIh = (__half*)Hhi;   // [row][72 halves]
    __half* HLOh = (__half*)Hlo;
    float c_reg[8];
#pragma unroll
    for (int i = 0; i < 8; i++) c_reg[i] = 0.f;

    for (int t = 0; t < SEQ; t++) {
        float d[8][4];
#pragma unroll
        for (int nt = 0; nt < 8; nt++)
#pragma unroll
            for (int j = 0; j < 4; j++) d[nt][j] = 0.f;

        if (t > 0) {   // h_{-1} = 0: gates at t=0 are tokgate only
            const bool exact = (t >= EXACT_FROM);
#pragma unroll
            for (int kt = 0; kt < 4; kt++) {
                const int kp0 = kt * 8 + tig;
                uint32_t ahi[4];
                ahi[0] = Hhi[(m0 + gid)     * WSTR + kp0];
                ahi[1] = Hhi[(m0 + gid + 8) * WSTR + kp0];
                ahi[2] = Hhi[(m0 + gid)     * WSTR + kp0 + 4];
                ahi[3] = Hhi[(m0 + gid + 8) * WSTR + kp0 + 4];

                uint32_t bh[8][2];
#pragma unroll
                for (int nt = 0; nt < 8; nt++) {
                    const int c = cn0 + nt * 8 + gid;
                    bh[nt][0] = Whi[c * WSTR + kp0];
                    bh[nt][1] = Whi[c * WSTR + kp0 + 4];
                    mma_f16(d[nt], ahi, bh[nt][0], bh[nt][1]);   // hi . Whi
                }
                if (exact) {
                    uint32_t alo[4];
                    alo[0] = Hlo[(m0 + gid)     * WSTR + kp0];
                    alo[1] = Hlo[(m0 + gid + 8) * WSTR + kp0];
                    alo[2] = Hlo[(m0 + gid)     * WSTR + kp0 + 4];
                    alo[3] = Hlo[(m0 + gid + 8) * WSTR + kp0 + 4];
#pragma unroll
                    for (int nt = 0; nt < 8; nt++)
                        mma_f16(d[nt], alo, bh[nt][0], bh[nt][1]);  // lo . Whi
#pragma unroll
                    for (int nt = 0; nt < 8; nt++) {
                        const int c = cn0 + nt * 8 + gid;
                        uint32_t bl0 = Wlo[c * WSTR + kp0];
                        uint32_t bl1 = Wlo[c * WSTR + kp0 + 4];
                        mma_f16(d[nt], ahi, bl0, bl1);              // hi . Wlo
                    }
                }
            }
        }
        __syncthreads();   // all reads of H done before rewrite

        // ---- epilogue: 2-shfl quad-exchange, + tokgate, LSTM cell (MUFU), store ----
        const int tv = tok[row * SEQ + t];
        const float* tgrow = g_tokgate + tv * NG;
        const bool e = (tig & 1) == 0;

#pragma unroll
        for (int nt = 0; nt < 8; nt++) {
            float x0 = e ? d[nt][2] : d[nt][0];
            float x1 = e ? d[nt][3] : d[nt][1];
            float s0 = __shfl_xor_sync(0xffffffffu, x0, 1);
            float s1 = __shfl_xor_sync(0xffffffffu, x1, 1);
            float ig = e ? d[nt][0] : s0;
            float fg = e ? d[nt][1] : s1;
            float gg = e ? s0 : d[nt][2];
            float og = e ? s1 : d[nt][3];
            const int u = nb * 16 + nt * 2 + upair;
            float4 tgv = *(const float4*)(tgrow + 4 * u);
            ig += tgv.x; fg += tgv.y; gg += tgv.z; og += tgv.w;
            float cb = fsig(fg) * c_reg[nt] + fsig(ig) * ftanh(gg);
            float h = fsig(og) * ftanh(cb);
            c_reg[nt] = cb;
            __half hh = __float2half_rn(h);
            HHIh[row * (2 * WSTR) + u] = hh;
            HLOh[row * (2 * WSTR) + u] = __float2half_rn(h - __half2float(hh));
            if (t == SEQ - 1) hout[(base + row) * RNN + u] = h;
        }
        __syncthreads();
    }
}

// ================= heads kernel (dialog-split: grid.y = 0/1) =================
#define HW_WC   0
#define HW_BC   (HW_WC + 192)
#define HW_WS   (HW_BC + 4)
#define HW_BS   (HW_WS + 192)
#define HW_WL   (HW_BS + 4)
#define HW_BL   (HW_WL + 1600)
#define HW_WP   (HW_BL + 28)
#define HW_BP   (HW_WP + 512)
#define HW_WR1  (HW_BP + 8)
#define HW_BR1  (HW_WR1 + 2176)
#define HW_WR2  (HW_BR1 + 32)
#define HW_BR2  (HW_WR2 + 32)
#define HW_HB   (HW_BR2 + 4)
#define HEADS_SMEM_FLOATS (HW_HB + HT * 65)
#define HEADS_SMEM_BYTES  (HEADS_SMEM_FLOATS * 4)

__device__ const int c_offx[8] = {-1, 1, 0, 0, -1, -1, 1, 1};
__device__ const int c_offy[8] = {0, 0, 1, -1, -1, 1, -1, 1};

template <int V>
__device__ __forceinline__ int sample_lp(const float* lg, uint32_t k0, uint32_t k1,
                                         int b, float& lp) {
    const uint32_t half = (uint32_t)(BN * V / 2);
    int best = 0;
    float bestz = -1e30f, bestl = lg[0], m = -1e30f;
#pragma unroll
    for (int v = 0; v < V; v++) {
        float z = lg[v] + jax_gumbel(k0, k1, (uint32_t)(b * V + v), half);
        if (z > bestz) { bestz = z; best = v; bestl = lg[v]; }
        m = fmaxf(m, lg[v]);
    }
    float ssum = 0.f;
#pragma unroll
    for (int v = 0; v < V; v++) ssum += expf(lg[v] - m);
    lp = (bestl - m) - logf(ssum);
    return best;
}

__global__ void __launch_bounds__(HT)
heads_kernel(const int* __restrict__ canvas0, const int* __restrict__ canvas1,
             const int* __restrict__ refp,
             const float* __restrict__ Wc, const float* __restrict__ bc,
             const float* __restrict__ Ws, const float* __restrict__ bs,
             const float* __restrict__ Wl, const float* __restrict__ bl,
             const float* __restrict__ Wr1, const float* __restrict__ br1,
             const float* __restrict__ Wr2, const float* __restrict__ br2,
             const float* __restrict__ Wp, const float* __restrict__ bp,
             float* __restrict__ out, Keys keys) {
    extern __shared__ float sm[];
    const int tid = threadIdx.x;
    const int b = blockIdx.x * HT + tid;
    const int tile = blockIdx.x * HT;
    const int dialog = blockIdx.y;

    for (int i = tid; i < 192;  i += HT) sm[HW_WC + i] = Wc[i];
    for (int i = tid; i < 192;  i += HT) sm[HW_WS + i] = Ws[i];
    if (tid < 3)  sm[HW_BC + tid]  = bc[tid];
    if (tid < 3)  sm[HW_BS + tid]  = bs[tid];
    if (dialog == 0) {
        for (int i = tid; i < 1600; i += HT) sm[HW_WL + i] = Wl[i];
        if (tid < 25) sm[HW_BL + tid]  = bl[tid];
    } else {
        for (int i = tid; i < 512;  i += HT) sm[HW_WP + i] = Wp[i];
        for (int i = tid; i < 2176; i += HT) sm[HW_WR1 + i] = Wr1[i];
        if (tid < 8)  sm[HW_BP + tid]  = bp[tid];
        if (tid < 32) sm[HW_BR1 + tid] = br1[tid];
        if (tid < 32) sm[HW_WR2 + tid] = Wr2[tid];
        if (tid == 0) sm[HW_BR2] = br2[0];
    }

    float* hb = sm + HW_HB;
    for (int i = tid; i < HT * RNN; i += HT) {
        int s = i >> 6, k = i & 63;
        hb[s * 65 + k] = g_h[dialog * (BN * RNN) + (tile + s) * RNN + k];
    }
    __syncthreads();

    const float* h = hb + tid * 65;

    float lc[3], lsh[3];
#pragma unroll
    for (int r = 0; r < 3; r++) {
        float d = 0.f, ee = 0.f;
        for (int k = 0; k < 64; k++) {
            d = fmaf(h[k], sm[HW_WC + r * 64 + k], d);
            ee = fmaf(h[k], sm[HW_WS + r * 64 + k], ee);
        }
        lc[r] = d + sm[HW_BC + r];
        lsh[r] = ee + sm[HW_BS + r];
    }

    if (dialog == 0) {
        float ll[25];
#pragma unroll 5
        for (int r = 0; r < 25; r++) {
            float d = 0.f;
            for (int k = 0; k < 64; k++) d = fmaf(h[k], sm[HW_WL + r * 64 + k], d);
            ll[r] = d + sm[HW_BL + r];
        }
        float clp0, slp0, llp0;
        int cs0  = sample_lp<3>(lc,  keys.a[0], keys.b[0], b, clp0);
        sample_lp<3>(lsh, keys.a[1], keys.b[1], b, slp0);
        int loc0 = sample_lp<25>(ll, keys.a[2], keys.b[2], b, llp0);

        int lclip = min(max(loc0, 0), 24);
        int4 pt = *(const int4*)(canvas1 + (b * 25 + lclip) * 4);
        bool ok0 = (loc0 >= 0) && (loc0 < 25) && ((pt.x + pt.y + pt.z + pt.w) >= 0);
        float loc_r0 = ok0 ? 1.f : -1.f;
        float col_r0 = ok0 ? ((cs0 == pt.x) ? 1.f : -1.f) : 0.f;

        out[0 * BN + b] = clp0;
        out[1 * BN + b] = slp0;
        out[2 * BN + b] = llp0;
        out[(7 + 0) * BN + b] = loc_r0;
        out[(7 + 1) * BN + b] = col_r0;
        out[(7 + 2) * BN + b] = loc_r0;
    } else {
        float lp8[8];
#pragma unroll 4
        for (int r = 0; r < 8; r++) {
            float d = 0.f;
            for (int k = 0; k < 64; k++) d = fmaf(h[k], sm[HW_WP + r * 64 + k], d);
            lp8[r] = d + sm[HW_BP + r];
        }
        float clp1, slp1, llp1, alp1;
        int cs1 = sample_lp<3>(lc,  keys.a[3], keys.b[3], b, clp1);
        sample_lp<3>(lsh, keys.a[4], keys.b[4], b, slp1);
        int ls1 = sample_lp<8>(lp8, keys.a[5], keys.b[5], b, llp1);

        float pre[32];
#pragma unroll 8
        for (int j = 0; j < 32; j++) {
            float d = 0.f;
            for (int k = 0; k < 64; k++) d = fmaf(h[k], sm[HW_WR1 + j * 68 + k], d);
            pre[j] = d + sm[HW_BR1 + j];
        }
        float al[25];
#pragma unroll
        for (int loc = 0; loc < 25; loc++) {
            int4 cv = *(const int4*)(canvas0 + (b * 25 + loc) * 4);
            float cx = (float)cv.x, cy = (float)cv.y, cz = (float)cv.z, cw = (float)cv.w;
            float a = sm[HW_BR2];
#pragma unroll
            for (int j = 0; j < 32; j++) {
                float v = pre[j];
                v = fmaf(cx, sm[HW_WR1 + j * 68 + 64], v);
                v = fmaf(cy, sm[HW_WR1 + j * 68 + 65], v);
                v = fmaf(cz, sm[HW_WR1 + j * 68 + 66], v);
                v = fmaf(cw, sm[HW_WR1 + j * 68 + 67], v);
                v = fmaxf(v, 0.f);
                a = fmaf(v, sm[HW_WR2 + j], a);
            }
            al[loc] = a;
        }
        int att = sample_lp<25>(al, keys.a[6], keys.b[6], b, alp1);

        int4 ro = *(const int4*)(canvas0 + (b * 25 + att) * 4);
        int4 rf = *(const int4*)(refp + b * 4);
        float att_rew = (ro.x == rf.x && ro.y == rf.y && ro.z == rf.z && ro.w == rf.w)
                            ? 1.f : -1.f;
        int loc1 = (ro.z + c_offx[ls1]) * 5 + (ro.w + c_offy[ls1]);
        int l1c = min(max(loc1, 0), 24);
        int4 pt1 = *(const int4*)(canvas1 + (b * 25 + l1c) * 4);
        bool ok1 = (loc1 >= 0) && (loc1 < 25) && ((pt1.x + pt1.y + pt1.z + pt1.w) >= 0);
        float loc_r1 = ok1 ? 1.f : -1.f;
        float col_r1 = ok1 ? ((cs1 == pt1.x) ? 1.f : -1.f) : 0.f;

        out[3 * BN + b] = clp1;
        out[4 * BN + b] = slp1;
        out[5 * BN + b] = llp1;
        out[6 * BN + b] = alp1;
        out[(7 + 3) * BN + b] = loc_r1;
        out[(7 + 4) * BN + b] = col_r1;
        out[(7 + 5) * BN + b] = loc_r1;
        out[(7 + 6) * BN + b] = att_rew;
    }
}

// ================= launch =================
extern "C" void kernel_launch(void* const* d_in, const int* in_sizes, int n_in,
                              void* d_out, int out_size) {
    const int*   inst0   = (const int*)d_in[0];
    const int*   inst1   = (const int*)d_in[1];
    const int*   canvas0 = (const int*)d_in[2];
    const int*   canvas1 = (const int*)d_in[3];
    const int*   refp    = (const int*)d_in[4];
    const float* embed   = (const float*)d_in[5];
    const float* W_ih    = (const float*)d_in[6];
    const float* W_hh    = (const float*)d_in[7];
    const float* b_ih    = (const float*)d_in[8];
    const float* b_hh    = (const float*)d_in[9];
    const float* Wc      = (const float*)d_in[10];
    const float* bc      = (const float*)d_in[11];
    const float* Ws      = (const float*)d_in[12];
    const float* bs      = (const float*)d_in[13];
    const float* Wl      = (const float*)d_in[14];
    const float* bl      = (const float*)d_in[15];
    const float* Wr1     = (const float*)d_in[16];
    const float* br1     = (const float*)d_in[17];
    const float* Wr2     = (const float*)d_in[18];
    const float* br2     = (const float*)d_in[19];
    const float* Wp      = (const float*)d_in[20];
    const float* bp      = (const float*)d_in[21];

    Keys keys;
#if THREEFRY_PARTITIONABLE
    for (int i = 0; i < 7; i++)
        threefry2x32(0u, 42u, 0u, (uint32_t)i, keys.a[i], keys.b[i]);
#else
    uint32_t o[14];
    for (int i = 0; i < 7; i++)
        threefry2x32(0u, 42u, (uint32_t)i, (uint32_t)(i + 7), o[i], o[7 + i]);
    for (int i = 0; i < 7; i++) { keys.a[i] = o[2 * i]; keys.b[i] = o[2 * i + 1]; }
#endif

    cudaFuncSetAttribute(lstm_kernel, cudaFuncAttributeMaxDynamicSharedMemorySize,
                         LSTM_SMEM_BYTES);
    cudaFuncSetAttribute(heads_kernel, cudaFuncAttributeMaxDynamicSharedMemorySize,
                         HEADS_SMEM_BYTES);

    tokgate_kernel<<<(VOCAB + 7) / 8, 256>>>(embed, W_ih, b_ih, b_hh);
    lstm_kernel<<<dim3(BN / TBM, 2), 256, LSTM_SMEM_BYTES>>>(inst0, inst1, W_hh);
    heads_kernel<<<dim3(BN / HT, 2), HT, HEADS_SMEM_BYTES>>>(
        canvas0, canvas1, refp, Wc, bc, Ws, bs, Wl, bl, Wr1, br1, Wr2, br2,
        Wp, bp, (float*)d_out, keys);
}

// round 12
// speedup vs baseline: 6.1644x; 1.1315x over previous
#include <cuda_runtime.h>
#include <cuda_fp16.h>
#include <cstdint>

#define BN 16384
#define SEQ 32
#define RNN 64
#define NG 256
#define VOCAB 1001
#define TBM 32             // samples per LSTM CTA
#define HT 64              // heads threads per block
#define EXACT_FROM 26      // steps >= this use full 3-product compensation
#define THREEFRY_PARTITIONABLE 1

typedef unsigned long long u64;

__device__ float g_h[2 * BN * RNN];
__device__ float g_tokgate[VOCAB * NG];
// Wlo B-fragments, pre-swizzled for coalesced warp loads:
// index ((nb*4+kt)*8+nt)*32 + lane ; .x = pack(lo(w[k0]),lo(w[k0+1])) at kp0, .y at kp0+4
__device__ uint2 g_WloF[4 * 4 * 8 * 32];

// ================= threefry2x32 (exact JAX algorithm) =================
__host__ __device__ __forceinline__ uint32_t rotl32(uint32_t x, int d) {
    return (x << d) | (x >> (32 - d));
}
__host__ __device__ __forceinline__ void threefry2x32(uint32_t k0, uint32_t k1,
                                                      uint32_t c0, uint32_t c1,
                                                      uint32_t& o0, uint32_t& o1) {
    uint32_t ks2 = k0 ^ k1 ^ 0x1BD11BDAu;
    uint32_t x0 = c0 + k0, x1 = c1 + k1;
#define TF_R4(a,b,c,d) \
    x0 += x1; x1 = rotl32(x1,a); x1 ^= x0; \
    x0 += x1; x1 = rotl32(x1,b); x1 ^= x0; \
    x0 += x1; x1 = rotl32(x1,c); x1 ^= x0; \
    x0 += x1; x1 = rotl32(x1,d); x1 ^= x0;
    TF_R4(13,15,26,6);  x0 += k1;  x1 += ks2 + 1u;
    TF_R4(17,29,16,24); x0 += ks2; x1 += k0  + 2u;
    TF_R4(13,15,26,6);  x0 += k0;  x1 += k1  + 3u;
    TF_R4(17,29,16,24); x0 += k1;  x1 += ks2 + 4u;
    TF_R4(13,15,26,6);  x0 += ks2; x1 += k0  + 5u;
#undef TF_R4
    o0 = x0; o1 = x1;
}

struct Keys { uint32_t a[7]; uint32_t b[7]; };

__device__ __forceinline__ uint32_t jax_bits32(uint32_t k0, uint32_t k1,
                                               uint32_t idx, uint32_t half) {
#if THREEFRY_PARTITIONABLE
    uint32_t y0, y1;
    threefry2x32(k0, k1, 0u, idx, y0, y1);
    return y0 ^ y1;
#else
    uint32_t p = (idx < half) ? idx : idx - half;
    uint32_t y0, y1;
    threefry2x32(k0, k1, p, p + half, y0, y1);
    return (idx < half) ? y0 : y1;
#endif
}
__device__ __forceinline__ float jax_gumbel(uint32_t k0, uint32_t k1,
                                            uint32_t idx, uint32_t half) {
    uint32_t bits = jax_bits32(k0, k1, idx, half);
    float f = __uint_as_float((bits >> 9) | 0x3f800000u) - 1.0f;
    f = fmaxf(f, 1.17549435e-38f);
    return -logf(-logf(f));
}
__device__ __forceinline__ float sigf(float x) {
    return fmaf(0.5f, tanhf(0.5f * x), 0.5f);   // exact path (heads)
}

// ---- MUFU-based fast activations (LSTM epilogue only) ----
__device__ __forceinline__ float fsig(float x) {
    return __fdividef(1.0f, 1.0f + __expf(-x));
}
__device__ __forceinline__ float ftanh(float x) {
    float xc = fminf(fmaxf(x, -12.0f), 12.0f);
    float t = __expf(2.0f * xc);
    return __fdividef(t - 1.0f, t + 1.0f);
}

// mma.sync m16n8k16 f16 (baseline PTX)
__device__ __forceinline__ void mma_f16(float d[4], const uint32_t a[4],
                                        uint32_t b0, uint32_t b1) {
    asm volatile(
        "mma.sync.aligned.m16n8k16.row.col.f32.f16.f16.f32 "
        "{%0,%1,%2,%3}, {%4,%5,%6,%7}, {%8,%9}, {%0,%1,%2,%3};"
        : "+f"(d[0]), "+f"(d[1]), "+f"(d[2]), "+f"(d[3])
        : "r"(a[0]), "r"(a[1]), "r"(a[2]), "r"(a[3]), "r"(b0), "r"(b1));
}

__device__ __forceinline__ uint32_t pack_h2(__half lo_h, __half hi_h) {
    __half2 h2 = __halves2half2(lo_h, hi_h);
    return *(uint32_t*)&h2;
}

// ================= tokgate precompute =================
__global__ void __launch_bounds__(256)
tokgate_kernel(const float* __restrict__ embed, const float* __restrict__ W_ih,
               const float* __restrict__ b_ih, const float* __restrict__ b_hh) {
    __shared__ float e[8][64];
    const int v0 = blockIdx.x * 8;
    const int tid = threadIdx.x;
    for (int i = tid; i < 8 * 64; i += 256) {
        int vv = v0 + (i >> 6);
        e[i >> 6][i & 63] = (vv < VOCAB) ? embed[vv * 64 + (i & 63)] : 0.f;
    }
    __syncthreads();
    const int c = tid, gg = c & 3, u = c >> 2;
    const int row = gg * 64 + u;
    float wreg[64];
    const float4* wp = (const float4*)(W_ih + row * 64);
#pragma unroll
    for (int i = 0; i < 16; i++) {
        float4 w4 = wp[i];
        wreg[4 * i] = w4.x; wreg[4 * i + 1] = w4.y;
        wreg[4 * i + 2] = w4.z; wreg[4 * i + 3] = w4.w;
    }
    const float bias = b_ih[row] + b_hh[row];
#pragma unroll
    for (int j = 0; j < 8; j++) {
        int v = v0 + j;
        if (v >= VOCAB) break;
        float d = bias;
#pragma unroll
        for (int k = 0; k < 64; k++) d = fmaf(e[j][k], wreg[k], d);
        g_tokgate[v * NG + c] = d;
    }
}

// ================= Wlo fragment table precompute =================
// lane = gid*4+tig; c = nb*64+nt*8+gid; kp0 = kt*8+tig; value halves k=2kp..
__global__ void __launch_bounds__(256)
wlof_kernel(const float* __restrict__ W_hh) {
    int idx = blockIdx.x * 256 + threadIdx.x;   // 0..4095
    int lane = idx & 31, nt = (idx >> 5) & 7, kt = (idx >> 8) & 3, nb = (idx >> 10) & 3;
    int gid = lane >> 2, tig = lane & 3;
    int c = nb * 64 + nt * 8 + gid;
    int cnb = c >> 6, cnt = (c >> 3) & 7, cup = (c >> 2) & 1, cg = c & 3;
    int u = cnb * 16 + cnt * 2 + cup;
    const float* wr = W_hh + (cg * 64 + u) * 64;
    uint2 v;
    {
        int kp = kt * 8 + tig;
        float w0 = wr[2 * kp], w1 = wr[2 * kp + 1];
        __half h0 = __float2half_rn(w0), h1 = __float2half_rn(w1);
        v.x = pack_h2(__float2half_rn(w0 - __half2float(h0)),
                      __float2half_rn(w1 - __half2float(h1)));
    }
    {
        int kp = kt * 8 + tig + 4;
        float w0 = wr[2 * kp], w1 = wr[2 * kp + 1];
        __half h0 = __float2half_rn(w0), h1 = __float2half_rn(w1);
        v.y = pack_h2(__float2half_rn(w0 - __half2float(h0)),
                      __float2half_rn(w1 - __half2float(h1)));
    }
    g_WloF[idx] = v;
}

// ================= LSTM kernel =================
// smem words: Whi[256][36] @0 (9216) | H bufs @9216: [buf][hi/lo][32][36] (4*1152)
//             tok[32][32] @13824 (1024)  -> 59392 B, 3 CTAs/SM
#define WSTR 36
#define OFF_WHI 0
#define OFF_H   (256 * WSTR)
#define OFF_TOK (OFF_H + 4 * TBM * WSTR)
#define LSTM_SMEM_WORDS (OFF_TOK + TBM * SEQ)
#define LSTM_SMEM_BYTES (LSTM_SMEM_WORDS * 4)
// column order: c' = nb*64 + nt*8 + 4*up + g ; unit u = nb*16 + nt*2 + up

__global__ void __launch_bounds__(256, 3)
lstm_kernel(const int* __restrict__ inst0, const int* __restrict__ inst1,
            const float* __restrict__ W_hh) {
    extern __shared__ uint32_t smw[];
    uint32_t* Whi = smw + OFF_WHI;
    int*      tok = (int*)(smw + OFF_TOK);    // [s][t]

    const int tid  = threadIdx.x;
    const int wid  = tid >> 5, lane = tid & 31;
    const int gid  = lane >> 2, tig = lane & 3;
    const int mb   = wid & 1;
    const int nb   = wid >> 1;
    const int base = blockIdx.x * TBM;
    const int* inst = (blockIdx.y == 0) ? inst0 : inst1;
    float* hout = g_h + blockIdx.y * (BN * RNN);

    // ---- stage W_hh hi-part into smem (permuted column order, packed k-pairs) ----
    for (int idx = tid; idx < NG * 32; idx += 256) {
        int c = idx >> 5, kp = idx & 31;
        int cnb = c >> 6, cnt = (c >> 3) & 7, cup = (c >> 2) & 1, cg = c & 3;
        int u = cnb * 16 + cnt * 2 + cup;
        const float* wr = W_hh + (cg * 64 + u) * 64 + 2 * kp;
        Whi[c * WSTR + kp] = pack_h2(__float2half_rn(wr[0]), __float2half_rn(wr[1]));
    }
    for (int idx = tid; idx < TBM * SEQ; idx += 256)
        tok[idx] = inst[base * SEQ + idx];
    __syncthreads();

    const int row   = mb * 16 + gid + 8 * (tig & 1);
    const int upair = tig >> 1;
    const int m0    = mb * 16;
    const int cn0   = nb * 64;
    float c_reg[8];
#pragma unroll
    for (int i = 0; i < 8; i++) c_reg[i] = 0.f;

    for (int t = 0; t < SEQ; t++) {
        // buffers: MMA reads buf[t&1], epilogue writes buf[(t+1)&1]
        uint32_t* Hr_hi = smw + OFF_H + (t & 1) * (2 * TBM * WSTR);
        uint32_t* Hr_lo = Hr_hi + TBM * WSTR;
        uint32_t* Hw_hi = smw + OFF_H + ((t + 1) & 1) * (2 * TBM * WSTR);
        uint32_t* Hw_lo = Hw_hi + TBM * WSTR;
        __half* HWh = (__half*)Hw_hi;
        __half* HWl = (__half*)Hw_lo;

        // ---- prefetch tokgate row (hides L2 latency behind the MMA phase) ----
        const int tv = tok[row * SEQ + t];
        const float4* tgp = (const float4*)(g_tokgate + tv * NG);

        float d[8][4];
#pragma unroll
        for (int nt = 0; nt < 8; nt++)
#pragma unroll
            for (int j = 0; j < 4; j++) d[nt][j] = 0.f;

        float4 tg0 = tgp[4 * (nb * 4 + upair)];          // units nb*16+... prefetch 2 of 8 rows
        // (full prefetch of all 8 unit rows costs 32 regs; fetch per-nt below instead,
        //  issued early here for the first iterations)
        float4 tg1 = tgp[4 * (nb * 4 + upair) + 2];

        if (t > 0) {   // h_{-1} = 0: gates at t=0 are tokgate only
            const bool exact = (t >= EXACT_FROM);
#pragma unroll
            for (int kt = 0; kt < 4; kt++) {
                const int kp0 = kt * 8 + tig;
                uint32_t ahi[4];
                ahi[0] = Hr_hi[(m0 + gid)     * WSTR + kp0];
                ahi[1] = Hr_hi[(m0 + gid + 8) * WSTR + kp0];
                ahi[2] = Hr_hi[(m0 + gid)     * WSTR + kp0 + 4];
                ahi[3] = Hr_hi[(m0 + gid + 8) * WSTR + kp0 + 4];

                uint32_t bh[8][2];
#pragma unroll
                for (int nt = 0; nt < 8; nt++) {
                    const int c = cn0 + nt * 8 + gid;
                    bh[nt][0] = Whi[c * WSTR + kp0];
                    bh[nt][1] = Whi[c * WSTR + kp0 + 4];
                    mma_f16(d[nt], ahi, bh[nt][0], bh[nt][1]);   // hi . Whi
                }
                if (exact) {
                    uint32_t alo[4];
                    alo[0] = Hr_lo[(m0 + gid)     * WSTR + kp0];
                    alo[1] = Hr_lo[(m0 + gid + 8) * WSTR + kp0];
                    alo[2] = Hr_lo[(m0 + gid)     * WSTR + kp0 + 4];
                    alo[3] = Hr_lo[(m0 + gid + 8) * WSTR + kp0 + 4];
#pragma unroll
                    for (int nt = 0; nt < 8; nt++)
                        mma_f16(d[nt], alo, bh[nt][0], bh[nt][1]);  // lo . Whi
                    const uint2* wlo = g_WloF + ((nb * 4 + kt) * 8) * 32 + lane;
#pragma unroll
                    for (int nt = 0; nt < 8; nt++) {
                        uint2 bl = wlo[nt * 32];                    // coalesced LDG.64
                        mma_f16(d[nt], ahi, bl.x, bl.y);            // hi . Wlo
                    }
                }
            }
        }

        // ---- epilogue: 2-shfl quad-exchange, + tokgate, LSTM cell (MUFU), store ----
        const bool e = (tig & 1) == 0;
        const bool store_lo = (t >= EXACT_FROM - 1);   // lo only read by exact steps

#pragma unroll
        for (int nt = 0; nt < 8; nt++) {
            float x0 = e ? d[nt][2] : d[nt][0];
            float x1 = e ? d[nt][3] : d[nt][1];
            float s0 = __shfl_xor_sync(0xffffffffu, x0, 1);
            float s1 = __shfl_xor_sync(0xffffffffu, x1, 1);
            float ig = e ? d[nt][0] : s0;
            float fg = e ? d[nt][1] : s1;
            float gg = e ? s0 : d[nt][2];
            float og = e ? s1 : d[nt][3];
            const int u = nb * 16 + nt * 2 + upair;
            float4 tgv = (nt == 0) ? tg0 : ((nt == 2) ? tg1 : tgp[4 * (nb * 4 + upair) + 2 * (nt & 1) + (nt >> 1) * 0 + nt]);
            // NOTE: tgv indexing must match u = nb*16 + nt*2 + upair -> row 4*u..:
            tgv = tgp[u];
            ig += tgv.x; fg += tgv.y; gg += tgv.z; og += tgv.w;
            float cb = fsig(fg) * c_reg[nt] + fsig(ig) * ftanh(gg);
            float h = fsig(og) * ftanh(cb);
            c_reg[nt] = cb;
            __half hh = __float2half_rn(h);
            HWh[row * (2 * WSTR) + u] = hh;
            if (store_lo)
                HWl[row * (2 * WSTR) + u] = __float2half_rn(h - __half2float(hh));
            if (t == SEQ - 1) hout[(base + row) * RNN + u] = h;
        }
        __syncthreads();   // single barrier per step (double-buffered H)
    }
}

// ================= heads kernel (dialog-split: grid.y = 0/1) =================
#define HW_WC   0
#define HW_BC   (HW_WC + 192)
#define HW_WS   (HW_BC + 4)
#define HW_BS   (HW_WS + 192)
#define HW_WL   (HW_BS + 4)
#define HW_BL   (HW_WL + 1600)
#define HW_WP   (HW_BL + 28)
#define HW_BP   (HW_WP + 512)
#define HW_WR1  (HW_BP + 8)
#define HW_BR1  (HW_WR1 + 2176)
#define HW_WR2  (HW_BR1 + 32)
#define HW_BR2  (HW_WR2 + 32)
#define HW_HB   (HW_BR2 + 4)
#define HEADS_SMEM_FLOATS (HW_HB + HT * 65)
#define HEADS_SMEM_BYTES  (HEADS_SMEM_FLOATS * 4)

__device__ const int c_offx[8] = {-1, 1, 0, 0, -1, -1, 1, 1};
__device__ const int c_offy[8] = {0, 0, 1, -1, -1, 1, -1, 1};

template <int V>
__device__ __forceinline__ int sample_lp(const float* lg, uint32_t k0, uint32_t k1,
                                         int b, float& lp) {
    const uint32_t half = (uint32_t)(BN * V / 2);
    int best = 0;
    float bestz = -1e30f, bestl = lg[0], m = -1e30f;
#pragma unroll
    for (int v = 0; v < V; v++) {
        float z = lg[v] + jax_gumbel(k0, k1, (uint32_t)(b * V + v), half);
        if (z > bestz) { bestz = z; best = v; bestl = lg[v]; }
        m = fmaxf(m, lg[v]);
    }
    float ssum = 0.f;
#pragma unroll
    for (int v = 0; v < V; v++) ssum += expf(lg[v] - m);
    lp = (bestl - m) - logf(ssum);
    return best;
}

__global__ void __launch_bounds__(HT)
heads_kernel(const int* __restrict__ canvas0, const int* __restrict__ canvas1,
             const int* __restrict__ refp,
             const float* __restrict__ Wc, const float* __restrict__ bc,
             const float* __restrict__ Ws, const float* __restrict__ bs,
             const float* __restrict__ Wl, const float* __restrict__ bl,
             const float* __restrict__ Wr1, const float* __restrict__ br1,
             const float* __restrict__ Wr2, const float* __restrict__ br2,
             const float* __restrict__ Wp, const float* __restrict__ bp,
             float* __restrict__ out, Keys keys) {
    extern __shared__ float sm[];
    const int tid = threadIdx.x;
    const int b = blockIdx.x * HT + tid;
    const int tile = blockIdx.x * HT;
    const int dialog = blockIdx.y;

    for (int i = tid; i < 192;  i += HT) sm[HW_WC + i] = Wc[i];
    for (int i = tid; i < 192;  i += HT) sm[HW_WS + i] = Ws[i];
    if (tid < 3)  sm[HW_BC + tid]  = bc[tid];
    if (tid < 3)  sm[HW_BS + tid]  = bs[tid];
    if (dialog == 0) {
        for (int i = tid; i < 1600; i += HT) sm[HW_WL + i] = Wl[i];
        if (tid < 25) sm[HW_BL + tid]  = bl[tid];
    } else {
        for (int i = tid; i < 512;  i += HT) sm[HW_WP + i] = Wp[i];
        for (int i = tid; i < 2176; i += HT) sm[HW_WR1 + i] = Wr1[i];
        if (tid < 8)  sm[HW_BP + tid]  = bp[tid];
        if (tid < 32) sm[HW_BR1 + tid] = br1[tid];
        if (tid < 32) sm[HW_WR2 + tid] = Wr2[tid];
        if (tid == 0) sm[HW_BR2] = br2[0];
    }

    float* hb = sm + HW_HB;
    for (int i = tid; i < HT * RNN; i += HT) {
        int s = i >> 6, k = i & 63;
        hb[s * 65 + k] = g_h[dialog * (BN * RNN) + (tile + s) * RNN + k];
    }
    __syncthreads();

    const float* h = hb + tid * 65;

    float lc[3], lsh[3];
#pragma unroll
    for (int r = 0; r < 3; r++) {
        float d = 0.f, ee = 0.f;
        for (int k = 0; k < 64; k++) {
            d = fmaf(h[k], sm[HW_WC + r * 64 + k], d);
            ee = fmaf(h[k], sm[HW_WS + r * 64 + k], ee);
        }
        lc[r] = d + sm[HW_BC + r];
        lsh[r] = ee + sm[HW_BS + r];
    }

    if (dialog == 0) {
        float ll[25];
#pragma unroll 5
        for (int r = 0; r < 25; r++) {
            float d = 0.f;
            for (int k = 0; k < 64; k++) d = fmaf(h[k], sm[HW_WL + r * 64 + k], d);
            ll[r] = d + sm[HW_BL + r];
        }
        float clp0, slp0, llp0;
        int cs0  = sample_lp<3>(lc,  keys.a[0], keys.b[0], b, clp0);
        sample_lp<3>(lsh, keys.a[1], keys.b[1], b, slp0);
        int loc0 = sample_lp<25>(ll, keys.a[2], keys.b[2], b, llp0);

        int lclip = min(max(loc0, 0), 24);
        int4 pt = *(const int4*)(canvas1 + (b * 25 + lclip) * 4);
        bool ok0 = (loc0 >= 0) && (loc0 < 25) && ((pt.x + pt.y + pt.z + pt.w) >= 0);
        float loc_r0 = ok0 ? 1.f : -1.f;
        float col_r0 = ok0 ? ((cs0 == pt.x) ? 1.f : -1.f) : 0.f;

        out[0 * BN + b] = clp0;
        out[1 * BN + b] = slp0;
        out[2 * BN + b] = llp0;
        out[(7 + 0) * BN + b] = loc_r0;
        out[(7 + 1) * BN + b] = col_r0;
        out[(7 + 2) * BN + b] = loc_r0;
    } else {
        float lp8[8];
#pragma unroll 4
        for (int r = 0; r < 8; r++) {
            float d = 0.f;
            for (int k = 0; k < 64; k++) d = fmaf(h[k], sm[HW_WP + r * 64 + k], d);
            lp8[r] = d + sm[HW_BP + r];
        }
        float clp1, slp1, llp1, alp1;
        int cs1 = sample_lp<3>(lc,  keys.a[3], keys.b[3], b, clp1);
        sample_lp<3>(lsh, keys.a[4], keys.b[4], b, slp1);
        int ls1 = sample_lp<8>(lp8, keys.a[5], keys.b[5], b, llp1);

        float pre[32];
#pragma unroll 8
        for (int j = 0; j < 32; j++) {
            float d = 0.f;
            for (int k = 0; k < 64; k++) d = fmaf(h[k], sm[HW_WR1 + j * 68 + k], d);
            pre[j] = d + sm[HW_BR1 + j];
        }
        float al[25];
#pragma unroll
        for (int loc = 0; loc < 25; loc++) {
            int4 cv = *(const int4*)(canvas0 + (b * 25 + loc) * 4);
            float cx = (float)cv.x, cy = (float)cv.y, cz = (float)cv.z, cw = (float)cv.w;
            float a = sm[HW_BR2];
#pragma unroll
            for (int j = 0; j < 32; j++) {
                float v = pre[j];
                v = fmaf(cx, sm[HW_WR1 + j * 68 + 64], v);
                v = fmaf(cy, sm[HW_WR1 + j * 68 + 65], v);
                v = fmaf(cz, sm[HW_WR1 + j * 68 + 66], v);
                v = fmaf(cw, sm[HW_WR1 + j * 68 + 67], v);
                v = fmaxf(v, 0.f);
                a = fmaf(v, sm[HW_WR2 + j], a);
            }
            al[loc] = a;
        }
        int att = sample_lp<25>(al, keys.a[6], keys.b[6], b, alp1);

        int4 ro = *(const int4*)(canvas0 + (b * 25 + att) * 4);
        int4 rf = *(const int4*)(refp + b * 4);
        float att_rew = (ro.x == rf.x && ro.y == rf.y && ro.z == rf.z && ro.w == rf.w)
                            ? 1.f : -1.f;
        int loc1 = (ro.z + c_offx[ls1]) * 5 + (ro.w + c_offy[ls1]);
        int l1c = min(max(loc1, 0), 24);
        int4 pt1 = *(const int4*)(canvas1 + (b * 25 + l1c) * 4);
        bool ok1 = (loc1 >= 0) && (loc1 < 25) && ((pt1.x + pt1.y + pt1.z + pt1.w) >= 0);
        float loc_r1 = ok1 ? 1.f : -1.f;
        float col_r1 = ok1 ? ((cs1 == pt1.x) ? 1.f : -1.f) : 0.f;

        out[3 * BN + b] = clp1;
        out[4 * BN + b] = slp1;
        out[5 * BN + b] = llp1;
        out[6 * BN + b] = alp1;
        out[(7 + 3) * BN + b] = loc_r1;
        out[(7 + 4) * BN + b] = col_r1;
        out[(7 + 5) * BN + b] = loc_r1;
        out[(7 + 6) * BN + b] = att_rew;
    }
}

// ================= launch =================
extern "C" void kernel_launch(void* const* d_in, const int* in_sizes, int n_in,
                              void* d_out, int out_size) {
    const int*   inst0   = (const int*)d_in[0];
    const int*   inst1   = (const int*)d_in[1];
    const int*   canvas0 = (const int*)d_in[2];
    const int*   canvas1 = (const int*)d_in[3];
    const int*   refp    = (const int*)d_in[4];
    const float* embed   = (const float*)d_in[5];
    const float* W_ih    = (const float*)d_in[6];
    const float* W_hh    = (const float*)d_in[7];
    const float* b_ih    = (const float*)d_in[8];
    const float* b_hh    = (const float*)d_in[9];
    const float* Wc      = (const float*)d_in[10];
    const float* bc      = (const float*)d_in[11];
    const float* Ws      = (const float*)d_in[12];
    const float* bs      = (const float*)d_in[13];
    const float* Wl      = (const float*)d_in[14];
    const float* bl      = (const float*)d_in[15];
    const float* Wr1     = (const float*)d_in[16];
    const float* br1     = (const float*)d_in[17];
    const float* Wr2     = (const float*)d_in[18];
    const float* br2     = (const float*)d_in[19];
    const float* Wp      = (const float*)d_in[20];
    const float* bp      = (const float*)d_in[21];

    Keys keys;
#if THREEFRY_PARTITIONABLE
    for (int i = 0; i < 7; i++)
        threefry2x32(0u, 42u, 0u, (uint32_t)i, keys.a[i], keys.b[i]);
#else
    uint32_t o[14];
    for (int i = 0; i < 7; i++)
        threefry2x32(0u, 42u, (uint32_t)i, (uint32_t)(i + 7), o[i], o[7 + i]);
    for (int i = 0; i < 7; i++) { keys.a[i] = o[2 * i]; keys.b[i] = o[2 * i + 1]; }
#endif

    cudaFuncSetAttribute(lstm_kernel, cudaFuncAttributeMaxDynamicSharedMemorySize,
                         LSTM_SMEM_BYTES);
    cudaFuncSetAttribute(heads_kernel, cudaFuncAttributeMaxDynamicSharedMemorySize,
                         HEADS_SMEM_BYTES);

    tokgate_kernel<<<(VOCAB + 7) / 8, 256>>>(embed, W_ih, b_ih, b_hh);
    wlof_kernel<<<16, 256>>>(W_hh);
    lstm_kernel<<<dim3(BN / TBM, 2), 256, LSTM_SMEM_BYTES>>>(inst0, inst1, W_hh);
    heads_kernel<<<dim3(BN / HT, 2), HT, HEADS_SMEM_BYTES>>>(
        canvas0, canvas1, refp, Wc, bc, Ws, bs, Wl, bl, Wr1, br1, Wr2, br2,
        Wp, bp, (float*)d_out, keys);
}

// round 13
// speedup vs baseline: 6.5719x; 1.0661x over previous
#include <cuda_runtime.h>
#include <cuda_fp16.h>
#include <cstdint>

#define BN 16384
#define SEQ 32
#define RNN 64
#define NG 256
#define VOCAB 1001
#define TBM 32             // samples per LSTM CTA
#define HT 128             // heads: 2 threads per sample, 64 samples per block
#define EXACT_FROM 30      // steps >= this use full 3-product compensation
#define THREEFRY_PARTITIONABLE 1

typedef unsigned long long u64;

__device__ float g_h[2 * BN * RNN];
__device__ float g_tokgate[VOCAB * NG];
// Wlo B-fragments, pre-swizzled for coalesced warp loads:
// index ((nb*4+kt)*8+nt)*32 + lane
__device__ uint2 g_WloF[4 * 4 * 8 * 32];

// ================= threefry2x32 (exact JAX algorithm) =================
__host__ __device__ __forceinline__ uint32_t rotl32(uint32_t x, int d) {
    return (x << d) | (x >> (32 - d));
}
__host__ __device__ __forceinline__ void threefry2x32(uint32_t k0, uint32_t k1,
                                                      uint32_t c0, uint32_t c1,
                                                      uint32_t& o0, uint32_t& o1) {
    uint32_t ks2 = k0 ^ k1 ^ 0x1BD11BDAu;
    uint32_t x0 = c0 + k0, x1 = c1 + k1;
#define TF_R4(a,b,c,d) \
    x0 += x1; x1 = rotl32(x1,a); x1 ^= x0; \
    x0 += x1; x1 = rotl32(x1,b); x1 ^= x0; \
    x0 += x1; x1 = rotl32(x1,c); x1 ^= x0; \
    x0 += x1; x1 = rotl32(x1,d); x1 ^= x0;
    TF_R4(13,15,26,6);  x0 += k1;  x1 += ks2 + 1u;
    TF_R4(17,29,16,24); x0 += ks2; x1 += k0  + 2u;
    TF_R4(13,15,26,6);  x0 += k0;  x1 += k1  + 3u;
    TF_R4(17,29,16,24); x0 += k1;  x1 += ks2 + 4u;
    TF_R4(13,15,26,6);  x0 += ks2; x1 += k0  + 5u;
#undef TF_R4
    o0 = x0; o1 = x1;
}

struct Keys { uint32_t a[7]; uint32_t b[7]; };

__device__ __forceinline__ uint32_t jax_bits32(uint32_t k0, uint32_t k1,
                                               uint32_t idx, uint32_t half) {
#if THREEFRY_PARTITIONABLE
    uint32_t y0, y1;
    threefry2x32(k0, k1, 0u, idx, y0, y1);
    return y0 ^ y1;
#else
    uint32_t p = (idx < half) ? idx : idx - half;
    uint32_t y0, y1;
    threefry2x32(k0, k1, p, p + half, y0, y1);
    return (idx < half) ? y0 : y1;
#endif
}
__device__ __forceinline__ float jax_gumbel(uint32_t k0, uint32_t k1,
                                            uint32_t idx, uint32_t half) {
    uint32_t bits = jax_bits32(k0, k1, idx, half);
    float f = __uint_as_float((bits >> 9) | 0x3f800000u) - 1.0f;
    f = fmaxf(f, 1.17549435e-38f);
    return -logf(-logf(f));
}

// ---- MUFU-based fast activations (LSTM epilogue only) ----
__device__ __forceinline__ float fsig(float x) {
    return __fdividef(1.0f, 1.0f + __expf(-x));
}
__device__ __forceinline__ float ftanh(float x) {
    float xc = fminf(fmaxf(x, -12.0f), 12.0f);
    float t = __expf(2.0f * xc);
    return __fdividef(t - 1.0f, t + 1.0f);
}

// mma.sync m16n8k16 f16 (baseline PTX)
__device__ __forceinline__ void mma_f16(float d[4], const uint32_t a[4],
                                        uint32_t b0, uint32_t b1) {
    asm volatile(
        "mma.sync.aligned.m16n8k16.row.col.f32.f16.f16.f32 "
        "{%0,%1,%2,%3}, {%4,%5,%6,%7}, {%8,%9}, {%0,%1,%2,%3};"
        : "+f"(d[0]), "+f"(d[1]), "+f"(d[2]), "+f"(d[3])
        : "r"(a[0]), "r"(a[1]), "r"(a[2]), "r"(a[3]), "r"(b0), "r"(b1));
}

__device__ __forceinline__ uint32_t pack_h2(__half lo_h, __half hi_h) {
    __half2 h2 = __halves2half2(lo_h, hi_h);
    return *(uint32_t*)&h2;
}

// ================= tokgate precompute =================
__global__ void __launch_bounds__(256)
tokgate_kernel(const float* __restrict__ embed, const float* __restrict__ W_ih,
               const float* __restrict__ b_ih, const float* __restrict__ b_hh) {
    __shared__ float e[8][64];
    const int v0 = blockIdx.x * 8;
    const int tid = threadIdx.x;
    for (int i = tid; i < 8 * 64; i += 256) {
        int vv = v0 + (i >> 6);
        e[i >> 6][i & 63] = (vv < VOCAB) ? embed[vv * 64 + (i & 63)] : 0.f;
    }
    __syncthreads();
    const int c = tid, gg = c & 3, u = c >> 2;
    const int row = gg * 64 + u;
    float wreg[64];
    const float4* wp = (const float4*)(W_ih + row * 64);
#pragma unroll
    for (int i = 0; i < 16; i++) {
        float4 w4 = wp[i];
        wreg[4 * i] = w4.x; wreg[4 * i + 1] = w4.y;
        wreg[4 * i + 2] = w4.z; wreg[4 * i + 3] = w4.w;
    }
    const float bias = b_ih[row] + b_hh[row];
#pragma unroll
    for (int j = 0; j < 8; j++) {
        int v = v0 + j;
        if (v >= VOCAB) break;
        float d = bias;
#pragma unroll
        for (int k = 0; k < 64; k++) d = fmaf(e[j][k], wreg[k], d);
        g_tokgate[v * NG + c] = d;
    }
}

// ================= Wlo fragment table precompute =================
__global__ void __launch_bounds__(256)
wlof_kernel(const float* __restrict__ W_hh) {
    int idx = blockIdx.x * 256 + threadIdx.x;   // 0..4095
    int lane = idx & 31, nt = (idx >> 5) & 7, kt = (idx >> 8) & 3, nb = (idx >> 10) & 3;
    int gid = lane >> 2, tig = lane & 3;
    int c = nb * 64 + nt * 8 + gid;
    int cnb = c >> 6, cnt = (c >> 3) & 7, cup = (c >> 2) & 1, cg = c & 3;
    int u = cnb * 16 + cnt * 2 + cup;
    const float* wr = W_hh + (cg * 64 + u) * 64;
    uint2 v;
    {
        int kp = kt * 8 + tig;
        float w0 = wr[2 * kp], w1 = wr[2 * kp + 1];
        __half h0 = __float2half_rn(w0), h1 = __float2half_rn(w1);
        v.x = pack_h2(__float2half_rn(w0 - __half2float(h0)),
                      __float2half_rn(w1 - __half2float(h1)));
    }
    {
        int kp = kt * 8 + tig + 4;
        float w0 = wr[2 * kp], w1 = wr[2 * kp + 1];
        __half h0 = __float2half_rn(w0), h1 = __float2half_rn(w1);
        v.y = pack_h2(__float2half_rn(w0 - __half2float(h0)),
                      __float2half_rn(w1 - __half2float(h1)));
    }
    g_WloF[idx] = v;
}

// ================= LSTM kernel =================
#define WSTR 36
#define OFF_WHI 0
#define OFF_H   (256 * WSTR)
#define OFF_TOK (OFF_H + 4 * TBM * WSTR)
#define LSTM_SMEM_WORDS (OFF_TOK + TBM * SEQ)
#define LSTM_SMEM_BYTES (LSTM_SMEM_WORDS * 4)
// column order: c' = nb*64 + nt*8 + 4*up + g ; unit u = nb*16 + nt*2 + up

__global__ void __launch_bounds__(256, 3)
lstm_kernel(const int* __restrict__ inst0, const int* __restrict__ inst1,
            const float* __restrict__ W_hh) {
    extern __shared__ uint32_t smw[];
    uint32_t* Whi = smw + OFF_WHI;
    int*      tok = (int*)(smw + OFF_TOK);    // [s][t]

    const int tid  = threadIdx.x;
    const int wid  = tid >> 5, lane = tid & 31;
    const int gid  = lane >> 2, tig = lane & 3;
    const int mb   = wid & 1;
    const int nb   = wid >> 1;
    const int base = blockIdx.x * TBM;
    const int* inst = (blockIdx.y == 0) ? inst0 : inst1;
    float* hout = g_h + blockIdx.y * (BN * RNN);

    for (int idx = tid; idx < NG * 32; idx += 256) {
        int c = idx >> 5, kp = idx & 31;
        int cnb = c >> 6, cnt = (c >> 3) & 7, cup = (c >> 2) & 1, cg = c & 3;
        int u = cnb * 16 + cnt * 2 + cup;
        const float* wr = W_hh + (cg * 64 + u) * 64 + 2 * kp;
        Whi[c * WSTR + kp] = pack_h2(__float2half_rn(wr[0]), __float2half_rn(wr[1]));
    }
    for (int idx = tid; idx < TBM * SEQ; idx += 256)
        tok[idx] = inst[base * SEQ + idx];
    __syncthreads();

    const int row   = mb * 16 + gid + 8 * (tig & 1);
    const int upair = tig >> 1;
    const int m0    = mb * 16;
    const int cn0   = nb * 64;
    float c_reg[8];
#pragma unroll
    for (int i = 0; i < 8; i++) c_reg[i] = 0.f;

    for (int t = 0; t < SEQ; t++) {
        uint32_t* Hr_hi = smw + OFF_H + (t & 1) * (2 * TBM * WSTR);
        uint32_t* Hr_lo = Hr_hi + TBM * WSTR;
        uint32_t* Hw_hi = smw + OFF_H + ((t + 1) & 1) * (2 * TBM * WSTR);
        uint32_t* Hw_lo = Hw_hi + TBM * WSTR;
        __half* HWh = (__half*)Hw_hi;
        __half* HWl = (__half*)Hw_lo;

        const int tv = tok[row * SEQ + t];
        const float4* tgp = (const float4*)(g_tokgate + tv * NG);

        float d[8][4];
#pragma unroll
        for (int nt = 0; nt < 8; nt++)
#pragma unroll
            for (int j = 0; j < 4; j++) d[nt][j] = 0.f;

        if (t > 0) {
            const bool exact = (t >= EXACT_FROM);
#pragma unroll
            for (int kt = 0; kt < 4; kt++) {
                const int kp0 = kt * 8 + tig;
                uint32_t ahi[4];
                ahi[0] = Hr_hi[(m0 + gid)     * WSTR + kp0];
                ahi[1] = Hr_hi[(m0 + gid + 8) * WSTR + kp0];
                ahi[2] = Hr_hi[(m0 + gid)     * WSTR + kp0 + 4];
                ahi[3] = Hr_hi[(m0 + gid + 8) * WSTR + kp0 + 4];

                uint32_t bh[8][2];
#pragma unroll
                for (int nt = 0; nt < 8; nt++) {
                    const int c = cn0 + nt * 8 + gid;
                    bh[nt][0] = Whi[c * WSTR + kp0];
                    bh[nt][1] = Whi[c * WSTR + kp0 + 4];
                    mma_f16(d[nt], ahi, bh[nt][0], bh[nt][1]);   // hi . Whi
                }
                if (exact) {
                    uint32_t alo[4];
                    alo[0] = Hr_lo[(m0 + gid)     * WSTR + kp0];
                    alo[1] = Hr_lo[(m0 + gid + 8) * WSTR + kp0];
                    alo[2] = Hr_lo[(m0 + gid)     * WSTR + kp0 + 4];
                    alo[3] = Hr_lo[(m0 + gid + 8) * WSTR + kp0 + 4];
#pragma unroll
                    for (int nt = 0; nt < 8; nt++)
                        mma_f16(d[nt], alo, bh[nt][0], bh[nt][1]);  // lo . Whi
                    const uint2* wlo = g_WloF + ((nb * 4 + kt) * 8) * 32 + lane;
#pragma unroll
                    for (int nt = 0; nt < 8; nt++) {
                        uint2 bl = wlo[nt * 32];                    // coalesced LDG.64
                        mma_f16(d[nt], ahi, bl.x, bl.y);            // hi . Wlo
                    }
                }
            }
        }

        // ---- epilogue: 2-shfl quad-exchange, + tokgate, LSTM cell (MUFU), store ----
        const bool e = (tig & 1) == 0;
        const bool store_lo = (t >= EXACT_FROM - 1);

#pragma unroll
        for (int nt = 0; nt < 8; nt++) {
            float x0 = e ? d[nt][2] : d[nt][0];
            float x1 = e ? d[nt][3] : d[nt][1];
            float s0 = __shfl_xor_sync(0xffffffffu, x0, 1);
            float s1 = __shfl_xor_sync(0xffffffffu, x1, 1);
            float ig = e ? d[nt][0] : s0;
            float fg = e ? d[nt][1] : s1;
            float gg = e ? s0 : d[nt][2];
            float og = e ? s1 : d[nt][3];
            const int u = nb * 16 + nt * 2 + upair;
            float4 tgv = tgp[u];
            ig += tgv.x; fg += tgv.y; gg += tgv.z; og += tgv.w;
            float cb = fsig(fg) * c_reg[nt] + fsig(ig) * ftanh(gg);
            float h = fsig(og) * ftanh(cb);
            c_reg[nt] = cb;
            __half hh = __float2half_rn(h);
            HWh[row * (2 * WSTR) + u] = hh;
            if (store_lo)
                HWl[row * (2 * WSTR) + u] = __float2half_rn(h - __half2float(hh));
            if (t == SEQ - 1) hout[(base + row) * RNN + u] = h;
        }
        __syncthreads();
    }
}

// ================= heads kernel: 2 threads per sample =================
#define HW_WC   0
#define HW_BC   (HW_WC + 192)
#define HW_WS   (HW_BC + 4)
#define HW_BS   (HW_WS + 192)
#define HW_WL   (HW_BS + 4)
#define HW_BL   (HW_WL + 1600)
#define HW_WP   (HW_BL + 28)
#define HW_BP   (HW_WP + 512)
#define HW_WR1  (HW_BP + 8)
#define HW_BR1  (HW_WR1 + 2176)
#define HW_WR2  (HW_BR1 + 32)
#define HW_BR2  (HW_WR2 + 32)
#define HW_HB   (HW_BR2 + 4)
#define SPB 64   // samples per block
#define HEADS_SMEM_FLOATS (HW_HB + SPB * 65)
#define HEADS_SMEM_BYTES  (HEADS_SMEM_FLOATS * 4)

__device__ const int c_offx[8] = {-1, 1, 0, 0, -1, -1, 1, 1};
__device__ const int c_offy[8] = {0, 0, 1, -1, -1, 1, -1, 1};

// Pair-split categorical sample: this thread owns logits lg[0..vcnt) for
// global categories vbase..vbase+vcnt-1; partner (lane^1) owns the rest.
// Returns the combined argmax(logits+gumbel) and combined log_prob.
template <int MAXC>
__device__ __forceinline__ int sample_lp_pair(const float* lg, int vbase, int vcnt,
                                              int V, uint32_t k0, uint32_t k1,
                                              int b, float& lp) {
    const uint32_t half = (uint32_t)(BN * V / 2);
    float bestz = -1e30f, bestl = -1e30f, m = -1e30f;
    int bestv = 0;
#pragma unroll
    for (int i = 0; i < MAXC; i++) {
        if (i >= vcnt) break;
        int v = vbase + i;
        float z = lg[i] + jax_gumbel(k0, k1, (uint32_t)(b * V + v), half);
        if (z > bestz) { bestz = z; bestv = v; bestl = lg[i]; }
        m = fmaxf(m, lg[i]);
    }
    m = fmaxf(m, __shfl_xor_sync(0xffffffffu, m, 1));
    float ssum = 0.f;
#pragma unroll
    for (int i = 0; i < MAXC; i++) {
        if (i >= vcnt) break;
        ssum += expf(lg[i] - m);
    }
    ssum += __shfl_xor_sync(0xffffffffu, ssum, 1);
    float zo = __shfl_xor_sync(0xffffffffu, bestz, 1);
    int   vo = __shfl_xor_sync(0xffffffffu, bestv, 1);
    float lo = __shfl_xor_sync(0xffffffffu, bestl, 1);
    if (zo > bestz) { bestv = vo; bestl = lo; }
    lp = (bestl - m) - logf(ssum);
    return bestv;
}

__global__ void __launch_bounds__(HT)
heads_kernel(const int* __restrict__ canvas0, const int* __restrict__ canvas1,
             const int* __restrict__ refp,
             const float* __restrict__ Wc, const float* __restrict__ bc,
             const float* __restrict__ Ws, const float* __restrict__ bs,
             const float* __restrict__ Wl, const float* __restrict__ bl,
             const float* __restrict__ Wr1, const float* __restrict__ br1,
             const float* __restrict__ Wr2, const float* __restrict__ br2,
             const float* __restrict__ Wp, const float* __restrict__ bp,
             float* __restrict__ out, Keys keys) {
    extern __shared__ float sm[];
    const int tid  = threadIdx.x;
    const int p    = tid & 1;            // half-index within sample pair
    const int sidx = tid >> 1;           // sample within block
    const int b    = blockIdx.x * SPB + sidx;
    const int tile = blockIdx.x * SPB;
    const int dialog = blockIdx.y;

    for (int i = tid; i < 192;  i += HT) sm[HW_WC + i] = Wc[i];
    for (int i = tid; i < 192;  i += HT) sm[HW_WS + i] = Ws[i];
    if (tid < 3)  sm[HW_BC + tid]  = bc[tid];
    if (tid < 3)  sm[HW_BS + tid]  = bs[tid];
    if (dialog == 0) {
        for (int i = tid; i < 1600; i += HT) sm[HW_WL + i] = Wl[i];
        if (tid < 25) sm[HW_BL + tid]  = bl[tid];
    } else {
        for (int i = tid; i < 512;  i += HT) sm[HW_WP + i] = Wp[i];
        for (int i = tid; i < 2176; i += HT) sm[HW_WR1 + i] = Wr1[i];
        if (tid < 8)  sm[HW_BP + tid]  = bp[tid];
        if (tid < 32) sm[HW_BR1 + tid] = br1[tid];
        if (tid < 32) sm[HW_WR2 + tid] = Wr2[tid];
        if (tid == 0) sm[HW_BR2] = br2[0];
    }

    float* hb = sm + HW_HB;
    for (int i = tid; i < SPB * RNN; i += HT) {
        int s = i >> 6, k = i & 63;
        hb[s * 65 + k] = g_h[dialog * (BN * RNN) + (tile + s) * RNN + k];
    }
    __syncthreads();

    const float* h = hb + sidx * 65;

    // color/shape logits, split 2/1 across the pair
    const int cbase = p ? 2 : 0;
    const int ccnt  = p ? 1 : 2;
    float lgc[2], lgs[2];
#pragma unroll
    for (int i = 0; i < 2; i++) {
        if (i >= ccnt) break;
        int r = cbase + i;
        float dd = 0.f, ee = 0.f;
        for (int k = 0; k < 64; k++) {
            dd = fmaf(h[k], sm[HW_WC + r * 64 + k], dd);
            ee = fmaf(h[k], sm[HW_WS + r * 64 + k], ee);
        }
        lgc[i] = dd + sm[HW_BC + r];
        lgs[i] = ee + sm[HW_BS + r];
    }

    const int lbase = p ? 13 : 0;
    const int lcnt  = p ? 12 : 13;

    if (dialog == 0) {
        // 25-way location logits, split 13/12
        float ll[13];
#pragma unroll
        for (int i = 0; i < 13; i++) {
            if (i >= lcnt) break;
            int r = lbase + i;
            float dd = 0.f;
            for (int k = 0; k < 64; k++) dd = fmaf(h[k], sm[HW_WL + r * 64 + k], dd);
            ll[i] = dd + sm[HW_BL + r];
        }
        float clp0, slp0, llp0;
        int cs0  = sample_lp_pair<2>(lgc, cbase, ccnt, 3, keys.a[0], keys.b[0], b, clp0);
        sample_lp_pair<2>(lgs, cbase, ccnt, 3, keys.a[1], keys.b[1], b, slp0);
        int loc0 = sample_lp_pair<13>(ll, lbase, lcnt, 25, keys.a[2], keys.b[2], b, llp0);

        if (p == 0) {
            int lclip = min(max(loc0, 0), 24);
            int4 pt = *(const int4*)(canvas1 + (b * 25 + lclip) * 4);
            bool ok0 = (loc0 >= 0) && (loc0 < 25) && ((pt.x + pt.y + pt.z + pt.w) >= 0);
            float loc_r0 = ok0 ? 1.f : -1.f;
            float col_r0 = ok0 ? ((cs0 == pt.x) ? 1.f : -1.f) : 0.f;

            out[0 * BN + b] = clp0;
            out[1 * BN + b] = slp0;
            out[2 * BN + b] = llp0;
            out[(7 + 0) * BN + b] = loc_r0;
            out[(7 + 1) * BN + b] = col_r0;
            out[(7 + 2) * BN + b] = loc_r0;
        }
    } else {
        // 8-way offset logits, split 4/4
        float lp8[4];
        const int pbase = p * 4;
#pragma unroll
        for (int i = 0; i < 4; i++) {
            int r = pbase + i;
            float dd = 0.f;
            for (int k = 0; k < 64; k++) dd = fmaf(h[k], sm[HW_WP + r * 64 + k], dd);
            lp8[i] = dd + sm[HW_BP + r];
        }
        float clp1, slp1, llp1, alp1;
        int cs1 = sample_lp_pair<2>(lgc, cbase, ccnt, 3, keys.a[3], keys.b[3], b, clp1);
        sample_lp_pair<2>(lgs, cbase, ccnt, 3, keys.a[4], keys.b[4], b, slp1);
        int ls1 = sample_lp_pair<4>(lp8, pbase, 4, 8, keys.a[5], keys.b[5], b, llp1);

        // attention MLP: this thread owns hidden units j0..j0+15
        const int j0 = p * 16;
        float pre[16];
#pragma unroll
        for (int jj = 0; jj < 16; jj++) {
            int j = j0 + jj;
            float dd = 0.f;
            for (int k = 0; k < 64; k++) dd = fmaf(h[k], sm[HW_WR1 + j * 68 + k], dd);
            pre[jj] = dd + sm[HW_BR1 + j];
        }
        float alsh[13];
#pragma unroll 5
        for (int loc = 0; loc < 25; loc++) {
            int4 cv = *(const int4*)(canvas0 + (b * 25 + loc) * 4);
            float cx = (float)cv.x, cy = (float)cv.y, cz = (float)cv.z, cw = (float)cv.w;
            float partial = p ? 0.f : sm[HW_BR2];
#pragma unroll
            for (int jj = 0; jj < 16; jj++) {
                int j = j0 + jj;
                float v = pre[jj];
                v = fmaf(cx, sm[HW_WR1 + j * 68 + 64], v);
                v = fmaf(cy, sm[HW_WR1 + j * 68 + 65], v);
                v = fmaf(cz, sm[HW_WR1 + j * 68 + 66], v);
                v = fmaf(cw, sm[HW_WR1 + j * 68 + 67], v);
                v = fmaxf(v, 0.f);
                partial = fmaf(v, sm[HW_WR2 + j], partial);
            }
            float tot = partial + __shfl_xor_sync(0xffffffffu, partial, 1);
            int li = loc - lbase;
            if (li >= 0 && li < lcnt) alsh[li] = tot;
        }
        int att = sample_lp_pair<13>(alsh, lbase, lcnt, 25, keys.a[6], keys.b[6], b, alp1);

        if (p == 0) {
            int4 ro = *(const int4*)(canvas0 + (b * 25 + att) * 4);
            int4 rf = *(const int4*)(refp + b * 4);
            float att_rew = (ro.x == rf.x && ro.y == rf.y && ro.z == rf.z && ro.w == rf.w)
                                ? 1.f : -1.f;
            int loc1 = (ro.z + c_offx[ls1]) * 5 + (ro.w + c_offy[ls1]);
            int l1c = min(max(loc1, 0), 24);
            int4 pt1 = *(const int4*)(canvas1 + (b * 25 + l1c) * 4);
            bool ok1 = (loc1 >= 0) && (loc1 < 25) && ((pt1.x + pt1.y + pt1.z + pt1.w) >= 0);
            float loc_r1 = ok1 ? 1.f : -1.f;
            float col_r1 = ok1 ? ((cs1 == pt1.x) ? 1.f : -1.f) : 0.f;

            out[3 * BN + b] = clp1;
            out[4 * BN + b] = slp1;
            out[5 * BN + b] = llp1;
            out[6 * BN + b] = alp1;
            out[(7 + 3) * BN + b] = loc_r1;
            out[(7 + 4) * BN + b] = col_r1;
            out[(7 + 5) * BN + b] = loc_r1;
            out[(7 + 6) * BN + b] = att_rew;
        }
    }
}

// ================= launch =================
extern "C" void kernel_launch(void* const* d_in, const int* in_sizes, int n_in,
                              void* d_out, int out_size) {
    const int*   inst0   = (const int*)d_in[0];
    const int*   inst1   = (const int*)d_in[1];
    const int*   canvas0 = (const int*)d_in[2];
    const int*   canvas1 = (const int*)d_in[3];
    const int*   refp    = (const int*)d_in[4];
    const float* embed   = (const float*)d_in[5];
    const float* W_ih    = (const float*)d_in[6];
    const float* W_hh    = (const float*)d_in[7];
    const float* b_ih    = (const float*)d_in[8];
    const float* b_hh    = (const float*)d_in[9];
    const float* Wc      = (const float*)d_in[10];
    const float* bc      = (const float*)d_in[11];
    const float* Ws      = (const float*)d_in[12];
    const float* bs      = (const float*)d_in[13];
    const float* Wl      = (const float*)d_in[14];
    const float* bl      = (const float*)d_in[15];
    const float* Wr1     = (const float*)d_in[16];
    const float* br1     = (const float*)d_in[17];
    const float* Wr2     = (const float*)d_in[18];
    const float* br2     = (const float*)d_in[19];
    const float* Wp      = (const float*)d_in[20];
    const float* bp      = (const float*)d_in[21];

    Keys keys;
#if THREEFRY_PARTITIONABLE
    for (int i = 0; i < 7; i++)
        threefry2x32(0u, 42u, 0u, (uint32_t)i, keys.a[i], keys.b[i]);
#else
    uint32_t o[14];
    for (int i = 0; i < 7; i++)
        threefry2x32(0u, 42u, (uint32_t)i, (uint32_t)(i + 7), o[i], o[7 + i]);
    for (int i = 0; i < 7; i++) { keys.a[i] = o[2 * i]; keys.b[i] = o[2 * i + 1]; }
#endif

    cudaFuncSetAttribute(lstm_kernel, cudaFuncAttributeMaxDynamicSharedMemorySize,
                         LSTM_SMEM_BYTES);
    cudaFuncSetAttribute(heads_kernel, cudaFuncAttributeMaxDynamicSharedMemorySize,
                         HEADS_SMEM_BYTES);

    tokgate_kernel<<<(VOCAB + 7) / 8, 256>>>(embed, W_ih, b_ih, b_hh);
    wlof_kernel<<<16, 256>>>(W_hh);
    lstm_kernel<<<dim3(BN / TBM, 2), 256, LSTM_SMEM_BYTES>>>(inst0, inst1, W_hh);
    heads_kernel<<<dim3(BN / SPB, 2), HT, HEADS_SMEM_BYTES>>>(
        canvas0, canvas1, refp, Wc, bc, Ws, bs, Wl, bl, Wr1, br1, Wr2, br2,
        Wp, bp, (float*)d_out, keys);
}